// round 7
// baseline (speedup 1.0000x reference)
#include <cuda_runtime.h>
#include <cuda_bf16.h>
#include <math.h>

// Problem constants (fixed by setup_inputs)
#define BQ    1024
#define DIM   1024
#define CDIM  128
#define NKEYS 100000
#define KNN   5
#define EPSW  1e-6f
#define NB    2048
// fixed kn->bucket mapping (any mapping with valid floors is exact)
#define KN_LO 48.0f
#define KN_SPAN 96.0f

// ---------------- scratch (device globals; no allocations allowed) ---------
__device__ __align__(16) __nv_bfloat16 g_qh[BQ * DIM],   g_ql[BQ * DIM];
__device__ __align__(16) __nv_bfloat16 g_W1h[DIM * 512], g_W1l[DIM * 512];
__device__ __align__(16) __nv_bfloat16 g_W2h[512 * 256], g_W2l[512 * 256];
__device__ __align__(16) __nv_bfloat16 g_W3h[256 * 128], g_W3l[256 * 128];
__device__ __align__(16) __nv_bfloat16 g_D1h[128 * 256], g_D1l[128 * 256];
__device__ __align__(16) __nv_bfloat16 g_D2h[256 * 512], g_D2l[256 * 512];
__device__ __align__(16) __nv_bfloat16 g_D3h[512 * 1024], g_D3l[512 * 1024];
__device__ __align__(16) __nv_bfloat16 g_h1h[BQ * 512], g_h1l[BQ * 512];
__device__ __align__(16) __nv_bfloat16 g_h2h[BQ * 256], g_h2l[BQ * 256];
__device__ __align__(16) __nv_bfloat16 g_wh[BQ * CDIM], g_wl[BQ * CDIM];
__device__ __align__(16) __nv_bfloat16 g_g1h[BQ * 256], g_g1l[BQ * 256];
__device__ __align__(16) __nv_bfloat16 g_g2h[BQ * 512], g_g2l[BQ * 512];

__device__ float g_cq[BQ * CDIM];
__device__ float g_qn[BQ];
__device__ float g_kn[NKEYS];
__device__ int   g_hist[NB];
__device__ int   g_cursor[NB];
__device__ int   g_scand[NKEYS];
__device__ float g_skn[NKEYS];
__device__ float g_sblo[NKEYS];

// ---------------- init ------------------------------------------------------
__global__ void init_kernel() {
    int t = blockIdx.x * blockDim.x + threadIdx.x;
    if (t < NB) g_hist[t] = 0;
}

// ---------------- batched fp32 -> bf16 hi/lo split --------------------------
struct SplitSeg { const float* src; __nv_bfloat16* h; __nv_bfloat16* l; };
struct SplitArgs { SplitSeg s[7]; int cum[8]; };

__global__ void split_batch_kernel(SplitArgs a) {
    int i = blockIdx.x * blockDim.x + threadIdx.x;   // float4 units
    if (i >= a.cum[7]) return;
    int sg = 0;
    while (i >= a.cum[sg + 1]) sg++;
    int j = i - a.cum[sg];
    float4 v = reinterpret_cast<const float4*>(a.s[sg].src)[j];
    float x[4] = {v.x, v.y, v.z, v.w};
    unsigned short h[4], l[4];
#pragma unroll
    for (int q = 0; q < 4; q++) {
        __nv_bfloat16 hb = __float2bfloat16(x[q]);
        __nv_bfloat16 lb = __float2bfloat16(x[q] - __bfloat162float(hb));
        h[q] = __bfloat16_as_ushort(hb);
        l[q] = __bfloat16_as_ushort(lb);
    }
    uint2 hp = {(unsigned)h[0] | ((unsigned)h[1] << 16),
                (unsigned)h[2] | ((unsigned)h[3] << 16)};
    uint2 lp = {(unsigned)l[0] | ((unsigned)l[1] << 16),
                (unsigned)l[2] | ((unsigned)l[3] << 16)};
    reinterpret_cast<uint2*>(a.s[sg].h)[j] = hp;
    reinterpret_cast<uint2*>(a.s[sg].l)[j] = lp;
}

// ============================================================================
// bf16 hi/lo tensor-core GEMM. Tile 64x64, BK=32, 256 threads / 8 warps;
// warp tile 16x32 (1x m16 x 4x n8). AhBh + AhBl + AlBh, fp32 accumulate.
// cp.async double buffered.
// ============================================================================
#define GBM 64
#define GBN 64
#define GBK 32
#define ASTR 40
#define BSTR 72

__device__ __forceinline__ void mma_bf16(float c[4], const unsigned a[4],
                                         const unsigned b[2]) {
    asm volatile(
        "mma.sync.aligned.m16n8k16.row.col.f32.bf16.bf16.f32 "
        "{%0,%1,%2,%3}, {%4,%5,%6,%7}, {%8,%9}, {%0,%1,%2,%3};"
        : "+f"(c[0]), "+f"(c[1]), "+f"(c[2]), "+f"(c[3])
        : "r"(a[0]), "r"(a[1]), "r"(a[2]), "r"(a[3]), "r"(b[0]), "r"(b[1]));
}
__device__ __forceinline__ void ldmA(unsigned a[4], unsigned addr) {
    asm volatile("ldmatrix.sync.aligned.m8n8.x4.shared.b16 {%0,%1,%2,%3}, [%4];"
                 : "=r"(a[0]), "=r"(a[1]), "=r"(a[2]), "=r"(a[3]) : "r"(addr));
}
__device__ __forceinline__ void ldmB(unsigned b[2], unsigned addr) {
    asm volatile("ldmatrix.sync.aligned.m8n8.x2.trans.shared.b16 {%0,%1}, [%2];"
                 : "=r"(b[0]), "=r"(b[1]) : "r"(addr));
}
__device__ __forceinline__ void cpa16(unsigned dst, const void* src) {
    asm volatile("cp.async.cg.shared.global [%0], [%1], 16;"
                 :: "r"(dst), "l"(src));
}

template <int RELU, int WF32, int WBF>
__global__ __launch_bounds__(256)
void bgemm(const __nv_bfloat16* __restrict__ Ah, const __nv_bfloat16* __restrict__ Al,
           const __nv_bfloat16* __restrict__ Bh, const __nv_bfloat16* __restrict__ Bl,
           const float* __restrict__ bias,
           float* __restrict__ Cf,
           __nv_bfloat16* __restrict__ Ch, __nv_bfloat16* __restrict__ Cl,
           int M, int N, int K) {
    __shared__ __align__(16) __nv_bfloat16 sA[2 * 2 * GBM * ASTR];
    __shared__ __align__(16) __nv_bfloat16 sB[2 * 2 * GBK * BSTR];

    const int tid  = threadIdx.x;
    const int lane = tid & 31;
    const int wid  = tid >> 5;
    const int wm   = wid & 3;       // 4 warps along M (16 rows each)
    const int wn   = wid >> 2;      // 2 warps along N (32 cols each)
    const int bm   = blockIdx.y * GBM;
    const int bn   = blockIdx.x * GBN;

    const unsigned saddrA = (unsigned)__cvta_generic_to_shared(sA);
    const unsigned saddrB = (unsigned)__cvta_generic_to_shared(sB);
    const unsigned aBufB  = GBM * ASTR * 2;
    const unsigned bBufB  = GBK * BSTR * 2;

    // 256-thread staging: one 16B cp.async per matrix per thread
    const int ar  = tid >> 2;           // A row 0..63
    const int ac0 = (tid & 3) << 3;     // A col 0,8,16,24
    const int br  = tid >> 3;           // B row 0..31
    const int bc  = (tid & 7) << 3;     // B col 0..56

    const int a_r  = (lane & 7) + ((lane >> 3) & 1) * 8;
    const int a_k8 = (lane >> 4) * 8;
    const int b_r  = lane & 15;

    float acc[4][4];
#pragma unroll
    for (int nt = 0; nt < 4; nt++)
#pragma unroll
        for (int i = 0; i < 4; i++) acc[nt][i] = 0.f;

    const int ntk = K >> 5;

    auto stage = [&](int t, int buf) {
        const int k0 = t * GBK;
        size_t ga = (size_t)(bm + ar) * K + k0 + ac0;
        unsigned da = saddrA + (unsigned)(buf * 2) * aBufB + (ar * ASTR + ac0) * 2;
        cpa16(da,         Ah + ga);
        cpa16(da + aBufB, Al + ga);
        size_t gb = (size_t)(k0 + br) * N + bn + bc;
        unsigned db = saddrB + (unsigned)(buf * 2) * bBufB + (br * BSTR + bc) * 2;
        cpa16(db,         Bh + gb);
        cpa16(db + bBufB, Bl + gb);
        asm volatile("cp.async.commit_group;");
    };

    stage(0, 0);

    for (int t = 0; t < ntk; t++) {
        asm volatile("cp.async.wait_group 0;");
        __syncthreads();
        if (t + 1 < ntk) stage(t + 1, (t + 1) & 1);

        const int buf = t & 1;
        const unsigned base_ah = saddrA + (unsigned)(buf * 2) * aBufB;
        const unsigned base_al = base_ah + aBufB;
        const unsigned base_bh = saddrB + (unsigned)(buf * 2) * bBufB;
        const unsigned base_bl = base_bh + bBufB;

#pragma unroll
        for (int kk = 0; kk < GBK; kk += 16) {
            unsigned ah[4], al_[4];
            unsigned ro = ((wm * 16 + a_r) * ASTR + kk + a_k8) * 2;
            ldmA(ah,  base_ah + ro);
            ldmA(al_, base_al + ro);
#pragma unroll
            for (int nt = 0; nt < 4; nt++) {
                unsigned bh[2], bl_[2];
                unsigned bo = ((kk + b_r) * BSTR + wn * 32 + nt * 8) * 2;
                ldmB(bh,  base_bh + bo);
                ldmB(bl_, base_bl + bo);
                mma_bf16(acc[nt], ah,  bh);
                mma_bf16(acc[nt], ah,  bl_);
                mma_bf16(acc[nt], al_, bh);
            }
        }
        __syncthreads();
    }

    // epilogue
    const int g  = lane >> 2;
    const int tq = lane & 3;
#pragma unroll
    for (int nt = 0; nt < 4; nt++) {
        int row = bm + wm * 16 + g;
        int col = bn + wn * 32 + nt * 8 + tq * 2;
        float bz0 = bias[col], bz1 = bias[col + 1];
        float v0 = acc[nt][0] + bz0;
        float v1 = acc[nt][1] + bz1;
        float v2 = acc[nt][2] + bz0;
        float v3 = acc[nt][3] + bz1;
        if (RELU) {
            v0 = fmaxf(v0, 0.f); v1 = fmaxf(v1, 0.f);
            v2 = fmaxf(v2, 0.f); v3 = fmaxf(v3, 0.f);
        }
        if (WF32) {
            float2 o0 = {v0, v1}, o1 = {v2, v3};
            *reinterpret_cast<float2*>(&Cf[(size_t)row * N + col]) = o0;
            *reinterpret_cast<float2*>(&Cf[(size_t)(row + 8) * N + col]) = o1;
        }
        if (WBF) {
            __nv_bfloat16 h0 = __float2bfloat16(v0);
            __nv_bfloat16 h1 = __float2bfloat16(v1);
            __nv_bfloat16 h2 = __float2bfloat16(v2);
            __nv_bfloat16 h3 = __float2bfloat16(v3);
            unsigned hp0 = (unsigned)__bfloat16_as_ushort(h0) |
                           ((unsigned)__bfloat16_as_ushort(h1) << 16);
            unsigned hp1 = (unsigned)__bfloat16_as_ushort(h2) |
                           ((unsigned)__bfloat16_as_ushort(h3) << 16);
            unsigned lp0 = (unsigned)__bfloat16_as_ushort(
                               __float2bfloat16(v0 - __bfloat162float(h0))) |
                           ((unsigned)__bfloat16_as_ushort(
                               __float2bfloat16(v1 - __bfloat162float(h1))) << 16);
            unsigned lp1 = (unsigned)__bfloat16_as_ushort(
                               __float2bfloat16(v2 - __bfloat162float(h2))) |
                           ((unsigned)__bfloat16_as_ushort(
                               __float2bfloat16(v3 - __bfloat162float(h3))) << 16);
            *reinterpret_cast<unsigned*>(&Ch[(size_t)row * N + col]) = hp0;
            *reinterpret_cast<unsigned*>(&Ch[(size_t)(row + 8) * N + col]) = hp1;
            *reinterpret_cast<unsigned*>(&Cl[(size_t)row * N + col]) = lp0;
            *reinterpret_cast<unsigned*>(&Cl[(size_t)(row + 8) * N + col]) = lp1;
        }
    }
}

// ---------------- row squared-norms (rows of width 128) --------------------
__global__ void rownorm_kernel(const float* __restrict__ X,
                               float* __restrict__ out, int rows) {
    int gw = (int)((blockIdx.x * (size_t)blockDim.x + threadIdx.x) >> 5);
    int lane = threadIdx.x & 31;
    if (gw >= rows) return;
    float4 v = reinterpret_cast<const float4*>(X + (size_t)gw * 128)[lane];
    float s = v.x * v.x + v.y * v.y + v.z * v.z + v.w * v.w;
#pragma unroll
    for (int o = 16; o; o >>= 1) s += __shfl_xor_sync(0xffffffffu, s, o);
    if (lane == 0) out[gw] = s;
}

// ---------------- fixed bucket mapping --------------------------------------
__device__ __forceinline__ int kn_bucket(float kn) {
    int b = (int)((kn - KN_LO) * ((float)NB / KN_SPAN));
    return min(NB - 1, max(0, b));
}
__device__ __forceinline__ float kn_floor(int b) {
    // valid lower bound for every key in buckets >= b
    return (b == 0) ? 0.f : (KN_LO + (float)b * (KN_SPAN / (float)NB));
}

// ---------------- histogram / scan / scatter over ALL keys ------------------
__global__ void cand_hist_kernel() {
    int n = blockIdx.x * blockDim.x + threadIdx.x;
    if (n >= NKEYS) return;
    atomicAdd(&g_hist[kn_bucket(g_kn[n])], 1);
}

__global__ void scan_kernel() {
    __shared__ int s[NB];
    __shared__ int tmp[NB];
    const int tid = threadIdx.x;   // 1024
    for (int i = tid; i < NB; i += 1024) s[i] = g_hist[i];
    __syncthreads();
    for (int off = 1; off < NB; off <<= 1) {
        for (int i = tid; i < NB; i += 1024)
            tmp[i] = s[i] + (i >= off ? s[i - off] : 0);
        __syncthreads();
        for (int i = tid; i < NB; i += 1024) s[i] = tmp[i];
        __syncthreads();
    }
    for (int i = tid; i < NB; i += 1024)
        g_cursor[i] = (i == 0) ? 0 : s[i - 1];
}

__global__ void scatter_kernel() {
    int n = blockIdx.x * blockDim.x + threadIdx.x;
    if (n >= NKEYS) return;
    float kn = g_kn[n];
    int b = kn_bucket(kn);
    int pos = atomicAdd(&g_cursor[b], 1);
    g_scand[pos] = n;
    g_skn[pos]   = kn;
    g_sblo[pos]  = kn_floor(b);
}

// ---------------- exact rescore + top-5 + weighted gather ------------------
// All keys bucket-sorted ascending by kn; provably-safe early exit:
//   d2(n) >= qn + kn - 2*qb*sqrt(kn) >= qn + f(blo)   (f increasing, kn >> qb^2)
__global__ __launch_bounds__(128, 8)
void rescore_kernel(const float* __restrict__ keys,
                    const float* __restrict__ values,
                    float* __restrict__ conf_out) {
    const int b = blockIdx.x;
    const int tid = threadIdx.x;
    __shared__ float sq[CDIM];
    __shared__ float dv[128];
    __shared__ int   di[128];
    __shared__ float rd[KNN];
    __shared__ int   ri[KNN];
    __shared__ float rv[128];
    __shared__ int   rvi[128];
    __shared__ int   rvj[128];
    __shared__ float sw[KNN];
    __shared__ int   s_stop;

    sq[tid] = g_cq[(size_t)b * CDIM + tid];
    if (tid < KNN) { rd[tid] = 3.4e38f; ri[tid] = 0x7fffffff; }
    if (tid == 0) s_stop = 0;
    const float qn = g_qn[b];
    const float qb = sqrtf(qn);
    __syncthreads();

    for (int c0 = 0; c0 < NKEYS; c0 += 128) {
        if (tid == 0 && c0 > 0) {
            float blo = g_sblo[c0];
            float lb = qn + blo - 2.f * qb * sqrtf(blo) - 1e-3f;
            if (lb > rd[KNN - 1]) s_stop = 1;
        }
        __syncthreads();
        if (s_stop) break;

        int len = min(128, NKEYS - c0);
        int j = c0 + tid;
        if (tid < len) {
            int n = g_scand[j];
            const float4* kr = reinterpret_cast<const float4*>(keys + (size_t)n * CDIM);
            const float4* sq4 = reinterpret_cast<const float4*>(sq);
            float a0 = 0.f, a1 = 0.f, a2 = 0.f, a3 = 0.f;
#pragma unroll
            for (int d = 0; d < CDIM / 4; d++) {
                float4 kv = __ldg(&kr[d]);
                float4 qv = sq4[d];
                a0 = fmaf(qv.x, kv.x, a0);
                a1 = fmaf(qv.y, kv.y, a1);
                a2 = fmaf(qv.z, kv.z, a2);
                a3 = fmaf(qv.w, kv.w, a3);
            }
            float dot = (a0 + a1) + (a2 + a3);
            dv[tid] = qn + g_skn[j] - 2.f * dot;
            di[tid] = n;
        } else {
            dv[tid] = 3.4e38f;
            di[tid] = 0x7fffffff;
        }
        __syncthreads();

        for (int r = 0; r < KNN; r++) {
            rv[tid] = dv[tid]; rvi[tid] = di[tid]; rvj[tid] = tid;
            __syncthreads();
#pragma unroll
            for (int s = 64; s >= 1; s >>= 1) {
                if (tid < s) {
                    if (rv[tid + s] < rv[tid] ||
                        (rv[tid + s] == rv[tid] && rvi[tid + s] < rvi[tid])) {
                        rv[tid] = rv[tid + s];
                        rvi[tid] = rvi[tid + s];
                        rvj[tid] = rvj[tid + s];
                    }
                }
                __syncthreads();
            }
            if (tid == 0) {
                float v = rv[0]; int n = rvi[0];
                if (v < rd[KNN - 1] || (v == rd[KNN - 1] && n < ri[KNN - 1])) {
                    int p = KNN - 1;
                    while (p > 0 && (rd[p - 1] > v ||
                                     (rd[p - 1] == v && ri[p - 1] > n))) {
                        rd[p] = rd[p - 1]; ri[p] = ri[p - 1]; p--;
                    }
                    rd[p] = v; ri[p] = n;
                }
                dv[rvj[0]] = 3.4e38f;
            }
            __syncthreads();
        }
    }

    if (tid == 0) {
        float w[KNN], ws = 0.f;
#pragma unroll
        for (int j2 = 0; j2 < KNN; j2++) { w[j2] = 1.f / (rd[j2] + EPSW); ws += w[j2]; }
#pragma unroll
        for (int j2 = 0; j2 < KNN; j2++) sw[j2] = w[j2] / ws;
        conf_out[b] = 1.f / (rd[0] + EPSW);
    }
    __syncthreads();

    float acc = 0.f;
#pragma unroll
    for (int j2 = 0; j2 < KNN; j2++)
        acc += sw[j2] * values[(size_t)ri[j2] * CDIM + tid];
    __nv_bfloat16 hb = __float2bfloat16(acc);
    g_wh[(size_t)b * CDIM + tid] = hb;
    g_wl[(size_t)b * CDIM + tid] = __float2bfloat16(acc - __bfloat162float(hb));
}

// ---------------- launch ----------------------------------------------------
extern "C" void kernel_launch(void* const* d_in, const int* in_sizes, int n_in,
                              void* d_out, int out_size) {
    const float* query = (const float*)d_in[0];
    const float* W1    = (const float*)d_in[1];
    const float* b1    = (const float*)d_in[2];
    const float* W2    = (const float*)d_in[3];
    const float* b2    = (const float*)d_in[4];
    const float* W3    = (const float*)d_in[5];
    const float* b3    = (const float*)d_in[6];
    const float* keys  = (const float*)d_in[7];
    const float* values= (const float*)d_in[8];
    const float* D1w   = (const float*)d_in[9];
    const float* D1b   = (const float*)d_in[10];
    const float* D2w   = (const float*)d_in[11];
    const float* D2b   = (const float*)d_in[12];
    const float* D3w   = (const float*)d_in[13];
    const float* D3b   = (const float*)d_in[14];

    float* out  = (float*)d_out;
    float* conf = out + (size_t)BQ * DIM;

    void *qh, *ql, *W1h, *W1l, *W2h, *W2l, *W3h, *W3l;
    void *D1h, *D1l, *D2h, *D2l, *D3h, *D3l;
    void *h1h, *h1l, *h2h, *h2l, *wh, *wl, *g1h, *g1l, *g2h, *g2l;
    void *cq, *qn, *kn;
    cudaGetSymbolAddress(&qh, g_qh);   cudaGetSymbolAddress(&ql, g_ql);
    cudaGetSymbolAddress(&W1h, g_W1h); cudaGetSymbolAddress(&W1l, g_W1l);
    cudaGetSymbolAddress(&W2h, g_W2h); cudaGetSymbolAddress(&W2l, g_W2l);
    cudaGetSymbolAddress(&W3h, g_W3h); cudaGetSymbolAddress(&W3l, g_W3l);
    cudaGetSymbolAddress(&D1h, g_D1h); cudaGetSymbolAddress(&D1l, g_D1l);
    cudaGetSymbolAddress(&D2h, g_D2h); cudaGetSymbolAddress(&D2l, g_D2l);
    cudaGetSymbolAddress(&D3h, g_D3h); cudaGetSymbolAddress(&D3l, g_D3l);
    cudaGetSymbolAddress(&h1h, g_h1h); cudaGetSymbolAddress(&h1l, g_h1l);
    cudaGetSymbolAddress(&h2h, g_h2h); cudaGetSymbolAddress(&h2l, g_h2l);
    cudaGetSymbolAddress(&wh, g_wh);   cudaGetSymbolAddress(&wl, g_wl);
    cudaGetSymbolAddress(&g1h, g_g1h); cudaGetSymbolAddress(&g1l, g_g1l);
    cudaGetSymbolAddress(&g2h, g_g2h); cudaGetSymbolAddress(&g2l, g_g2l);
    cudaGetSymbolAddress(&cq, g_cq);
    cudaGetSymbolAddress(&qn, g_qn);
    cudaGetSymbolAddress(&kn, g_kn);

    init_kernel<<<NB / 256, 256>>>();

    // batched split: query + 6 weight matrices
    SplitArgs sa;
    int sizes4[7] = {BQ * DIM / 4, DIM * 512 / 4, 512 * 256 / 4, 256 * 128 / 4,
                     128 * 256 / 4, 256 * 512 / 4, 512 * 1024 / 4};
    const float* srcs[7] = {query, W1, W2, W3, D1w, D2w, D3w};
    void* hs[7] = {qh, W1h, W2h, W3h, D1h, D2h, D3h};
    void* ls[7] = {ql, W1l, W2l, W3l, D1l, D2l, D3l};
    sa.cum[0] = 0;
    for (int i = 0; i < 7; i++) {
        sa.s[i].src = srcs[i];
        sa.s[i].h = (__nv_bfloat16*)hs[i];
        sa.s[i].l = (__nv_bfloat16*)ls[i];
        sa.cum[i + 1] = sa.cum[i] + sizes4[i];
    }
    split_batch_kernel<<<(sa.cum[7] + 255) / 256, 256>>>(sa);

    // key norms -> bucket-sort all keys by kn (independent of encode chain)
    rownorm_kernel<<<(NKEYS * 32 + 255) / 256, 256>>>(keys, (float*)kn, NKEYS);
    cand_hist_kernel<<<(NKEYS + 255) / 256, 256>>>();
    scan_kernel<<<1, 1024>>>();
    scatter_kernel<<<(NKEYS + 255) / 256, 256>>>();

    // Encode MLP
    bgemm<1, 0, 1><<<dim3(512 / GBN, BQ / GBM), 256>>>(
        (__nv_bfloat16*)qh, (__nv_bfloat16*)ql, (__nv_bfloat16*)W1h, (__nv_bfloat16*)W1l,
        b1, nullptr, (__nv_bfloat16*)h1h, (__nv_bfloat16*)h1l, BQ, 512, 1024);
    bgemm<1, 0, 1><<<dim3(256 / GBN, BQ / GBM), 256>>>(
        (__nv_bfloat16*)h1h, (__nv_bfloat16*)h1l, (__nv_bfloat16*)W2h, (__nv_bfloat16*)W2l,
        b2, nullptr, (__nv_bfloat16*)h2h, (__nv_bfloat16*)h2l, BQ, 256, 512);
    bgemm<0, 1, 0><<<dim3(128 / GBN, BQ / GBM), 256>>>(
        (__nv_bfloat16*)h2h, (__nv_bfloat16*)h2l, (__nv_bfloat16*)W3h, (__nv_bfloat16*)W3l,
        b3, (float*)cq, nullptr, nullptr, BQ, 128, 256);

    // query norms
    rownorm_kernel<<<(BQ * 32 + 255) / 256, 256>>>((float*)cq, (float*)qn, BQ);

    // exact rescore + top-5 + gather (emits weighted as bf16 hi/lo)
    rescore_kernel<<<BQ, 128>>>(keys, values, conf);

    // Decode MLP
    bgemm<1, 0, 1><<<dim3(256 / GBN, BQ / GBM), 256>>>(
        (__nv_bfloat16*)wh, (__nv_bfloat16*)wl, (__nv_bfloat16*)D1h, (__nv_bfloat16*)D1l,
        D1b, nullptr, (__nv_bfloat16*)g1h, (__nv_bfloat16*)g1l, BQ, 256, 128);
    bgemm<1, 0, 1><<<dim3(512 / GBN, BQ / GBM), 256>>>(
        (__nv_bfloat16*)g1h, (__nv_bfloat16*)g1l, (__nv_bfloat16*)D2h, (__nv_bfloat16*)D2l,
        D2b, nullptr, (__nv_bfloat16*)g2h, (__nv_bfloat16*)g2l, BQ, 512, 256);
    bgemm<0, 1, 0><<<dim3(1024 / GBN, BQ / GBM), 256>>>(
        (__nv_bfloat16*)g2h, (__nv_bfloat16*)g2l, (__nv_bfloat16*)D3h, (__nv_bfloat16*)D3l,
        D3b, out, nullptr, nullptr, BQ, 1024, 512);
}

// round 8
// speedup vs baseline: 1.1221x; 1.1221x over previous
#include <cuda_runtime.h>
#include <cuda_bf16.h>
#include <math.h>

// Problem constants (fixed by setup_inputs)
#define BQ    1024
#define DIM   1024
#define CDIM  128
#define NKEYS 100000
#define KNN   5
#define EPSW  1e-6f
#define NB    2048
// fixed kn->bucket mapping: covers kn in [64,192]; kn ~ chi2(128) (mean 128, sd 16)
#define KN_LO 64.0f
#define KN_SPAN 128.0f

// ---------------- scratch (device globals; no allocations allowed) ---------
__device__ __align__(16) __nv_bfloat16 g_qh[BQ * DIM],   g_ql[BQ * DIM];
__device__ __align__(16) __nv_bfloat16 g_W1h[DIM * 512], g_W1l[DIM * 512];
__device__ __align__(16) __nv_bfloat16 g_W2h[512 * 256], g_W2l[512 * 256];
__device__ __align__(16) __nv_bfloat16 g_W3h[256 * 128], g_W3l[256 * 128];
__device__ __align__(16) __nv_bfloat16 g_D1h[128 * 256], g_D1l[128 * 256];
__device__ __align__(16) __nv_bfloat16 g_D2h[256 * 512], g_D2l[256 * 512];
__device__ __align__(16) __nv_bfloat16 g_D3h[512 * 1024], g_D3l[512 * 1024];
__device__ __align__(16) __nv_bfloat16 g_h1h[BQ * 512], g_h1l[BQ * 512];
__device__ __align__(16) __nv_bfloat16 g_h2h[BQ * 256], g_h2l[BQ * 256];
__device__ __align__(16) __nv_bfloat16 g_wh[BQ * CDIM], g_wl[BQ * CDIM];
__device__ __align__(16) __nv_bfloat16 g_g1h[BQ * 256], g_g1l[BQ * 256];
__device__ __align__(16) __nv_bfloat16 g_g2h[BQ * 512], g_g2l[BQ * 512];

__device__ float g_cq[BQ * CDIM];
__device__ float g_qn[BQ];
__device__ float g_kn[NKEYS];
__device__ int   g_hist[NB];
__device__ int   g_cursor[NB];
__device__ int   g_scand[NKEYS];
__device__ float g_skn[NKEYS];
__device__ float g_sblo[NKEYS];

// ---------------- fixed bucket mapping --------------------------------------
__device__ __forceinline__ int kn_bucket(float kn) {
    int b = (int)((kn - KN_LO) * ((float)NB / KN_SPAN));
    return min(NB - 1, max(0, b));
}
__device__ __forceinline__ float kn_floor(int b) {
    // valid lower bound on kn for every key in buckets >= b
    return (b == 0) ? 0.f : (KN_LO + (float)b * (KN_SPAN / (float)NB));
}

// ---------------- init ------------------------------------------------------
__global__ void init_kernel() {
    int t = blockIdx.x * blockDim.x + threadIdx.x;
    if (t < NB) g_hist[t] = 0;
}

// ---------------- batched fp32 -> bf16 hi/lo split --------------------------
struct SplitSeg { const float* src; __nv_bfloat16* h; __nv_bfloat16* l; };
struct SplitArgs { SplitSeg s[7]; int cum[8]; };

__global__ void split_batch_kernel(SplitArgs a) {
    int i = blockIdx.x * blockDim.x + threadIdx.x;   // float4 units
    if (i >= a.cum[7]) return;
    int sg = 0;
    while (i >= a.cum[sg + 1]) sg++;
    int j = i - a.cum[sg];
    float4 v = reinterpret_cast<const float4*>(a.s[sg].src)[j];
    float x[4] = {v.x, v.y, v.z, v.w};
    unsigned short h[4], l[4];
#pragma unroll
    for (int q = 0; q < 4; q++) {
        __nv_bfloat16 hb = __float2bfloat16(x[q]);
        __nv_bfloat16 lb = __float2bfloat16(x[q] - __bfloat162float(hb));
        h[q] = __bfloat16_as_ushort(hb);
        l[q] = __bfloat16_as_ushort(lb);
    }
    uint2 hp = {(unsigned)h[0] | ((unsigned)h[1] << 16),
                (unsigned)h[2] | ((unsigned)h[3] << 16)};
    uint2 lp = {(unsigned)l[0] | ((unsigned)l[1] << 16),
                (unsigned)l[2] | ((unsigned)l[3] << 16)};
    reinterpret_cast<uint2*>(a.s[sg].h)[j] = hp;
    reinterpret_cast<uint2*>(a.s[sg].l)[j] = lp;
}

// ============================================================================
// bf16 hi/lo tensor-core GEMM. Tile 64x64, BK=32, 256 threads / 8 warps;
// warp tile 16x32 (1x m16 x 4x n8). AhBh + AhBl + AlBh, fp32 accumulate.
// cp.async double buffered.
// ============================================================================
#define GBM 64
#define GBN 64
#define GBK 32
#define ASTR 40
#define BSTR 72

__device__ __forceinline__ void mma_bf16(float c[4], const unsigned a[4],
                                         const unsigned b[2]) {
    asm volatile(
        "mma.sync.aligned.m16n8k16.row.col.f32.bf16.bf16.f32 "
        "{%0,%1,%2,%3}, {%4,%5,%6,%7}, {%8,%9}, {%0,%1,%2,%3};"
        : "+f"(c[0]), "+f"(c[1]), "+f"(c[2]), "+f"(c[3])
        : "r"(a[0]), "r"(a[1]), "r"(a[2]), "r"(a[3]), "r"(b[0]), "r"(b[1]));
}
__device__ __forceinline__ void ldmA(unsigned a[4], unsigned addr) {
    asm volatile("ldmatrix.sync.aligned.m8n8.x4.shared.b16 {%0,%1,%2,%3}, [%4];"
                 : "=r"(a[0]), "=r"(a[1]), "=r"(a[2]), "=r"(a[3]) : "r"(addr));
}
__device__ __forceinline__ void ldmB(unsigned b[2], unsigned addr) {
    asm volatile("ldmatrix.sync.aligned.m8n8.x2.trans.shared.b16 {%0,%1}, [%2];"
                 : "=r"(b[0]), "=r"(b[1]) : "r"(addr));
}
__device__ __forceinline__ void cpa16(unsigned dst, const void* src) {
    asm volatile("cp.async.cg.shared.global [%0], [%1], 16;"
                 :: "r"(dst), "l"(src));
}

template <int RELU, int WF32, int WBF>
__global__ __launch_bounds__(256)
void bgemm(const __nv_bfloat16* __restrict__ Ah, const __nv_bfloat16* __restrict__ Al,
           const __nv_bfloat16* __restrict__ Bh, const __nv_bfloat16* __restrict__ Bl,
           const float* __restrict__ bias,
           float* __restrict__ Cf,
           __nv_bfloat16* __restrict__ Ch, __nv_bfloat16* __restrict__ Cl,
           int M, int N, int K) {
    __shared__ __align__(16) __nv_bfloat16 sA[2 * 2 * GBM * ASTR];
    __shared__ __align__(16) __nv_bfloat16 sB[2 * 2 * GBK * BSTR];

    const int tid  = threadIdx.x;
    const int lane = tid & 31;
    const int wid  = tid >> 5;
    const int wm   = wid & 3;       // 4 warps along M (16 rows each)
    const int wn   = wid >> 2;      // 2 warps along N (32 cols each)
    const int bm   = blockIdx.y * GBM;
    const int bn   = blockIdx.x * GBN;

    const unsigned saddrA = (unsigned)__cvta_generic_to_shared(sA);
    const unsigned saddrB = (unsigned)__cvta_generic_to_shared(sB);
    const unsigned aBufB  = GBM * ASTR * 2;
    const unsigned bBufB  = GBK * BSTR * 2;

    const int ar  = tid >> 2;           // A row 0..63
    const int ac0 = (tid & 3) << 3;     // A col 0,8,16,24
    const int br  = tid >> 3;           // B row 0..31
    const int bc  = (tid & 7) << 3;     // B col 0..56

    const int a_r  = (lane & 7) + ((lane >> 3) & 1) * 8;
    const int a_k8 = (lane >> 4) * 8;
    const int b_r  = lane & 15;

    float acc[4][4];
#pragma unroll
    for (int nt = 0; nt < 4; nt++)
#pragma unroll
        for (int i = 0; i < 4; i++) acc[nt][i] = 0.f;

    const int ntk = K >> 5;

    auto stage = [&](int t, int buf) {
        const int k0 = t * GBK;
        size_t ga = (size_t)(bm + ar) * K + k0 + ac0;
        unsigned da = saddrA + (unsigned)(buf * 2) * aBufB + (ar * ASTR + ac0) * 2;
        cpa16(da,         Ah + ga);
        cpa16(da + aBufB, Al + ga);
        size_t gb = (size_t)(k0 + br) * N + bn + bc;
        unsigned db = saddrB + (unsigned)(buf * 2) * bBufB + (br * BSTR + bc) * 2;
        cpa16(db,         Bh + gb);
        cpa16(db + bBufB, Bl + gb);
        asm volatile("cp.async.commit_group;");
    };

    stage(0, 0);

    for (int t = 0; t < ntk; t++) {
        asm volatile("cp.async.wait_group 0;");
        __syncthreads();
        if (t + 1 < ntk) stage(t + 1, (t + 1) & 1);

        const int buf = t & 1;
        const unsigned base_ah = saddrA + (unsigned)(buf * 2) * aBufB;
        const unsigned base_al = base_ah + aBufB;
        const unsigned base_bh = saddrB + (unsigned)(buf * 2) * bBufB;
        const unsigned base_bl = base_bh + bBufB;

#pragma unroll
        for (int kk = 0; kk < GBK; kk += 16) {
            unsigned ah[4], al_[4];
            unsigned ro = ((wm * 16 + a_r) * ASTR + kk + a_k8) * 2;
            ldmA(ah,  base_ah + ro);
            ldmA(al_, base_al + ro);
#pragma unroll
            for (int nt = 0; nt < 4; nt++) {
                unsigned bh[2], bl_[2];
                unsigned bo = ((kk + b_r) * BSTR + wn * 32 + nt * 8) * 2;
                ldmB(bh,  base_bh + bo);
                ldmB(bl_, base_bl + bo);
                mma_bf16(acc[nt], ah,  bh);
                mma_bf16(acc[nt], ah,  bl_);
                mma_bf16(acc[nt], al_, bh);
            }
        }
        __syncthreads();
    }

    // epilogue
    const int g  = lane >> 2;
    const int tq = lane & 3;
#pragma unroll
    for (int nt = 0; nt < 4; nt++) {
        int row = bm + wm * 16 + g;
        int col = bn + wn * 32 + nt * 8 + tq * 2;
        float bz0 = bias[col], bz1 = bias[col + 1];
        float v0 = acc[nt][0] + bz0;
        float v1 = acc[nt][1] + bz1;
        float v2 = acc[nt][2] + bz0;
        float v3 = acc[nt][3] + bz1;
        if (RELU) {
            v0 = fmaxf(v0, 0.f); v1 = fmaxf(v1, 0.f);
            v2 = fmaxf(v2, 0.f); v3 = fmaxf(v3, 0.f);
        }
        if (WF32) {
            float2 o0 = {v0, v1}, o1 = {v2, v3};
            *reinterpret_cast<float2*>(&Cf[(size_t)row * N + col]) = o0;
            *reinterpret_cast<float2*>(&Cf[(size_t)(row + 8) * N + col]) = o1;
        }
        if (WBF) {
            __nv_bfloat16 h0 = __float2bfloat16(v0);
            __nv_bfloat16 h1 = __float2bfloat16(v1);
            __nv_bfloat16 h2 = __float2bfloat16(v2);
            __nv_bfloat16 h3 = __float2bfloat16(v3);
            unsigned hp0 = (unsigned)__bfloat16_as_ushort(h0) |
                           ((unsigned)__bfloat16_as_ushort(h1) << 16);
            unsigned hp1 = (unsigned)__bfloat16_as_ushort(h2) |
                           ((unsigned)__bfloat16_as_ushort(h3) << 16);
            unsigned lp0 = (unsigned)__bfloat16_as_ushort(
                               __float2bfloat16(v0 - __bfloat162float(h0))) |
                           ((unsigned)__bfloat16_as_ushort(
                               __float2bfloat16(v1 - __bfloat162float(h1))) << 16);
            unsigned lp1 = (unsigned)__bfloat16_as_ushort(
                               __float2bfloat16(v2 - __bfloat162float(h2))) |
                           ((unsigned)__bfloat16_as_ushort(
                               __float2bfloat16(v3 - __bfloat162float(h3))) << 16);
            *reinterpret_cast<unsigned*>(&Ch[(size_t)row * N + col]) = hp0;
            *reinterpret_cast<unsigned*>(&Ch[(size_t)(row + 8) * N + col]) = hp1;
            *reinterpret_cast<unsigned*>(&Cl[(size_t)row * N + col]) = lp0;
            *reinterpret_cast<unsigned*>(&Cl[(size_t)(row + 8) * N + col]) = lp1;
        }
    }
}

// ---------------- row squared-norms (rows of width 128), fused histogram ---
template <int DO_HIST>
__global__ void rownorm_kernel(const float* __restrict__ X,
                               float* __restrict__ out, int rows) {
    int gw = (int)((blockIdx.x * (size_t)blockDim.x + threadIdx.x) >> 5);
    int lane = threadIdx.x & 31;
    if (gw >= rows) return;
    float4 v = reinterpret_cast<const float4*>(X + (size_t)gw * 128)[lane];
    float s = v.x * v.x + v.y * v.y + v.z * v.z + v.w * v.w;
#pragma unroll
    for (int o = 16; o; o >>= 1) s += __shfl_xor_sync(0xffffffffu, s, o);
    if (lane == 0) {
        out[gw] = s;
        if (DO_HIST) atomicAdd(&g_hist[kn_bucket(s)], 1);
    }
}

// ---------------- scan / scatter over ALL keys ------------------------------
__global__ void scan_kernel() {
    __shared__ int s[NB];
    __shared__ int tmp[NB];
    const int tid = threadIdx.x;   // 1024
    for (int i = tid; i < NB; i += 1024) s[i] = g_hist[i];
    __syncthreads();
    for (int off = 1; off < NB; off <<= 1) {
        for (int i = tid; i < NB; i += 1024)
            tmp[i] = s[i] + (i >= off ? s[i - off] : 0);
        __syncthreads();
        for (int i = tid; i < NB; i += 1024) s[i] = tmp[i];
        __syncthreads();
    }
    for (int i = tid; i < NB; i += 1024)
        g_cursor[i] = (i == 0) ? 0 : s[i - 1];
}

__global__ void scatter_kernel() {
    int n = blockIdx.x * blockDim.x + threadIdx.x;
    if (n >= NKEYS) return;
    float kn = g_kn[n];
    int b = kn_bucket(kn);
    int pos = atomicAdd(&g_cursor[b], 1);
    g_scand[pos] = n;
    g_skn[pos]   = kn;
    g_sblo[pos]  = kn_floor(b);
}

// ---------------- exact rescore + top-5 + weighted gather ------------------
// All keys bucket-sorted ascending by kn; provably-safe early exit:
//   d2(n) >= qn + kn - 2*qb*sqrt(kn) >= qn + f(blo)   (f increasing for kn>qb^2;
//   reachable exit checks all have blo >= ~64 >> qb^2)
__global__ __launch_bounds__(128, 8)
void rescore_kernel(const float* __restrict__ keys,
                    const float* __restrict__ values,
                    float* __restrict__ conf_out) {
    const int b = blockIdx.x;
    const int tid = threadIdx.x;
    __shared__ float sq[CDIM];
    __shared__ float dv[128];
    __shared__ int   di[128];
    __shared__ float rd[KNN];
    __shared__ int   ri[KNN];
    __shared__ float rv[128];
    __shared__ int   rvi[128];
    __shared__ int   rvj[128];
    __shared__ float sw[KNN];
    __shared__ int   s_stop;

    sq[tid] = g_cq[(size_t)b * CDIM + tid];
    if (tid < KNN) { rd[tid] = 3.4e38f; ri[tid] = 0x7fffffff; }
    if (tid == 0) s_stop = 0;
    const float qn = g_qn[b];
    const float qb = sqrtf(qn);
    __syncthreads();

    for (int c0 = 0; c0 < NKEYS; c0 += 128) {
        if (tid == 0 && c0 > 0) {
            float blo = g_sblo[c0];
            float lb = qn + blo - 2.f * qb * sqrtf(blo) - 1e-3f;
            if (lb > rd[KNN - 1]) s_stop = 1;
        }
        __syncthreads();
        if (s_stop) break;

        int len = min(128, NKEYS - c0);
        int j = c0 + tid;
        if (tid < len) {
            int n = g_scand[j];
            const float4* kr = reinterpret_cast<const float4*>(keys + (size_t)n * CDIM);
            const float4* sq4 = reinterpret_cast<const float4*>(sq);
            float a0 = 0.f, a1 = 0.f, a2 = 0.f, a3 = 0.f;
#pragma unroll
            for (int d = 0; d < CDIM / 4; d++) {
                float4 kv = __ldg(&kr[d]);
                float4 qv = sq4[d];
                a0 = fmaf(qv.x, kv.x, a0);
                a1 = fmaf(qv.y, kv.y, a1);
                a2 = fmaf(qv.z, kv.z, a2);
                a3 = fmaf(qv.w, kv.w, a3);
            }
            float dot = (a0 + a1) + (a2 + a3);
            dv[tid] = qn + g_skn[j] - 2.f * dot;
            di[tid] = n;
        } else {
            dv[tid] = 3.4e38f;
            di[tid] = 0x7fffffff;
        }
        __syncthreads();

        for (int r = 0; r < KNN; r++) {
            rv[tid] = dv[tid]; rvi[tid] = di[tid]; rvj[tid] = tid;
            __syncthreads();
#pragma unroll
            for (int s = 64; s >= 1; s >>= 1) {
                if (tid < s) {
                    if (rv[tid + s] < rv[tid] ||
                        (rv[tid + s] == rv[tid] && rvi[tid + s] < rvi[tid])) {
                        rv[tid] = rv[tid + s];
                        rvi[tid] = rvi[tid + s];
                        rvj[tid] = rvj[tid + s];
                    }
                }
                __syncthreads();
            }
            if (tid == 0) {
                float v = rv[0]; int n = rvi[0];
                if (v < rd[KNN - 1] || (v == rd[KNN - 1] && n < ri[KNN - 1])) {
                    int p = KNN - 1;
                    while (p > 0 && (rd[p - 1] > v ||
                                     (rd[p - 1] == v && ri[p - 1] > n))) {
                        rd[p] = rd[p - 1]; ri[p] = ri[p - 1]; p--;
                    }
                    rd[p] = v; ri[p] = n;
                }
                dv[rvj[0]] = 3.4e38f;
            }
            __syncthreads();
        }
    }

    if (tid == 0) {
        float w[KNN], ws = 0.f;
#pragma unroll
        for (int j2 = 0; j2 < KNN; j2++) { w[j2] = 1.f / (rd[j2] + EPSW); ws += w[j2]; }
#pragma unroll
        for (int j2 = 0; j2 < KNN; j2++) sw[j2] = w[j2] / ws;
        conf_out[b] = 1.f / (rd[0] + EPSW);
    }
    __syncthreads();

    float acc = 0.f;
#pragma unroll
    for (int j2 = 0; j2 < KNN; j2++)
        acc += sw[j2] * values[(size_t)ri[j2] * CDIM + tid];
    __nv_bfloat16 hb = __float2bfloat16(acc);
    g_wh[(size_t)b * CDIM + tid] = hb;
    g_wl[(size_t)b * CDIM + tid] = __float2bfloat16(acc - __bfloat162float(hb));
}

// ---------------- launch ----------------------------------------------------
extern "C" void kernel_launch(void* const* d_in, const int* in_sizes, int n_in,
                              void* d_out, int out_size) {
    const float* query = (const float*)d_in[0];
    const float* W1    = (const float*)d_in[1];
    const float* b1    = (const float*)d_in[2];
    const float* W2    = (const float*)d_in[3];
    const float* b2    = (const float*)d_in[4];
    const float* W3    = (const float*)d_in[5];
    const float* b3    = (const float*)d_in[6];
    const float* keys  = (const float*)d_in[7];
    const float* values= (const float*)d_in[8];
    const float* D1w   = (const float*)d_in[9];
    const float* D1b   = (const float*)d_in[10];
    const float* D2w   = (const float*)d_in[11];
    const float* D2b   = (const float*)d_in[12];
    const float* D3w   = (const float*)d_in[13];
    const float* D3b   = (const float*)d_in[14];

    float* out  = (float*)d_out;
    float* conf = out + (size_t)BQ * DIM;

    void *qh, *ql, *W1h, *W1l, *W2h, *W2l, *W3h, *W3l;
    void *D1h, *D1l, *D2h, *D2l, *D3h, *D3l;
    void *h1h, *h1l, *h2h, *h2l, *wh, *wl, *g1h, *g1l, *g2h, *g2l;
    void *cq, *qn, *kn;
    cudaGetSymbolAddress(&qh, g_qh);   cudaGetSymbolAddress(&ql, g_ql);
    cudaGetSymbolAddress(&W1h, g_W1h); cudaGetSymbolAddress(&W1l, g_W1l);
    cudaGetSymbolAddress(&W2h, g_W2h); cudaGetSymbolAddress(&W2l, g_W2l);
    cudaGetSymbolAddress(&W3h, g_W3h); cudaGetSymbolAddress(&W3l, g_W3l);
    cudaGetSymbolAddress(&D1h, g_D1h); cudaGetSymbolAddress(&D1l, g_D1l);
    cudaGetSymbolAddress(&D2h, g_D2h); cudaGetSymbolAddress(&D2l, g_D2l);
    cudaGetSymbolAddress(&D3h, g_D3h); cudaGetSymbolAddress(&D3l, g_D3l);
    cudaGetSymbolAddress(&h1h, g_h1h); cudaGetSymbolAddress(&h1l, g_h1l);
    cudaGetSymbolAddress(&h2h, g_h2h); cudaGetSymbolAddress(&h2l, g_h2l);
    cudaGetSymbolAddress(&wh, g_wh);   cudaGetSymbolAddress(&wl, g_wl);
    cudaGetSymbolAddress(&g1h, g_g1h); cudaGetSymbolAddress(&g1l, g_g1l);
    cudaGetSymbolAddress(&g2h, g_g2h); cudaGetSymbolAddress(&g2l, g_g2l);
    cudaGetSymbolAddress(&cq, g_cq);
    cudaGetSymbolAddress(&qn, g_qn);
    cudaGetSymbolAddress(&kn, g_kn);

    init_kernel<<<NB / 256, 256>>>();

    // batched split: query + 6 weight matrices
    SplitArgs sa;
    int sizes4[7] = {BQ * DIM / 4, DIM * 512 / 4, 512 * 256 / 4, 256 * 128 / 4,
                     128 * 256 / 4, 256 * 512 / 4, 512 * 1024 / 4};
    const float* srcs[7] = {query, W1, W2, W3, D1w, D2w, D3w};
    void* hs[7] = {qh, W1h, W2h, W3h, D1h, D2h, D3h};
    void* ls[7] = {ql, W1l, W2l, W3l, D1l, D2l, D3l};
    sa.cum[0] = 0;
    for (int i = 0; i < 7; i++) {
        sa.s[i].src = srcs[i];
        sa.s[i].h = (__nv_bfloat16*)hs[i];
        sa.s[i].l = (__nv_bfloat16*)ls[i];
        sa.cum[i + 1] = sa.cum[i] + sizes4[i];
    }
    split_batch_kernel<<<(sa.cum[7] + 255) / 256, 256>>>(sa);

    // key norms + fused histogram -> scan -> scatter (bucket-sort all keys)
    rownorm_kernel<1><<<(NKEYS * 32 + 255) / 256, 256>>>(keys, (float*)kn, NKEYS);
    scan_kernel<<<1, 1024>>>();
    scatter_kernel<<<(NKEYS + 255) / 256, 256>>>();

    // Encode MLP
    bgemm<1, 0, 1><<<dim3(512 / GBN, BQ / GBM), 256>>>(
        (__nv_bfloat16*)qh, (__nv_bfloat16*)ql, (__nv_bfloat16*)W1h, (__nv_bfloat16*)W1l,
        b1, nullptr, (__nv_bfloat16*)h1h, (__nv_bfloat16*)h1l, BQ, 512, 1024);
    bgemm<1, 0, 1><<<dim3(256 / GBN, BQ / GBM), 256>>>(
        (__nv_bfloat16*)h1h, (__nv_bfloat16*)h1l, (__nv_bfloat16*)W2h, (__nv_bfloat16*)W2l,
        b2, nullptr, (__nv_bfloat16*)h2h, (__nv_bfloat16*)h2l, BQ, 256, 512);
    bgemm<0, 1, 0><<<dim3(128 / GBN, BQ / GBM), 256>>>(
        (__nv_bfloat16*)h2h, (__nv_bfloat16*)h2l, (__nv_bfloat16*)W3h, (__nv_bfloat16*)W3l,
        b3, (float*)cq, nullptr, nullptr, BQ, 128, 256);

    // query norms (no histogram)
    rownorm_kernel<0><<<(BQ * 32 + 255) / 256, 256>>>((float*)cq, (float*)qn, BQ);

    // exact rescore + top-5 + gather (emits weighted as bf16 hi/lo)
    rescore_kernel<<<BQ, 128>>>(keys, values, conf);

    // Decode MLP
    bgemm<1, 0, 1><<<dim3(256 / GBN, BQ / GBM), 256>>>(
        (__nv_bfloat16*)wh, (__nv_bfloat16*)wl, (__nv_bfloat16*)D1h, (__nv_bfloat16*)D1l,
        D1b, nullptr, (__nv_bfloat16*)g1h, (__nv_bfloat16*)g1l, BQ, 256, 128);
    bgemm<1, 0, 1><<<dim3(512 / GBN, BQ / GBM), 256>>>(
        (__nv_bfloat16*)g1h, (__nv_bfloat16*)g1l, (__nv_bfloat16*)D2h, (__nv_bfloat16*)D2l,
        D2b, nullptr, (__nv_bfloat16*)g2h, (__nv_bfloat16*)g2l, BQ, 512, 256);
    bgemm<0, 1, 0><<<dim3(1024 / GBN, BQ / GBM), 256>>>(
        (__nv_bfloat16*)g2h, (__nv_bfloat16*)g2l, (__nv_bfloat16*)D3h, (__nv_bfloat16*)D3l,
        D3b, out, nullptr, nullptr, BQ, 1024, 512);
}

// round 9
// speedup vs baseline: 1.2102x; 1.0786x over previous
#include <cuda_runtime.h>
#include <cuda_bf16.h>
#include <math.h>

// Problem constants (fixed by setup_inputs)
#define BQ    1024
#define DIM   1024
#define CDIM  128
#define NKEYS 100000
#define KNN   5
#define EPSW  1e-6f
#define NB    2048
// fixed kn->bucket mapping: covers kn in [64,192]; kn ~ chi2(128) (mean 128, sd 16)
#define KN_LO 64.0f
#define KN_SPAN 128.0f

// ---------------- scratch (device globals; no allocations allowed) ---------
__device__ __align__(16) __nv_bfloat16 g_qh[BQ * DIM],   g_ql[BQ * DIM];
__device__ __align__(16) __nv_bfloat16 g_W1h[DIM * 512], g_W1l[DIM * 512];
__device__ __align__(16) __nv_bfloat16 g_W2h[512 * 256], g_W2l[512 * 256];
__device__ __align__(16) __nv_bfloat16 g_W3h[256 * 128], g_W3l[256 * 128];
__device__ __align__(16) __nv_bfloat16 g_D1h[128 * 256], g_D1l[128 * 256];
__device__ __align__(16) __nv_bfloat16 g_D2h[256 * 512], g_D2l[256 * 512];
__device__ __align__(16) __nv_bfloat16 g_D3h[512 * 1024], g_D3l[512 * 1024];
__device__ __align__(16) __nv_bfloat16 g_h1h[BQ * 512], g_h1l[BQ * 512];
__device__ __align__(16) __nv_bfloat16 g_h2h[BQ * 256], g_h2l[BQ * 256];
__device__ __align__(16) __nv_bfloat16 g_wh[BQ * CDIM], g_wl[BQ * CDIM];
__device__ __align__(16) __nv_bfloat16 g_g1h[BQ * 256], g_g1l[BQ * 256];
__device__ __align__(16) __nv_bfloat16 g_g2h[BQ * 512], g_g2l[BQ * 512];

__device__ float g_cq[BQ * CDIM];
__device__ float g_qn[BQ];
__device__ float g_kn[NKEYS];
__device__ int   g_hist[NB];
__device__ int   g_cursor[NB];
__device__ int   g_scand[NKEYS];
__device__ float g_skn[NKEYS];
__device__ float g_sblo[NKEYS];

// ---------------- fixed bucket mapping --------------------------------------
__device__ __forceinline__ int kn_bucket(float kn) {
    int b = (int)((kn - KN_LO) * ((float)NB / KN_SPAN));
    return min(NB - 1, max(0, b));
}
__device__ __forceinline__ float kn_floor(int b) {
    // valid lower bound on kn for every key in buckets >= b
    return (b == 0) ? 0.f : (KN_LO + (float)b * (KN_SPAN / (float)NB));
}

// ---------------- batched fp32 -> bf16 hi/lo split (+ hist zero) -----------
struct SplitSeg { const float* src; __nv_bfloat16* h; __nv_bfloat16* l; };
struct SplitArgs { SplitSeg s[7]; int cum[8]; };

__global__ void split_batch_kernel(SplitArgs a) {
    int i = blockIdx.x * blockDim.x + threadIdx.x;   // float4 units
    if (i < NB) g_hist[i] = 0;                       // fused histogram init
    if (i >= a.cum[7]) return;
    int sg = 0;
    while (i >= a.cum[sg + 1]) sg++;
    int j = i - a.cum[sg];
    float4 v = reinterpret_cast<const float4*>(a.s[sg].src)[j];
    float x[4] = {v.x, v.y, v.z, v.w};
    unsigned short h[4], l[4];
#pragma unroll
    for (int q = 0; q < 4; q++) {
        __nv_bfloat16 hb = __float2bfloat16(x[q]);
        __nv_bfloat16 lb = __float2bfloat16(x[q] - __bfloat162float(hb));
        h[q] = __bfloat16_as_ushort(hb);
        l[q] = __bfloat16_as_ushort(lb);
    }
    uint2 hp = {(unsigned)h[0] | ((unsigned)h[1] << 16),
                (unsigned)h[2] | ((unsigned)h[3] << 16)};
    uint2 lp = {(unsigned)l[0] | ((unsigned)l[1] << 16),
                (unsigned)l[2] | ((unsigned)l[3] << 16)};
    reinterpret_cast<uint2*>(a.s[sg].h)[j] = hp;
    reinterpret_cast<uint2*>(a.s[sg].l)[j] = lp;
}

// ============================================================================
// bf16 hi/lo tensor-core GEMM. Tile 64x64, BK=32, 256 threads / 8 warps;
// warp tile 16x32 (1x m16 x 4x n8). AhBh + AhBl + AlBh, fp32 accumulate.
// cp.async double buffered.  (unchanged from round 8)
// ============================================================================
#define GBM 64
#define GBN 64
#define GBK 32
#define ASTR 40
#define BSTR 72

__device__ __forceinline__ void mma_bf16(float c[4], const unsigned a[4],
                                         const unsigned b[2]) {
    asm volatile(
        "mma.sync.aligned.m16n8k16.row.col.f32.bf16.bf16.f32 "
        "{%0,%1,%2,%3}, {%4,%5,%6,%7}, {%8,%9}, {%0,%1,%2,%3};"
        : "+f"(c[0]), "+f"(c[1]), "+f"(c[2]), "+f"(c[3])
        : "r"(a[0]), "r"(a[1]), "r"(a[2]), "r"(a[3]), "r"(b[0]), "r"(b[1]));
}
__device__ __forceinline__ void ldmA(unsigned a[4], unsigned addr) {
    asm volatile("ldmatrix.sync.aligned.m8n8.x4.shared.b16 {%0,%1,%2,%3}, [%4];"
                 : "=r"(a[0]), "=r"(a[1]), "=r"(a[2]), "=r"(a[3]) : "r"(addr));
}
__device__ __forceinline__ void ldmB(unsigned b[2], unsigned addr) {
    asm volatile("ldmatrix.sync.aligned.m8n8.x2.trans.shared.b16 {%0,%1}, [%2];"
                 : "=r"(b[0]), "=r"(b[1]) : "r"(addr));
}
__device__ __forceinline__ void cpa16(unsigned dst, const void* src) {
    asm volatile("cp.async.cg.shared.global [%0], [%1], 16;"
                 :: "r"(dst), "l"(src));
}

template <int RELU, int WF32, int WBF>
__global__ __launch_bounds__(256)
void bgemm(const __nv_bfloat16* __restrict__ Ah, const __nv_bfloat16* __restrict__ Al,
           const __nv_bfloat16* __restrict__ Bh, const __nv_bfloat16* __restrict__ Bl,
           const float* __restrict__ bias,
           float* __restrict__ Cf,
           __nv_bfloat16* __restrict__ Ch, __nv_bfloat16* __restrict__ Cl,
           int M, int N, int K) {
    __shared__ __align__(16) __nv_bfloat16 sA[2 * 2 * GBM * ASTR];
    __shared__ __align__(16) __nv_bfloat16 sB[2 * 2 * GBK * BSTR];

    const int tid  = threadIdx.x;
    const int lane = tid & 31;
    const int wid  = tid >> 5;
    const int wm   = wid & 3;       // 4 warps along M (16 rows each)
    const int wn   = wid >> 2;      // 2 warps along N (32 cols each)
    const int bm   = blockIdx.y * GBM;
    const int bn   = blockIdx.x * GBN;

    const unsigned saddrA = (unsigned)__cvta_generic_to_shared(sA);
    const unsigned saddrB = (unsigned)__cvta_generic_to_shared(sB);
    const unsigned aBufB  = GBM * ASTR * 2;
    const unsigned bBufB  = GBK * BSTR * 2;

    const int ar  = tid >> 2;           // A row 0..63
    const int ac0 = (tid & 3) << 3;     // A col 0,8,16,24
    const int br  = tid >> 3;           // B row 0..31
    const int bc  = (tid & 7) << 3;     // B col 0..56

    const int a_r  = (lane & 7) + ((lane >> 3) & 1) * 8;
    const int a_k8 = (lane >> 4) * 8;
    const int b_r  = lane & 15;

    float acc[4][4];
#pragma unroll
    for (int nt = 0; nt < 4; nt++)
#pragma unroll
        for (int i = 0; i < 4; i++) acc[nt][i] = 0.f;

    const int ntk = K >> 5;

    auto stage = [&](int t, int buf) {
        const int k0 = t * GBK;
        size_t ga = (size_t)(bm + ar) * K + k0 + ac0;
        unsigned da = saddrA + (unsigned)(buf * 2) * aBufB + (ar * ASTR + ac0) * 2;
        cpa16(da,         Ah + ga);
        cpa16(da + aBufB, Al + ga);
        size_t gb = (size_t)(k0 + br) * N + bn + bc;
        unsigned db = saddrB + (unsigned)(buf * 2) * bBufB + (br * BSTR + bc) * 2;
        cpa16(db,         Bh + gb);
        cpa16(db + bBufB, Bl + gb);
        asm volatile("cp.async.commit_group;");
    };

    stage(0, 0);

    for (int t = 0; t < ntk; t++) {
        asm volatile("cp.async.wait_group 0;");
        __syncthreads();
        if (t + 1 < ntk) stage(t + 1, (t + 1) & 1);

        const int buf = t & 1;
        const unsigned base_ah = saddrA + (unsigned)(buf * 2) * aBufB;
        const unsigned base_al = base_ah + aBufB;
        const unsigned base_bh = saddrB + (unsigned)(buf * 2) * bBufB;
        const unsigned base_bl = base_bh + bBufB;

#pragma unroll
        for (int kk = 0; kk < GBK; kk += 16) {
            unsigned ah[4], al_[4];
            unsigned ro = ((wm * 16 + a_r) * ASTR + kk + a_k8) * 2;
            ldmA(ah,  base_ah + ro);
            ldmA(al_, base_al + ro);
#pragma unroll
            for (int nt = 0; nt < 4; nt++) {
                unsigned bh[2], bl_[2];
                unsigned bo = ((kk + b_r) * BSTR + wn * 32 + nt * 8) * 2;
                ldmB(bh,  base_bh + bo);
                ldmB(bl_, base_bl + bo);
                mma_bf16(acc[nt], ah,  bh);
                mma_bf16(acc[nt], ah,  bl_);
                mma_bf16(acc[nt], al_, bh);
            }
        }
        __syncthreads();
    }

    // epilogue
    const int g  = lane >> 2;
    const int tq = lane & 3;
#pragma unroll
    for (int nt = 0; nt < 4; nt++) {
        int row = bm + wm * 16 + g;
        int col = bn + wn * 32 + nt * 8 + tq * 2;
        float bz0 = bias[col], bz1 = bias[col + 1];
        float v0 = acc[nt][0] + bz0;
        float v1 = acc[nt][1] + bz1;
        float v2 = acc[nt][2] + bz0;
        float v3 = acc[nt][3] + bz1;
        if (RELU) {
            v0 = fmaxf(v0, 0.f); v1 = fmaxf(v1, 0.f);
            v2 = fmaxf(v2, 0.f); v3 = fmaxf(v3, 0.f);
        }
        if (WF32) {
            float2 o0 = {v0, v1}, o1 = {v2, v3};
            *reinterpret_cast<float2*>(&Cf[(size_t)row * N + col]) = o0;
            *reinterpret_cast<float2*>(&Cf[(size_t)(row + 8) * N + col]) = o1;
        }
        if (WBF) {
            __nv_bfloat16 h0 = __float2bfloat16(v0);
            __nv_bfloat16 h1 = __float2bfloat16(v1);
            __nv_bfloat16 h2 = __float2bfloat16(v2);
            __nv_bfloat16 h3 = __float2bfloat16(v3);
            unsigned hp0 = (unsigned)__bfloat16_as_ushort(h0) |
                           ((unsigned)__bfloat16_as_ushort(h1) << 16);
            unsigned hp1 = (unsigned)__bfloat16_as_ushort(h2) |
                           ((unsigned)__bfloat16_as_ushort(h3) << 16);
            unsigned lp0 = (unsigned)__bfloat16_as_ushort(
                               __float2bfloat16(v0 - __bfloat162float(h0))) |
                           ((unsigned)__bfloat16_as_ushort(
                               __float2bfloat16(v1 - __bfloat162float(h1))) << 16);
            unsigned lp1 = (unsigned)__bfloat16_as_ushort(
                               __float2bfloat16(v2 - __bfloat162float(h2))) |
                           ((unsigned)__bfloat16_as_ushort(
                               __float2bfloat16(v3 - __bfloat162float(h3))) << 16);
            *reinterpret_cast<unsigned*>(&Ch[(size_t)row * N + col]) = hp0;
            *reinterpret_cast<unsigned*>(&Ch[(size_t)(row + 8) * N + col]) = hp1;
            *reinterpret_cast<unsigned*>(&Cl[(size_t)row * N + col]) = lp0;
            *reinterpret_cast<unsigned*>(&Cl[(size_t)(row + 8) * N + col]) = lp1;
        }
    }
}

// ---------------- row squared-norms (rows of width 128), fused histogram ---
template <int DO_HIST>
__global__ void rownorm_kernel(const float* __restrict__ X,
                               float* __restrict__ out, int rows) {
    int gw = (int)((blockIdx.x * (size_t)blockDim.x + threadIdx.x) >> 5);
    int lane = threadIdx.x & 31;
    if (gw >= rows) return;
    float4 v = reinterpret_cast<const float4*>(X + (size_t)gw * 128)[lane];
    float s = v.x * v.x + v.y * v.y + v.z * v.z + v.w * v.w;
#pragma unroll
    for (int o = 16; o; o >>= 1) s += __shfl_xor_sync(0xffffffffu, s, o);
    if (lane == 0) {
        out[gw] = s;
        if (DO_HIST) atomicAdd(&g_hist[kn_bucket(s)], 1);
    }
}

// ---------------- exclusive scan: warp-shuffle two-level (1024 thr, 2/thr) --
__global__ void scan_kernel() {
    __shared__ int wsum[32];
    const int t = threadIdx.x;
    const int lane = t & 31, w = t >> 5;
    int a = g_hist[2 * t], b2 = g_hist[2 * t + 1];
    int s = a + b2;
    int x = s;
#pragma unroll
    for (int o = 1; o < 32; o <<= 1) {
        int y = __shfl_up_sync(0xffffffffu, x, o);
        if (lane >= o) x += y;
    }
    if (lane == 31) wsum[w] = x;
    __syncthreads();
    if (w == 0) {
        int v = wsum[lane];
#pragma unroll
        for (int o = 1; o < 32; o <<= 1) {
            int y = __shfl_up_sync(0xffffffffu, v, o);
            if (lane >= o) v += y;
        }
        wsum[lane] = v;
    }
    __syncthreads();
    int incl = x + (w > 0 ? wsum[w - 1] : 0);
    int excl = incl - s;
    g_cursor[2 * t]     = excl;
    g_cursor[2 * t + 1] = excl + a;
}

__global__ void scatter_kernel() {
    int n = blockIdx.x * blockDim.x + threadIdx.x;
    if (n >= NKEYS) return;
    float kn = g_kn[n];
    int b = kn_bucket(kn);
    int pos = atomicAdd(&g_cursor[b], 1);
    g_scand[pos] = n;
    g_skn[pos]   = kn;
    g_sblo[pos]  = kn_floor(b);
}

// ---------------- exact rescore + top-5 + weighted gather ------------------
// Keys bucket-sorted ascending by kn. Per 128-key chunk: each warp computes
// its exact top-5 via argmin-lex shuffles (no block barriers), tid0 merges
// 4x5 entries into the running top-5 and evaluates the provably-safe exit:
//   d2(n) >= qn + kn - 2*qb*sqrt(kn) >= qn + f(blo)   (f increasing, blo>>qb^2)
__global__ __launch_bounds__(128, 8)
void rescore_kernel(const float* __restrict__ keys,
                    const float* __restrict__ values,
                    float* __restrict__ conf_out) {
    const int b = blockIdx.x;
    const int tid = threadIdx.x;
    const int lane = tid & 31;
    const int wid = tid >> 5;
    __shared__ float sq[CDIM];
    __shared__ float rd[KNN];
    __shared__ int   ri[KNN];
    __shared__ float wv[4][KNN];
    __shared__ int   wi[4][KNN];
    __shared__ float sw[KNN];
    __shared__ int   s_stop;

    sq[tid] = g_cq[(size_t)b * CDIM + tid];
    if (tid < KNN) { rd[tid] = 3.4e38f; ri[tid] = 0x7fffffff; }
    if (tid == 0) s_stop = 0;
    const float qn = g_qn[b];
    const float qb = sqrtf(qn);
    __syncthreads();

    for (int c0 = 0; c0 < NKEYS; c0 += 128) {
        int j = c0 + tid;
        float d = 3.4e38f;
        int   nidx = 0x7fffffff;
        if (j < NKEYS) {
            int n = g_scand[j];
            const float4* kr = reinterpret_cast<const float4*>(keys + (size_t)n * CDIM);
            const float4* sq4 = reinterpret_cast<const float4*>(sq);
            float a0 = 0.f, a1 = 0.f, a2 = 0.f, a3 = 0.f;
#pragma unroll
            for (int dd = 0; dd < CDIM / 4; dd++) {
                float4 kv = __ldg(&kr[dd]);
                float4 qv = sq4[dd];
                a0 = fmaf(qv.x, kv.x, a0);
                a1 = fmaf(qv.y, kv.y, a1);
                a2 = fmaf(qv.z, kv.z, a2);
                a3 = fmaf(qv.w, kv.w, a3);
            }
            float dot = (a0 + a1) + (a2 + a3);
            d = qn + g_skn[j] - 2.f * dot;
            nidx = n;
        }

        // warp top-5 via 5 argmin-lex rounds (shuffles only)
#pragma unroll
        for (int r = 0; r < KNN; r++) {
            float v = d; int ix = nidx;
#pragma unroll
            for (int o = 16; o; o >>= 1) {
                float v2 = __shfl_xor_sync(0xffffffffu, v, o);
                int   i2 = __shfl_xor_sync(0xffffffffu, ix, o);
                if (v2 < v || (v2 == v && i2 < ix)) { v = v2; ix = i2; }
            }
            if (lane == 0) { wv[wid][r] = v; wi[wid][r] = ix; }
            if (d == v && nidx == ix) { d = 3.4e38f; nidx = 0x7fffffff; }
        }
        __syncthreads();

        if (tid == 0) {
            // merge 4 warps x 5 entries into running top-5
#pragma unroll
            for (int w = 0; w < 4; w++) {
#pragma unroll
                for (int r = 0; r < KNN; r++) {
                    float v = wv[w][r]; int n = wi[w][r];
                    if (v < rd[KNN - 1] || (v == rd[KNN - 1] && n < ri[KNN - 1])) {
                        int p = KNN - 1;
                        while (p > 0 && (rd[p - 1] > v ||
                                         (rd[p - 1] == v && ri[p - 1] > n))) {
                            rd[p] = rd[p - 1]; ri[p] = ri[p - 1]; p--;
                        }
                        rd[p] = v; ri[p] = n;
                    }
                }
            }
            // exit check for next chunk
            if (c0 + 128 < NKEYS) {
                float blo = g_sblo[c0 + 128];
                float lb = qn + blo - 2.f * qb * sqrtf(blo) - 1e-3f;
                if (lb > rd[KNN - 1]) s_stop = 1;
            }
        }
        __syncthreads();
        if (s_stop) break;
    }

    if (tid == 0) {
        float w[KNN], ws = 0.f;
#pragma unroll
        for (int j2 = 0; j2 < KNN; j2++) { w[j2] = 1.f / (rd[j2] + EPSW); ws += w[j2]; }
#pragma unroll
        for (int j2 = 0; j2 < KNN; j2++) sw[j2] = w[j2] / ws;
        conf_out[b] = 1.f / (rd[0] + EPSW);
    }
    __syncthreads();

    float acc = 0.f;
#pragma unroll
    for (int j2 = 0; j2 < KNN; j2++)
        acc += sw[j2] * values[(size_t)ri[j2] * CDIM + tid];
    __nv_bfloat16 hb = __float2bfloat16(acc);
    g_wh[(size_t)b * CDIM + tid] = hb;
    g_wl[(size_t)b * CDIM + tid] = __float2bfloat16(acc - __bfloat162float(hb));
}

// ---------------- launch ----------------------------------------------------
extern "C" void kernel_launch(void* const* d_in, const int* in_sizes, int n_in,
                              void* d_out, int out_size) {
    const float* query = (const float*)d_in[0];
    const float* W1    = (const float*)d_in[1];
    const float* b1    = (const float*)d_in[2];
    const float* W2    = (const float*)d_in[3];
    const float* b2    = (const float*)d_in[4];
    const float* W3    = (const float*)d_in[5];
    const float* b3    = (const float*)d_in[6];
    const float* keys  = (const float*)d_in[7];
    const float* values= (const float*)d_in[8];
    const float* D1w   = (const float*)d_in[9];
    const float* D1b   = (const float*)d_in[10];
    const float* D2w   = (const float*)d_in[11];
    const float* D2b   = (const float*)d_in[12];
    const float* D3w   = (const float*)d_in[13];
    const float* D3b   = (const float*)d_in[14];

    float* out  = (float*)d_out;
    float* conf = out + (size_t)BQ * DIM;

    void *qh, *ql, *W1h, *W1l, *W2h, *W2l, *W3h, *W3l;
    void *D1h, *D1l, *D2h, *D2l, *D3h, *D3l;
    void *h1h, *h1l, *h2h, *h2l, *wh, *wl, *g1h, *g1l, *g2h, *g2l;
    void *cq, *qn, *kn;
    cudaGetSymbolAddress(&qh, g_qh);   cudaGetSymbolAddress(&ql, g_ql);
    cudaGetSymbolAddress(&W1h, g_W1h); cudaGetSymbolAddress(&W1l, g_W1l);
    cudaGetSymbolAddress(&W2h, g_W2h); cudaGetSymbolAddress(&W2l, g_W2l);
    cudaGetSymbolAddress(&W3h, g_W3h); cudaGetSymbolAddress(&W3l, g_W3l);
    cudaGetSymbolAddress(&D1h, g_D1h); cudaGetSymbolAddress(&D1l, g_D1l);
    cudaGetSymbolAddress(&D2h, g_D2h); cudaGetSymbolAddress(&D2l, g_D2l);
    cudaGetSymbolAddress(&D3h, g_D3h); cudaGetSymbolAddress(&D3l, g_D3l);
    cudaGetSymbolAddress(&h1h, g_h1h); cudaGetSymbolAddress(&h1l, g_h1l);
    cudaGetSymbolAddress(&h2h, g_h2h); cudaGetSymbolAddress(&h2l, g_h2l);
    cudaGetSymbolAddress(&wh, g_wh);   cudaGetSymbolAddress(&wl, g_wl);
    cudaGetSymbolAddress(&g1h, g_g1h); cudaGetSymbolAddress(&g1l, g_g1l);
    cudaGetSymbolAddress(&g2h, g_g2h); cudaGetSymbolAddress(&g2l, g_g2l);
    cudaGetSymbolAddress(&cq, g_cq);
    cudaGetSymbolAddress(&qn, g_qn);
    cudaGetSymbolAddress(&kn, g_kn);

    // batched split: query + 6 weight matrices (+ fused g_hist zeroing)
    SplitArgs sa;
    int sizes4[7] = {BQ * DIM / 4, DIM * 512 / 4, 512 * 256 / 4, 256 * 128 / 4,
                     128 * 256 / 4, 256 * 512 / 4, 512 * 1024 / 4};
    const float* srcs[7] = {query, W1, W2, W3, D1w, D2w, D3w};
    void* hs[7] = {qh, W1h, W2h, W3h, D1h, D2h, D3h};
    void* ls[7] = {ql, W1l, W2l, W3l, D1l, D2l, D3l};
    sa.cum[0] = 0;
    for (int i = 0; i < 7; i++) {
        sa.s[i].src = srcs[i];
        sa.s[i].h = (__nv_bfloat16*)hs[i];
        sa.s[i].l = (__nv_bfloat16*)ls[i];
        sa.cum[i + 1] = sa.cum[i] + sizes4[i];
    }
    split_batch_kernel<<<(sa.cum[7] + 255) / 256, 256>>>(sa);

    // key norms + fused histogram -> scan -> scatter (bucket-sort all keys)
    rownorm_kernel<1><<<(NKEYS * 32 + 255) / 256, 256>>>(keys, (float*)kn, NKEYS);
    scan_kernel<<<1, 1024>>>();
    scatter_kernel<<<(NKEYS + 255) / 256, 256>>>();

    // Encode MLP
    bgemm<1, 0, 1><<<dim3(512 / GBN, BQ / GBM), 256>>>(
        (__nv_bfloat16*)qh, (__nv_bfloat16*)ql, (__nv_bfloat16*)W1h, (__nv_bfloat16*)W1l,
        b1, nullptr, (__nv_bfloat16*)h1h, (__nv_bfloat16*)h1l, BQ, 512, 1024);
    bgemm<1, 0, 1><<<dim3(256 / GBN, BQ / GBM), 256>>>(
        (__nv_bfloat16*)h1h, (__nv_bfloat16*)h1l, (__nv_bfloat16*)W2h, (__nv_bfloat16*)W2l,
        b2, nullptr, (__nv_bfloat16*)h2h, (__nv_bfloat16*)h2l, BQ, 256, 512);
    bgemm<0, 1, 0><<<dim3(128 / GBN, BQ / GBM), 256>>>(
        (__nv_bfloat16*)h2h, (__nv_bfloat16*)h2l, (__nv_bfloat16*)W3h, (__nv_bfloat16*)W3l,
        b3, (float*)cq, nullptr, nullptr, BQ, 128, 256);

    // query norms (no histogram)
    rownorm_kernel<0><<<(BQ * 32 + 255) / 256, 256>>>((float*)cq, (float*)qn, BQ);

    // exact rescore + top-5 + gather (emits weighted as bf16 hi/lo)
    rescore_kernel<<<BQ, 128>>>(keys, values, conf);

    // Decode MLP
    bgemm<1, 0, 1><<<dim3(256 / GBN, BQ / GBM), 256>>>(
        (__nv_bfloat16*)wh, (__nv_bfloat16*)wl, (__nv_bfloat16*)D1h, (__nv_bfloat16*)D1l,
        D1b, nullptr, (__nv_bfloat16*)g1h, (__nv_bfloat16*)g1l, BQ, 256, 128);
    bgemm<1, 0, 1><<<dim3(512 / GBN, BQ / GBM), 256>>>(
        (__nv_bfloat16*)g1h, (__nv_bfloat16*)g1l, (__nv_bfloat16*)D2h, (__nv_bfloat16*)D2l,
        D2b, nullptr, (__nv_bfloat16*)g2h, (__nv_bfloat16*)g2l, BQ, 512, 256);
    bgemm<0, 1, 0><<<dim3(1024 / GBN, BQ / GBM), 256>>>(
        (__nv_bfloat16*)g2h, (__nv_bfloat16*)g2l, (__nv_bfloat16*)D3h, (__nv_bfloat16*)D3l,
        D3b, out, nullptr, nullptr, BQ, 1024, 512);
}

// round 10
// speedup vs baseline: 1.2105x; 1.0002x over previous
#include <cuda_runtime.h>
#include <cuda_bf16.h>
#include <math.h>

// Problem constants (fixed by setup_inputs)
#define BQ    1024
#define DIM   1024
#define CDIM  128
#define NKEYS 100000
#define KNN   5
#define EPSW  1e-6f
#define NB    2048
#define NSL   8                     // slices per bucket (atomic decontention)
#define NCNT  (NB * NSL)            // 16384 counters
// fixed kn->bucket mapping: covers kn in [64,192]; kn ~ chi2(128) (mean 128, sd 16)
#define KN_LO 64.0f
#define KN_SPAN 128.0f

// ---------------- scratch (device globals; no allocations allowed) ---------
__device__ __align__(16) __nv_bfloat16 g_qh[BQ * DIM],   g_ql[BQ * DIM];
__device__ __align__(16) __nv_bfloat16 g_W1h[DIM * 512], g_W1l[DIM * 512];
__device__ __align__(16) __nv_bfloat16 g_W2h[512 * 256], g_W2l[512 * 256];
__device__ __align__(16) __nv_bfloat16 g_W3h[256 * 128], g_W3l[256 * 128];
__device__ __align__(16) __nv_bfloat16 g_D1h[128 * 256], g_D1l[128 * 256];
__device__ __align__(16) __nv_bfloat16 g_D2h[256 * 512], g_D2l[256 * 512];
__device__ __align__(16) __nv_bfloat16 g_D3h[512 * 1024], g_D3l[512 * 1024];
__device__ __align__(16) __nv_bfloat16 g_h1h[BQ * 512], g_h1l[BQ * 512];
__device__ __align__(16) __nv_bfloat16 g_h2h[BQ * 256], g_h2l[BQ * 256];
__device__ __align__(16) __nv_bfloat16 g_wh[BQ * CDIM], g_wl[BQ * CDIM];
__device__ __align__(16) __nv_bfloat16 g_g1h[BQ * 256], g_g1l[BQ * 256];
__device__ __align__(16) __nv_bfloat16 g_g2h[BQ * 512], g_g2l[BQ * 512];

__device__ float g_cq[BQ * CDIM];
__device__ float g_qn[BQ];
__device__ float g_kn[NKEYS];
__device__ int   g_hist[NCNT];
__device__ int   g_cursor[NCNT];
__device__ int   g_scand[NKEYS];
__device__ float g_skn[NKEYS];
__device__ float g_sblo[NKEYS];

// ---------------- fixed bucket mapping --------------------------------------
__device__ __forceinline__ int kn_bucket(float kn) {
    int b = (int)((kn - KN_LO) * ((float)NB / KN_SPAN));
    return min(NB - 1, max(0, b));
}
__device__ __forceinline__ float kn_floor(int b) {
    // valid lower bound on kn for every key in buckets >= b
    return (b == 0) ? 0.f : (KN_LO + (float)b * (KN_SPAN / (float)NB));
}

// ---------------- batched fp32 -> bf16 hi/lo split (+ hist zero) -----------
struct SplitSeg { const float* src; __nv_bfloat16* h; __nv_bfloat16* l; };
struct SplitArgs { SplitSeg s[7]; int cum[8]; };

__global__ void split_batch_kernel(SplitArgs a) {
    int i = blockIdx.x * blockDim.x + threadIdx.x;   // float4 units
    if (i < NCNT) g_hist[i] = 0;                     // fused counter init
    if (i >= a.cum[7]) return;
    int sg = 0;
    while (i >= a.cum[sg + 1]) sg++;
    int j = i - a.cum[sg];
    float4 v = reinterpret_cast<const float4*>(a.s[sg].src)[j];
    float x[4] = {v.x, v.y, v.z, v.w};
    unsigned short h[4], l[4];
#pragma unroll
    for (int q = 0; q < 4; q++) {
        __nv_bfloat16 hb = __float2bfloat16(x[q]);
        __nv_bfloat16 lb = __float2bfloat16(x[q] - __bfloat162float(hb));
        h[q] = __bfloat16_as_ushort(hb);
        l[q] = __bfloat16_as_ushort(lb);
    }
    uint2 hp = {(unsigned)h[0] | ((unsigned)h[1] << 16),
                (unsigned)h[2] | ((unsigned)h[3] << 16)};
    uint2 lp = {(unsigned)l[0] | ((unsigned)l[1] << 16),
                (unsigned)l[2] | ((unsigned)l[3] << 16)};
    reinterpret_cast<uint2*>(a.s[sg].h)[j] = hp;
    reinterpret_cast<uint2*>(a.s[sg].l)[j] = lp;
}

// ============================================================================
// bf16 hi/lo tensor-core GEMM. Tile 64x64, BK=32, 256 threads / 8 warps;
// warp tile 16x32 (1x m16 x 4x n8). AhBh + AhBl + AlBh, fp32 accumulate.
// cp.async double buffered.  (unchanged from round 9)
// ============================================================================
#define GBM 64
#define GBN 64
#define GBK 32
#define ASTR 40
#define BSTR 72

__device__ __forceinline__ void mma_bf16(float c[4], const unsigned a[4],
                                         const unsigned b[2]) {
    asm volatile(
        "mma.sync.aligned.m16n8k16.row.col.f32.bf16.bf16.f32 "
        "{%0,%1,%2,%3}, {%4,%5,%6,%7}, {%8,%9}, {%0,%1,%2,%3};"
        : "+f"(c[0]), "+f"(c[1]), "+f"(c[2]), "+f"(c[3])
        : "r"(a[0]), "r"(a[1]), "r"(a[2]), "r"(a[3]), "r"(b[0]), "r"(b[1]));
}
__device__ __forceinline__ void ldmA(unsigned a[4], unsigned addr) {
    asm volatile("ldmatrix.sync.aligned.m8n8.x4.shared.b16 {%0,%1,%2,%3}, [%4];"
                 : "=r"(a[0]), "=r"(a[1]), "=r"(a[2]), "=r"(a[3]) : "r"(addr));
}
__device__ __forceinline__ void ldmB(unsigned b[2], unsigned addr) {
    asm volatile("ldmatrix.sync.aligned.m8n8.x2.trans.shared.b16 {%0,%1}, [%2];"
                 : "=r"(b[0]), "=r"(b[1]) : "r"(addr));
}
__device__ __forceinline__ void cpa16(unsigned dst, const void* src) {
    asm volatile("cp.async.cg.shared.global [%0], [%1], 16;"
                 :: "r"(dst), "l"(src));
}

template <int RELU, int WF32, int WBF>
__global__ __launch_bounds__(256)
void bgemm(const __nv_bfloat16* __restrict__ Ah, const __nv_bfloat16* __restrict__ Al,
           const __nv_bfloat16* __restrict__ Bh, const __nv_bfloat16* __restrict__ Bl,
           const float* __restrict__ bias,
           float* __restrict__ Cf,
           __nv_bfloat16* __restrict__ Ch, __nv_bfloat16* __restrict__ Cl,
           int M, int N, int K) {
    __shared__ __align__(16) __nv_bfloat16 sA[2 * 2 * GBM * ASTR];
    __shared__ __align__(16) __nv_bfloat16 sB[2 * 2 * GBK * BSTR];

    const int tid  = threadIdx.x;
    const int lane = tid & 31;
    const int wid  = tid >> 5;
    const int wm   = wid & 3;       // 4 warps along M (16 rows each)
    const int wn   = wid >> 2;      // 2 warps along N (32 cols each)
    const int bm   = blockIdx.y * GBM;
    const int bn   = blockIdx.x * GBN;

    const unsigned saddrA = (unsigned)__cvta_generic_to_shared(sA);
    const unsigned saddrB = (unsigned)__cvta_generic_to_shared(sB);
    const unsigned aBufB  = GBM * ASTR * 2;
    const unsigned bBufB  = GBK * BSTR * 2;

    const int ar  = tid >> 2;           // A row 0..63
    const int ac0 = (tid & 3) << 3;     // A col 0,8,16,24
    const int br  = tid >> 3;           // B row 0..31
    const int bc  = (tid & 7) << 3;     // B col 0..56

    const int a_r  = (lane & 7) + ((lane >> 3) & 1) * 8;
    const int a_k8 = (lane >> 4) * 8;
    const int b_r  = lane & 15;

    float acc[4][4];
#pragma unroll
    for (int nt = 0; nt < 4; nt++)
#pragma unroll
        for (int i = 0; i < 4; i++) acc[nt][i] = 0.f;

    const int ntk = K >> 5;

    auto stage = [&](int t, int buf) {
        const int k0 = t * GBK;
        size_t ga = (size_t)(bm + ar) * K + k0 + ac0;
        unsigned da = saddrA + (unsigned)(buf * 2) * aBufB + (ar * ASTR + ac0) * 2;
        cpa16(da,         Ah + ga);
        cpa16(da + aBufB, Al + ga);
        size_t gb = (size_t)(k0 + br) * N + bn + bc;
        unsigned db = saddrB + (unsigned)(buf * 2) * bBufB + (br * BSTR + bc) * 2;
        cpa16(db,         Bh + gb);
        cpa16(db + bBufB, Bl + gb);
        asm volatile("cp.async.commit_group;");
    };

    stage(0, 0);

    for (int t = 0; t < ntk; t++) {
        asm volatile("cp.async.wait_group 0;");
        __syncthreads();
        if (t + 1 < ntk) stage(t + 1, (t + 1) & 1);

        const int buf = t & 1;
        const unsigned base_ah = saddrA + (unsigned)(buf * 2) * aBufB;
        const unsigned base_al = base_ah + aBufB;
        const unsigned base_bh = saddrB + (unsigned)(buf * 2) * bBufB;
        const unsigned base_bl = base_bh + bBufB;

#pragma unroll
        for (int kk = 0; kk < GBK; kk += 16) {
            unsigned ah[4], al_[4];
            unsigned ro = ((wm * 16 + a_r) * ASTR + kk + a_k8) * 2;
            ldmA(ah,  base_ah + ro);
            ldmA(al_, base_al + ro);
#pragma unroll
            for (int nt = 0; nt < 4; nt++) {
                unsigned bh[2], bl_[2];
                unsigned bo = ((kk + b_r) * BSTR + wn * 32 + nt * 8) * 2;
                ldmB(bh,  base_bh + bo);
                ldmB(bl_, base_bl + bo);
                mma_bf16(acc[nt], ah,  bh);
                mma_bf16(acc[nt], ah,  bl_);
                mma_bf16(acc[nt], al_, bh);
            }
        }
        __syncthreads();
    }

    // epilogue
    const int g  = lane >> 2;
    const int tq = lane & 3;
#pragma unroll
    for (int nt = 0; nt < 4; nt++) {
        int row = bm + wm * 16 + g;
        int col = bn + wn * 32 + nt * 8 + tq * 2;
        float bz0 = bias[col], bz1 = bias[col + 1];
        float v0 = acc[nt][0] + bz0;
        float v1 = acc[nt][1] + bz1;
        float v2 = acc[nt][2] + bz0;
        float v3 = acc[nt][3] + bz1;
        if (RELU) {
            v0 = fmaxf(v0, 0.f); v1 = fmaxf(v1, 0.f);
            v2 = fmaxf(v2, 0.f); v3 = fmaxf(v3, 0.f);
        }
        if (WF32) {
            float2 o0 = {v0, v1}, o1 = {v2, v3};
            *reinterpret_cast<float2*>(&Cf[(size_t)row * N + col]) = o0;
            *reinterpret_cast<float2*>(&Cf[(size_t)(row + 8) * N + col]) = o1;
        }
        if (WBF) {
            __nv_bfloat16 h0 = __float2bfloat16(v0);
            __nv_bfloat16 h1 = __float2bfloat16(v1);
            __nv_bfloat16 h2 = __float2bfloat16(v2);
            __nv_bfloat16 h3 = __float2bfloat16(v3);
            unsigned hp0 = (unsigned)__bfloat16_as_ushort(h0) |
                           ((unsigned)__bfloat16_as_ushort(h1) << 16);
            unsigned hp1 = (unsigned)__bfloat16_as_ushort(h2) |
                           ((unsigned)__bfloat16_as_ushort(h3) << 16);
            unsigned lp0 = (unsigned)__bfloat16_as_ushort(
                               __float2bfloat16(v0 - __bfloat162float(h0))) |
                           ((unsigned)__bfloat16_as_ushort(
                               __float2bfloat16(v1 - __bfloat162float(h1))) << 16);
            unsigned lp1 = (unsigned)__bfloat16_as_ushort(
                               __float2bfloat16(v2 - __bfloat162float(h2))) |
                           ((unsigned)__bfloat16_as_ushort(
                               __float2bfloat16(v3 - __bfloat162float(h3))) << 16);
            *reinterpret_cast<unsigned*>(&Ch[(size_t)row * N + col]) = hp0;
            *reinterpret_cast<unsigned*>(&Ch[(size_t)(row + 8) * N + col]) = hp1;
            *reinterpret_cast<unsigned*>(&Cl[(size_t)row * N + col]) = lp0;
            *reinterpret_cast<unsigned*>(&Cl[(size_t)(row + 8) * N + col]) = lp1;
        }
    }
}

// ---------------- row squared-norms (rows of width 128), fused histogram ---
template <int DO_HIST>
__global__ void rownorm_kernel(const float* __restrict__ X,
                               float* __restrict__ out, int rows) {
    int gw = (int)((blockIdx.x * (size_t)blockDim.x + threadIdx.x) >> 5);
    int lane = threadIdx.x & 31;
    if (gw >= rows) return;
    float4 v = reinterpret_cast<const float4*>(X + (size_t)gw * 128)[lane];
    float s = v.x * v.x + v.y * v.y + v.z * v.z + v.w * v.w;
#pragma unroll
    for (int o = 16; o; o >>= 1) s += __shfl_xor_sync(0xffffffffu, s, o);
    if (lane == 0) {
        out[gw] = s;
        if (DO_HIST) atomicAdd(&g_hist[kn_bucket(s) * NSL + (gw & (NSL - 1))], 1);
    }
}

// ---------------- exclusive scan over NCNT counters (1024 thr, 16/thr) -----
__global__ void scan_kernel() {
    __shared__ int wsum[32];
    const int t = threadIdx.x;
    const int lane = t & 31, w = t >> 5;
    const int base = t * 16;
    int loc[16];
    int s = 0;
#pragma unroll
    for (int i = 0; i < 16; i++) { loc[i] = g_hist[base + i]; s += loc[i]; }
    int x = s;
#pragma unroll
    for (int o = 1; o < 32; o <<= 1) {
        int y = __shfl_up_sync(0xffffffffu, x, o);
        if (lane >= o) x += y;
    }
    if (lane == 31) wsum[w] = x;
    __syncthreads();
    if (w == 0) {
        int v = wsum[lane];
#pragma unroll
        for (int o = 1; o < 32; o <<= 1) {
            int y = __shfl_up_sync(0xffffffffu, v, o);
            if (lane >= o) v += y;
        }
        wsum[lane] = v;
    }
    __syncthreads();
    int excl = x - s + (w > 0 ? wsum[w - 1] : 0);
#pragma unroll
    for (int i = 0; i < 16; i++) { g_cursor[base + i] = excl; excl += loc[i]; }
}

__global__ void scatter_kernel() {
    int n = blockIdx.x * blockDim.x + threadIdx.x;
    if (n >= NKEYS) return;
    float kn = g_kn[n];
    int b = kn_bucket(kn);
    int pos = atomicAdd(&g_cursor[b * NSL + (n & (NSL - 1))], 1);
    g_scand[pos] = n;
    g_skn[pos]   = kn;
    g_sblo[pos]  = kn_floor(b);
}

// ---------------- exact rescore + top-5 + weighted gather ------------------
// Keys bucket-sorted ascending by kn. Per 128-key chunk: each warp computes
// its exact top-5 via argmin-lex shuffles (no block barriers), tid0 merges
// 4x5 entries into the running top-5 and evaluates the provably-safe exit:
//   d2(n) >= qn + kn - 2*qb*sqrt(kn) >= qn + f(blo)   (f increasing, blo>>qb^2)
__global__ __launch_bounds__(128, 8)
void rescore_kernel(const float* __restrict__ keys,
                    const float* __restrict__ values,
                    float* __restrict__ conf_out) {
    const int b = blockIdx.x;
    const int tid = threadIdx.x;
    const int lane = tid & 31;
    const int wid = tid >> 5;
    __shared__ float sq[CDIM];
    __shared__ float rd[KNN];
    __shared__ int   ri[KNN];
    __shared__ float wv[4][KNN];
    __shared__ int   wi[4][KNN];
    __shared__ float sw[KNN];
    __shared__ int   s_stop;

    sq[tid] = g_cq[(size_t)b * CDIM + tid];
    if (tid < KNN) { rd[tid] = 3.4e38f; ri[tid] = 0x7fffffff; }
    if (tid == 0) s_stop = 0;
    const float qn = g_qn[b];
    const float qb = sqrtf(qn);
    __syncthreads();

    for (int c0 = 0; c0 < NKEYS; c0 += 128) {
        int j = c0 + tid;
        float d = 3.4e38f;
        int   nidx = 0x7fffffff;
        if (j < NKEYS) {
            int n = g_scand[j];
            const float4* kr = reinterpret_cast<const float4*>(keys + (size_t)n * CDIM);
            const float4* sq4 = reinterpret_cast<const float4*>(sq);
            float a0 = 0.f, a1 = 0.f, a2 = 0.f, a3 = 0.f;
#pragma unroll
            for (int dd = 0; dd < CDIM / 4; dd++) {
                float4 kv = __ldg(&kr[dd]);
                float4 qv = sq4[dd];
                a0 = fmaf(qv.x, kv.x, a0);
                a1 = fmaf(qv.y, kv.y, a1);
                a2 = fmaf(qv.z, kv.z, a2);
                a3 = fmaf(qv.w, kv.w, a3);
            }
            float dot = (a0 + a1) + (a2 + a3);
            d = qn + g_skn[j] - 2.f * dot;
            nidx = n;
        }

        // warp top-5 via 5 argmin-lex rounds (shuffles only)
#pragma unroll
        for (int r = 0; r < KNN; r++) {
            float v = d; int ix = nidx;
#pragma unroll
            for (int o = 16; o; o >>= 1) {
                float v2 = __shfl_xor_sync(0xffffffffu, v, o);
                int   i2 = __shfl_xor_sync(0xffffffffu, ix, o);
                if (v2 < v || (v2 == v && i2 < ix)) { v = v2; ix = i2; }
            }
            if (lane == 0) { wv[wid][r] = v; wi[wid][r] = ix; }
            if (d == v && nidx == ix) { d = 3.4e38f; nidx = 0x7fffffff; }
        }
        __syncthreads();

        if (tid == 0) {
            // merge 4 warps x 5 entries into running top-5
#pragma unroll
            for (int w = 0; w < 4; w++) {
#pragma unroll
                for (int r = 0; r < KNN; r++) {
                    float v = wv[w][r]; int n = wi[w][r];
                    if (v < rd[KNN - 1] || (v == rd[KNN - 1] && n < ri[KNN - 1])) {
                        int p = KNN - 1;
                        while (p > 0 && (rd[p - 1] > v ||
                                         (rd[p - 1] == v && ri[p - 1] > n))) {
                            rd[p] = rd[p - 1]; ri[p] = ri[p - 1]; p--;
                        }
                        rd[p] = v; ri[p] = n;
                    }
                }
            }
            // exit check for next chunk
            if (c0 + 128 < NKEYS) {
                float blo = g_sblo[c0 + 128];
                float lb = qn + blo - 2.f * qb * sqrtf(blo) - 1e-3f;
                if (lb > rd[KNN - 1]) s_stop = 1;
            }
        }
        __syncthreads();
        if (s_stop) break;
    }

    if (tid == 0) {
        float w[KNN], ws = 0.f;
#pragma unroll
        for (int j2 = 0; j2 < KNN; j2++) { w[j2] = 1.f / (rd[j2] + EPSW); ws += w[j2]; }
#pragma unroll
        for (int j2 = 0; j2 < KNN; j2++) sw[j2] = w[j2] / ws;
        conf_out[b] = 1.f / (rd[0] + EPSW);
    }
    __syncthreads();

    float acc = 0.f;
#pragma unroll
    for (int j2 = 0; j2 < KNN; j2++)
        acc += sw[j2] * values[(size_t)ri[j2] * CDIM + tid];
    __nv_bfloat16 hb = __float2bfloat16(acc);
    g_wh[(size_t)b * CDIM + tid] = hb;
    g_wl[(size_t)b * CDIM + tid] = __float2bfloat16(acc - __bfloat162float(hb));
}

// ---------------- launch ----------------------------------------------------
extern "C" void kernel_launch(void* const* d_in, const int* in_sizes, int n_in,
                              void* d_out, int out_size) {
    const float* query = (const float*)d_in[0];
    const float* W1    = (const float*)d_in[1];
    const float* b1    = (const float*)d_in[2];
    const float* W2    = (const float*)d_in[3];
    const float* b2    = (const float*)d_in[4];
    const float* W3    = (const float*)d_in[5];
    const float* b3    = (const float*)d_in[6];
    const float* keys  = (const float*)d_in[7];
    const float* values= (const float*)d_in[8];
    const float* D1w   = (const float*)d_in[9];
    const float* D1b   = (const float*)d_in[10];
    const float* D2w   = (const float*)d_in[11];
    const float* D2b   = (const float*)d_in[12];
    const float* D3w   = (const float*)d_in[13];
    const float* D3b   = (const float*)d_in[14];

    float* out  = (float*)d_out;
    float* conf = out + (size_t)BQ * DIM;

    void *qh, *ql, *W1h, *W1l, *W2h, *W2l, *W3h, *W3l;
    void *D1h, *D1l, *D2h, *D2l, *D3h, *D3l;
    void *h1h, *h1l, *h2h, *h2l, *wh, *wl, *g1h, *g1l, *g2h, *g2l;
    void *cq, *qn, *kn;
    cudaGetSymbolAddress(&qh, g_qh);   cudaGetSymbolAddress(&ql, g_ql);
    cudaGetSymbolAddress(&W1h, g_W1h); cudaGetSymbolAddress(&W1l, g_W1l);
    cudaGetSymbolAddress(&W2h, g_W2h); cudaGetSymbolAddress(&W2l, g_W2l);
    cudaGetSymbolAddress(&W3h, g_W3h); cudaGetSymbolAddress(&W3l, g_W3l);
    cudaGetSymbolAddress(&D1h, g_D1h); cudaGetSymbolAddress(&D1l, g_D1l);
    cudaGetSymbolAddress(&D2h, g_D2h); cudaGetSymbolAddress(&D2l, g_D2l);
    cudaGetSymbolAddress(&D3h, g_D3h); cudaGetSymbolAddress(&D3l, g_D3l);
    cudaGetSymbolAddress(&h1h, g_h1h); cudaGetSymbolAddress(&h1l, g_h1l);
    cudaGetSymbolAddress(&h2h, g_h2h); cudaGetSymbolAddress(&h2l, g_h2l);
    cudaGetSymbolAddress(&wh, g_wh);   cudaGetSymbolAddress(&wl, g_wl);
    cudaGetSymbolAddress(&g1h, g_g1h); cudaGetSymbolAddress(&g1l, g_g1l);
    cudaGetSymbolAddress(&g2h, g_g2h); cudaGetSymbolAddress(&g2l, g_g2l);
    cudaGetSymbolAddress(&cq, g_cq);
    cudaGetSymbolAddress(&qn, g_qn);
    cudaGetSymbolAddress(&kn, g_kn);

    // batched split: query + 6 weight matrices (+ fused counter zeroing)
    SplitArgs sa;
    int sizes4[7] = {BQ * DIM / 4, DIM * 512 / 4, 512 * 256 / 4, 256 * 128 / 4,
                     128 * 256 / 4, 256 * 512 / 4, 512 * 1024 / 4};
    const float* srcs[7] = {query, W1, W2, W3, D1w, D2w, D3w};
    void* hs[7] = {qh, W1h, W2h, W3h, D1h, D2h, D3h};
    void* ls[7] = {ql, W1l, W2l, W3l, D1l, D2l, D3l};
    sa.cum[0] = 0;
    for (int i = 0; i < 7; i++) {
        sa.s[i].src = srcs[i];
        sa.s[i].h = (__nv_bfloat16*)hs[i];
        sa.s[i].l = (__nv_bfloat16*)ls[i];
        sa.cum[i + 1] = sa.cum[i] + sizes4[i];
    }
    split_batch_kernel<<<(sa.cum[7] + 255) / 256, 256>>>(sa);

    // key norms + fused sliced histogram -> scan -> scatter (bucket-sort keys)
    rownorm_kernel<1><<<(NKEYS * 32 + 255) / 256, 256>>>(keys, (float*)kn, NKEYS);
    scan_kernel<<<1, 1024>>>();
    scatter_kernel<<<(NKEYS + 255) / 256, 256>>>();

    // Encode MLP
    bgemm<1, 0, 1><<<dim3(512 / GBN, BQ / GBM), 256>>>(
        (__nv_bfloat16*)qh, (__nv_bfloat16*)ql, (__nv_bfloat16*)W1h, (__nv_bfloat16*)W1l,
        b1, nullptr, (__nv_bfloat16*)h1h, (__nv_bfloat16*)h1l, BQ, 512, 1024);
    bgemm<1, 0, 1><<<dim3(256 / GBN, BQ / GBM), 256>>>(
        (__nv_bfloat16*)h1h, (__nv_bfloat16*)h1l, (__nv_bfloat16*)W2h, (__nv_bfloat16*)W2l,
        b2, nullptr, (__nv_bfloat16*)h2h, (__nv_bfloat16*)h2l, BQ, 256, 512);
    bgemm<0, 1, 0><<<dim3(128 / GBN, BQ / GBM), 256>>>(
        (__nv_bfloat16*)h2h, (__nv_bfloat16*)h2l, (__nv_bfloat16*)W3h, (__nv_bfloat16*)W3l,
        b3, (float*)cq, nullptr, nullptr, BQ, 128, 256);

    // query norms (no histogram)
    rownorm_kernel<0><<<(BQ * 32 + 255) / 256, 256>>>((float*)cq, (float*)qn, BQ);

    // exact rescore + top-5 + gather (emits weighted as bf16 hi/lo)
    rescore_kernel<<<BQ, 128>>>(keys, values, conf);

    // Decode MLP
    bgemm<1, 0, 1><<<dim3(256 / GBN, BQ / GBM), 256>>>(
        (__nv_bfloat16*)wh, (__nv_bfloat16*)wl, (__nv_bfloat16*)D1h, (__nv_bfloat16*)D1l,
        D1b, nullptr, (__nv_bfloat16*)g1h, (__nv_bfloat16*)g1l, BQ, 256, 128);
    bgemm<1, 0, 1><<<dim3(512 / GBN, BQ / GBM), 256>>>(
        (__nv_bfloat16*)g1h, (__nv_bfloat16*)g1l, (__nv_bfloat16*)D2h, (__nv_bfloat16*)D2l,
        D2b, nullptr, (__nv_bfloat16*)g2h, (__nv_bfloat16*)g2l, BQ, 512, 256);
    bgemm<0, 1, 0><<<dim3(1024 / GBN, BQ / GBM), 256>>>(
        (__nv_bfloat16*)g2h, (__nv_bfloat16*)g2l, (__nv_bfloat16*)D3h, (__nv_bfloat16*)D3l,
        D3b, out, nullptr, nullptr, BQ, 1024, 512);
}

// round 12
// speedup vs baseline: 1.2269x; 1.0135x over previous
#include <cuda_runtime.h>
#include <cuda_bf16.h>
#include <math.h>

// Problem constants (fixed by setup_inputs)
#define BQ    1024
#define DIM   1024
#define CDIM  128
#define NKEYS 100000
#define KNN   5
#define EPSW  1e-6f
#define NB    2048
#define NSL   8
#define NCNT  (NB * NSL)
#define KN_LO 64.0f
#define KN_SPAN 128.0f

// ---------------- scratch (device globals; no allocations allowed) ---------
__device__ __align__(16) __nv_bfloat16 g_qh[BQ * DIM],   g_ql[BQ * DIM];
__device__ __align__(16) __nv_bfloat16 g_W1h[DIM * 512], g_W1l[DIM * 512];
__device__ __align__(16) __nv_bfloat16 g_W2h[512 * 256], g_W2l[512 * 256];
__device__ __align__(16) __nv_bfloat16 g_W3h[256 * 128], g_W3l[256 * 128];
__device__ __align__(16) __nv_bfloat16 g_D1h[128 * 256], g_D1l[128 * 256];
__device__ __align__(16) __nv_bfloat16 g_D2h[256 * 512], g_D2l[256 * 512];
__device__ __align__(16) __nv_bfloat16 g_D3h[512 * 1024], g_D3l[512 * 1024];
__device__ __align__(16) __nv_bfloat16 g_h1h[BQ * 512], g_h1l[BQ * 512];
__device__ __align__(16) __nv_bfloat16 g_h2h[BQ * 256], g_h2l[BQ * 256];
__device__ __align__(16) __nv_bfloat16 g_wh[BQ * CDIM], g_wl[BQ * CDIM];
__device__ __align__(16) __nv_bfloat16 g_g1h[BQ * 256], g_g1l[BQ * 256];
__device__ __align__(16) __nv_bfloat16 g_g2h[BQ * 512], g_g2l[BQ * 512];

__device__ float g_cq[BQ * CDIM];
__device__ float g_qn[BQ];
__device__ float g_kn[NKEYS];
__device__ int   g_hist[NCNT];
__device__ int   g_cursor[NCNT];
__device__ int   g_scand[NKEYS];
__device__ float g_skn[NKEYS];
__device__ float g_sblo[NKEYS];

// ---------------- fixed bucket mapping --------------------------------------
__device__ __forceinline__ int kn_bucket(float kn) {
    int b = (int)((kn - KN_LO) * ((float)NB / KN_SPAN));
    return min(NB - 1, max(0, b));
}
__device__ __forceinline__ float kn_floor(int b) {
    return (b == 0) ? 0.f : (KN_LO + (float)b * (KN_SPAN / (float)NB));
}

// ---------------- batched fp32 -> bf16 hi/lo split (+ counter zero) ---------
struct SplitSeg { const float* src; __nv_bfloat16* h; __nv_bfloat16* l; };
struct SplitArgs { SplitSeg s[7]; int cum[8]; };

__global__ void split_batch_kernel(SplitArgs a) {
    int i = blockIdx.x * blockDim.x + threadIdx.x;   // float4 units
    if (i < NCNT) g_hist[i] = 0;                     // fused counter init
    if (i >= a.cum[7]) return;
    int sg = 0;
    while (i >= a.cum[sg + 1]) sg++;
    int j = i - a.cum[sg];
    float4 v = reinterpret_cast<const float4*>(a.s[sg].src)[j];
    float x[4] = {v.x, v.y, v.z, v.w};
    unsigned short h[4], l[4];
#pragma unroll
    for (int q = 0; q < 4; q++) {
        __nv_bfloat16 hb = __float2bfloat16(x[q]);
        __nv_bfloat16 lb = __float2bfloat16(x[q] - __bfloat162float(hb));
        h[q] = __bfloat16_as_ushort(hb);
        l[q] = __bfloat16_as_ushort(lb);
    }
    uint2 hp = {(unsigned)h[0] | ((unsigned)h[1] << 16),
                (unsigned)h[2] | ((unsigned)h[3] << 16)};
    uint2 lp = {(unsigned)l[0] | ((unsigned)l[1] << 16),
                (unsigned)l[2] | ((unsigned)l[3] << 16)};
    reinterpret_cast<uint2*>(a.s[sg].h)[j] = hp;
    reinterpret_cast<uint2*>(a.s[sg].l)[j] = lp;
}

// ============================================================================
// bf16 hi/lo tensor-core GEMM (mma.sync). Tile 64x64, BK=32, 256 thr / 8 warps.
// Warp tile 32x16 (2x m16 x 2x n8): per-k16 = 4 LDSM(A) + 4 LDSM(B) + 12 MMA
// (balanced; previous layout had 20 LDSM per 12 MMA).
// AhBh + AhBl + AlBh, fp32 accumulate. cp.async double buffered.
// ============================================================================
#define GBM 64
#define GBN 64
#define GBK 32
#define ASTR 40
#define BSTR 72

__device__ __forceinline__ void mma_bf16(float c[4], const unsigned a[4],
                                         const unsigned b[2]) {
    asm volatile(
        "mma.sync.aligned.m16n8k16.row.col.f32.bf16.bf16.f32 "
        "{%0,%1,%2,%3}, {%4,%5,%6,%7}, {%8,%9}, {%0,%1,%2,%3};"
        : "+f"(c[0]), "+f"(c[1]), "+f"(c[2]), "+f"(c[3])
        : "r"(a[0]), "r"(a[1]), "r"(a[2]), "r"(a[3]), "r"(b[0]), "r"(b[1]));
}
__device__ __forceinline__ void ldmA(unsigned a[4], unsigned addr) {
    asm volatile("ldmatrix.sync.aligned.m8n8.x4.shared.b16 {%0,%1,%2,%3}, [%4];"
                 : "=r"(a[0]), "=r"(a[1]), "=r"(a[2]), "=r"(a[3]) : "r"(addr));
}
__device__ __forceinline__ void ldmB(unsigned b[2], unsigned addr) {
    asm volatile("ldmatrix.sync.aligned.m8n8.x2.trans.shared.b16 {%0,%1}, [%2];"
                 : "=r"(b[0]), "=r"(b[1]) : "r"(addr));
}
__device__ __forceinline__ void cpa16(unsigned dst, const void* src) {
    asm volatile("cp.async.cg.shared.global [%0], [%1], 16;"
                 :: "r"(dst), "l"(src));
}

template <int RELU, int WF32, int WBF>
__global__ __launch_bounds__(256)
void bgemm(const __nv_bfloat16* __restrict__ Ah, const __nv_bfloat16* __restrict__ Al,
           const __nv_bfloat16* __restrict__ Bh, const __nv_bfloat16* __restrict__ Bl,
           const float* __restrict__ bias,
           float* __restrict__ Cf,
           __nv_bfloat16* __restrict__ Ch, __nv_bfloat16* __restrict__ Cl,
           int M, int N, int K) {
    __shared__ __align__(16) __nv_bfloat16 sA[2 * 2 * GBM * ASTR];
    __shared__ __align__(16) __nv_bfloat16 sB[2 * 2 * GBK * BSTR];

    const int tid  = threadIdx.x;
    const int lane = tid & 31;
    const int wid  = tid >> 5;
    const int wm   = wid & 1;       // 2 warps along M (32 rows each)
    const int wn   = wid >> 1;      // 4 warps along N (16 cols each)
    const int bm   = blockIdx.y * GBM;
    const int bn   = blockIdx.x * GBN;

    const unsigned saddrA = (unsigned)__cvta_generic_to_shared(sA);
    const unsigned saddrB = (unsigned)__cvta_generic_to_shared(sB);
    const unsigned aBufB  = GBM * ASTR * 2;
    const unsigned bBufB  = GBK * BSTR * 2;

    const int ar  = tid >> 2;           // A row 0..63
    const int ac0 = (tid & 3) << 3;     // A col 0,8,16,24
    const int br  = tid >> 3;           // B row 0..31
    const int bc  = (tid & 7) << 3;     // B col 0..56

    const int a_r  = (lane & 7) + ((lane >> 3) & 1) * 8;
    const int a_k8 = (lane >> 4) * 8;
    const int b_r  = lane & 15;

    float acc[2][2][4];
#pragma unroll
    for (int mt = 0; mt < 2; mt++)
#pragma unroll
        for (int nt = 0; nt < 2; nt++)
#pragma unroll
            for (int i = 0; i < 4; i++) acc[mt][nt][i] = 0.f;

    const int ntk = K >> 5;

    auto stage = [&](int t, int buf) {
        const int k0 = t * GBK;
        size_t ga = (size_t)(bm + ar) * K + k0 + ac0;
        unsigned da = saddrA + (unsigned)(buf * 2) * aBufB + (ar * ASTR + ac0) * 2;
        cpa16(da,         Ah + ga);
        cpa16(da + aBufB, Al + ga);
        size_t gb = (size_t)(k0 + br) * N + bn + bc;
        unsigned db = saddrB + (unsigned)(buf * 2) * bBufB + (br * BSTR + bc) * 2;
        cpa16(db,         Bh + gb);
        cpa16(db + bBufB, Bl + gb);
        asm volatile("cp.async.commit_group;");
    };

    stage(0, 0);

    for (int t = 0; t < ntk; t++) {
        asm volatile("cp.async.wait_group 0;");
        __syncthreads();
        if (t + 1 < ntk) stage(t + 1, (t + 1) & 1);

        const int buf = t & 1;
        const unsigned base_ah = saddrA + (unsigned)(buf * 2) * aBufB;
        const unsigned base_al = base_ah + aBufB;
        const unsigned base_bh = saddrB + (unsigned)(buf * 2) * bBufB;
        const unsigned base_bl = base_bh + bBufB;

#pragma unroll
        for (int kk = 0; kk < GBK; kk += 16) {
            unsigned ah[2][4], al_[2][4];
#pragma unroll
            for (int mt = 0; mt < 2; mt++) {
                unsigned ro = ((wm * 32 + mt * 16 + a_r) * ASTR + kk + a_k8) * 2;
                ldmA(ah[mt],  base_ah + ro);
                ldmA(al_[mt], base_al + ro);
            }
#pragma unroll
            for (int nt = 0; nt < 2; nt++) {
                unsigned bh[2], bl_[2];
                unsigned bo = ((kk + b_r) * BSTR + wn * 16 + nt * 8) * 2;
                ldmB(bh,  base_bh + bo);
                ldmB(bl_, base_bl + bo);
#pragma unroll
                for (int mt = 0; mt < 2; mt++) {
                    mma_bf16(acc[mt][nt], ah[mt],  bh);
                    mma_bf16(acc[mt][nt], ah[mt],  bl_);
                    mma_bf16(acc[mt][nt], al_[mt], bh);
                }
            }
        }
        __syncthreads();
    }

    // epilogue
    const int g  = lane >> 2;
    const int tq = lane & 3;
#pragma unroll
    for (int mt = 0; mt < 2; mt++) {
#pragma unroll
        for (int nt = 0; nt < 2; nt++) {
            int row = bm + wm * 32 + mt * 16 + g;
            int col = bn + wn * 16 + nt * 8 + tq * 2;
            float bz0 = bias[col], bz1 = bias[col + 1];
            float v0 = acc[mt][nt][0] + bz0;
            float v1 = acc[mt][nt][1] + bz1;
            float v2 = acc[mt][nt][2] + bz0;
            float v3 = acc[mt][nt][3] + bz1;
            if (RELU) {
                v0 = fmaxf(v0, 0.f); v1 = fmaxf(v1, 0.f);
                v2 = fmaxf(v2, 0.f); v3 = fmaxf(v3, 0.f);
            }
            if (WF32) {
                float2 o0 = {v0, v1}, o1 = {v2, v3};
                *reinterpret_cast<float2*>(&Cf[(size_t)row * N + col]) = o0;
                *reinterpret_cast<float2*>(&Cf[(size_t)(row + 8) * N + col]) = o1;
            }
            if (WBF) {
                __nv_bfloat16 h0 = __float2bfloat16(v0);
                __nv_bfloat16 h1 = __float2bfloat16(v1);
                __nv_bfloat16 h2 = __float2bfloat16(v2);
                __nv_bfloat16 h3 = __float2bfloat16(v3);
                unsigned hp0 = (unsigned)__bfloat16_as_ushort(h0) |
                               ((unsigned)__bfloat16_as_ushort(h1) << 16);
                unsigned hp1 = (unsigned)__bfloat16_as_ushort(h2) |
                               ((unsigned)__bfloat16_as_ushort(h3) << 16);
                unsigned lp0 = (unsigned)__bfloat16_as_ushort(
                                   __float2bfloat16(v0 - __bfloat162float(h0))) |
                               ((unsigned)__bfloat16_as_ushort(
                                   __float2bfloat16(v1 - __bfloat162float(h1))) << 16);
                unsigned lp1 = (unsigned)__bfloat16_as_ushort(
                                   __float2bfloat16(v2 - __bfloat162float(h2))) |
                               ((unsigned)__bfloat16_as_ushort(
                                   __float2bfloat16(v3 - __bfloat162float(h3))) << 16);
                *reinterpret_cast<unsigned*>(&Ch[(size_t)row * N + col]) = hp0;
                *reinterpret_cast<unsigned*>(&Ch[(size_t)(row + 8) * N + col]) = hp1;
                *reinterpret_cast<unsigned*>(&Cl[(size_t)row * N + col]) = lp0;
                *reinterpret_cast<unsigned*>(&Cl[(size_t)(row + 8) * N + col]) = lp1;
            }
        }
    }
}

// ---------------- row squared-norms (rows of width 128), fused histogram ---
template <int DO_HIST>
__global__ void rownorm_kernel(const float* __restrict__ X,
                               float* __restrict__ out, int rows) {
    int gw = (int)((blockIdx.x * (size_t)blockDim.x + threadIdx.x) >> 5);
    int lane = threadIdx.x & 31;
    if (gw >= rows) return;
    float4 v = reinterpret_cast<const float4*>(X + (size_t)gw * 128)[lane];
    float s = v.x * v.x + v.y * v.y + v.z * v.z + v.w * v.w;
#pragma unroll
    for (int o = 16; o; o >>= 1) s += __shfl_xor_sync(0xffffffffu, s, o);
    if (lane == 0) {
        out[gw] = s;
        if (DO_HIST) atomicAdd(&g_hist[kn_bucket(s) * NSL + (gw & (NSL - 1))], 1);
    }
}

// ---------------- exclusive scan over NCNT counters (1024 thr, 16/thr) -----
__global__ void scan_kernel() {
    __shared__ int wsum[32];
    const int t = threadIdx.x;
    const int lane = t & 31, w = t >> 5;
    const int base = t * 16;
    int loc[16];
    int s = 0;
#pragma unroll
    for (int i = 0; i < 16; i++) { loc[i] = g_hist[base + i]; s += loc[i]; }
    int x = s;
#pragma unroll
    for (int o = 1; o < 32; o <<= 1) {
        int y = __shfl_up_sync(0xffffffffu, x, o);
        if (lane >= o) x += y;
    }
    if (lane == 31) wsum[w] = x;
    __syncthreads();
    if (w == 0) {
        int v = wsum[lane];
#pragma unroll
        for (int o = 1; o < 32; o <<= 1) {
            int y = __shfl_up_sync(0xffffffffu, v, o);
            if (lane >= o) v += y;
        }
        wsum[lane] = v;
    }
    __syncthreads();
    int excl = x - s + (w > 0 ? wsum[w - 1] : 0);
#pragma unroll
    for (int i = 0; i < 16; i++) { g_cursor[base + i] = excl; excl += loc[i]; }
}

__global__ void scatter_kernel() {
    int n = blockIdx.x * blockDim.x + threadIdx.x;
    if (n >= NKEYS) return;
    float kn = g_kn[n];
    int b = kn_bucket(kn);
    int pos = atomicAdd(&g_cursor[b * NSL + (n & (NSL - 1))], 1);
    g_scand[pos] = n;
    g_skn[pos]   = kn;
    g_sblo[pos]  = kn_floor(b);
}

// ---------------- exact rescore + top-5 + weighted gather ------------------
__global__ __launch_bounds__(128, 8)
void rescore_kernel(const float* __restrict__ keys,
                    const float* __restrict__ values,
                    float* __restrict__ conf_out) {
    const int b = blockIdx.x;
    const int tid = threadIdx.x;
    const int lane = tid & 31;
    const int wid = tid >> 5;
    __shared__ float sq[CDIM];
    __shared__ float rd[KNN];
    __shared__ int   ri[KNN];
    __shared__ float wv[4][KNN];
    __shared__ int   wi[4][KNN];
    __shared__ float sw[KNN];
    __shared__ int   s_stop;

    sq[tid] = g_cq[(size_t)b * CDIM + tid];
    if (tid < KNN) { rd[tid] = 3.4e38f; ri[tid] = 0x7fffffff; }
    if (tid == 0) s_stop = 0;
    const float qn = g_qn[b];
    const float qb = sqrtf(qn);
    __syncthreads();

    for (int c0 = 0; c0 < NKEYS; c0 += 128) {
        int j = c0 + tid;
        float d = 3.4e38f;
        int   nidx = 0x7fffffff;
        if (j < NKEYS) {
            int n = g_scand[j];
            const float4* kr = reinterpret_cast<const float4*>(keys + (size_t)n * CDIM);
            const float4* sq4 = reinterpret_cast<const float4*>(sq);
            float a0 = 0.f, a1 = 0.f, a2 = 0.f, a3 = 0.f;
#pragma unroll
            for (int dd = 0; dd < CDIM / 4; dd++) {
                float4 kv = __ldg(&kr[dd]);
                float4 qv = sq4[dd];
                a0 = fmaf(qv.x, kv.x, a0);
                a1 = fmaf(qv.y, kv.y, a1);
                a2 = fmaf(qv.z, kv.z, a2);
                a3 = fmaf(qv.w, kv.w, a3);
            }
            float dot = (a0 + a1) + (a2 + a3);
            d = qn + g_skn[j] - 2.f * dot;
            nidx = n;
        }

#pragma unroll
        for (int r = 0; r < KNN; r++) {
            float v = d; int ix = nidx;
#pragma unroll
            for (int o = 16; o; o >>= 1) {
                float v2 = __shfl_xor_sync(0xffffffffu, v, o);
                int   i2 = __shfl_xor_sync(0xffffffffu, ix, o);
                if (v2 < v || (v2 == v && i2 < ix)) { v = v2; ix = i2; }
            }
            if (lane == 0) { wv[wid][r] = v; wi[wid][r] = ix; }
            if (d == v && nidx == ix) { d = 3.4e38f; nidx = 0x7fffffff; }
        }
        __syncthreads();

        if (tid == 0) {
#pragma unroll
            for (int w = 0; w < 4; w++) {
#pragma unroll
                for (int r = 0; r < KNN; r++) {
                    float v = wv[w][r]; int n = wi[w][r];
                    if (v < rd[KNN - 1] || (v == rd[KNN - 1] && n < ri[KNN - 1])) {
                        int p = KNN - 1;
                        while (p > 0 && (rd[p - 1] > v ||
                                         (rd[p - 1] == v && ri[p - 1] > n))) {
                            rd[p] = rd[p - 1]; ri[p] = ri[p - 1]; p--;
                        }
                        rd[p] = v; ri[p] = n;
                    }
                }
            }
            if (c0 + 128 < NKEYS) {
                float blo = g_sblo[c0 + 128];
                float lb = qn + blo - 2.f * qb * sqrtf(blo) - 1e-3f;
                if (lb > rd[KNN - 1]) s_stop = 1;
            }
        }
        __syncthreads();
        if (s_stop) break;
    }

    if (tid == 0) {
        float w[KNN], ws = 0.f;
#pragma unroll
        for (int j2 = 0; j2 < KNN; j2++) { w[j2] = 1.f / (rd[j2] + EPSW); ws += w[j2]; }
#pragma unroll
        for (int j2 = 0; j2 < KNN; j2++) sw[j2] = w[j2] / ws;
        conf_out[b] = 1.f / (rd[0] + EPSW);
    }
    __syncthreads();

    float acc = 0.f;
#pragma unroll
    for (int j2 = 0; j2 < KNN; j2++)
        acc += sw[j2] * values[(size_t)ri[j2] * CDIM + tid];
    __nv_bfloat16 hb = __float2bfloat16(acc);
    g_wh[(size_t)b * CDIM + tid] = hb;
    g_wl[(size_t)b * CDIM + tid] = __float2bfloat16(acc - __bfloat162float(hb));
}

// ---------------- launch ----------------------------------------------------
extern "C" void kernel_launch(void* const* d_in, const int* in_sizes, int n_in,
                              void* d_out, int out_size) {
    const float* query = (const float*)d_in[0];
    const float* W1    = (const float*)d_in[1];
    const float* b1    = (const float*)d_in[2];
    const float* W2    = (const float*)d_in[3];
    const float* b2    = (const float*)d_in[4];
    const float* W3    = (const float*)d_in[5];
    const float* b3    = (const float*)d_in[6];
    const float* keys  = (const float*)d_in[7];
    const float* values= (const float*)d_in[8];
    const float* D1w   = (const float*)d_in[9];
    const float* D1b   = (const float*)d_in[10];
    const float* D2w   = (const float*)d_in[11];
    const float* D2b   = (const float*)d_in[12];
    const float* D3w   = (const float*)d_in[13];
    const float* D3b   = (const float*)d_in[14];

    float* out  = (float*)d_out;
    float* conf = out + (size_t)BQ * DIM;

    void *qh, *ql, *W1h, *W1l, *W2h, *W2l, *W3h, *W3l;
    void *D1h, *D1l, *D2h, *D2l, *D3h, *D3l;
    void *h1h, *h1l, *h2h, *h2l, *wh, *wl, *g1h, *g1l, *g2h, *g2l;
    void *cq, *qn, *kn;
    cudaGetSymbolAddress(&qh, g_qh);   cudaGetSymbolAddress(&ql, g_ql);
    cudaGetSymbolAddress(&W1h, g_W1h); cudaGetSymbolAddress(&W1l, g_W1l);
    cudaGetSymbolAddress(&W2h, g_W2h); cudaGetSymbolAddress(&W2l, g_W2l);
    cudaGetSymbolAddress(&W3h, g_W3h); cudaGetSymbolAddress(&W3l, g_W3l);
    cudaGetSymbolAddress(&D1h, g_D1h); cudaGetSymbolAddress(&D1l, g_D1l);
    cudaGetSymbolAddress(&D2h, g_D2h); cudaGetSymbolAddress(&D2l, g_D2l);
    cudaGetSymbolAddress(&D3h, g_D3h); cudaGetSymbolAddress(&D3l, g_D3l);
    cudaGetSymbolAddress(&h1h, g_h1h); cudaGetSymbolAddress(&h1l, g_h1l);
    cudaGetSymbolAddress(&h2h, g_h2h); cudaGetSymbolAddress(&h2l, g_h2l);
    cudaGetSymbolAddress(&wh, g_wh);   cudaGetSymbolAddress(&wl, g_wl);
    cudaGetSymbolAddress(&g1h, g_g1h); cudaGetSymbolAddress(&g1l, g_g1l);
    cudaGetSymbolAddress(&g2h, g_g2h); cudaGetSymbolAddress(&g2l, g_g2l);
    cudaGetSymbolAddress(&cq, g_cq);
    cudaGetSymbolAddress(&qn, g_qn);
    cudaGetSymbolAddress(&kn, g_kn);

    // 1. batched split: query + 6 weight matrices (+ fused counter zeroing)
    SplitArgs sa;
    int sizes4[7] = {BQ * DIM / 4, DIM * 512 / 4, 512 * 256 / 4, 256 * 128 / 4,
                     128 * 256 / 4, 256 * 512 / 4, 512 * 1024 / 4};
    const float* srcs[7] = {query, W1, W2, W3, D1w, D2w, D3w};
    void* hs[7] = {qh, W1h, W2h, W3h, D1h, D2h, D3h};
    void* ls[7] = {ql, W1l, W2l, W3l, D1l, D2l, D3l};
    sa.cum[0] = 0;
    for (int i = 0; i < 7; i++) {
        sa.s[i].src = srcs[i];
        sa.s[i].h = (__nv_bfloat16*)hs[i];
        sa.s[i].l = (__nv_bfloat16*)ls[i];
        sa.cum[i + 1] = sa.cum[i] + sizes4[i];
    }
    split_batch_kernel<<<(sa.cum[7] + 255) / 256, 256>>>(sa);

    // 2. key norms + sliced histogram
    rownorm_kernel<1><<<(NKEYS * 32 + 255) / 256, 256>>>(keys, (float*)kn, NKEYS);

    // 3. scan
    scan_kernel<<<1, 1024>>>();

    // 4-6. Encode MLP (launch #4 = bgemm L1 -> profiled by ncu -s 5)
    bgemm<1, 0, 1><<<dim3(512 / GBN, BQ / GBM), 256>>>(
        (__nv_bfloat16*)qh, (__nv_bfloat16*)ql, (__nv_bfloat16*)W1h, (__nv_bfloat16*)W1l,
        b1, nullptr, (__nv_bfloat16*)h1h, (__nv_bfloat16*)h1l, BQ, 512, 1024);
    bgemm<1, 0, 1><<<dim3(256 / GBN, BQ / GBM), 256>>>(
        (__nv_bfloat16*)h1h, (__nv_bfloat16*)h1l, (__nv_bfloat16*)W2h, (__nv_bfloat16*)W2l,
        b2, nullptr, (__nv_bfloat16*)h2h, (__nv_bfloat16*)h2l, BQ, 256, 512);
    bgemm<0, 1, 0><<<dim3(128 / GBN, BQ / GBM), 256>>>(
        (__nv_bfloat16*)h2h, (__nv_bfloat16*)h2l, (__nv_bfloat16*)W3h, (__nv_bfloat16*)W3l,
        b3, (float*)cq, nullptr, nullptr, BQ, 128, 256);

    // 7. scatter (independent of encode chain; overlaps in issue order)
    scatter_kernel<<<(NKEYS + 255) / 256, 256>>>();

    // 8. query norms
    rownorm_kernel<0><<<(BQ * 32 + 255) / 256, 256>>>((float*)cq, (float*)qn, BQ);

    // 9. exact rescore + top-5 + gather (emits weighted as bf16 hi/lo)
    rescore_kernel<<<BQ, 128>>>(keys, values, conf);

    // 10-12. Decode MLP
    bgemm<1, 0, 1><<<dim3(256 / GBN, BQ / GBM), 256>>>(
        (__nv_bfloat16*)wh, (__nv_bfloat16*)wl, (__nv_bfloat16*)D1h, (__nv_bfloat16*)D1l,
        D1b, nullptr, (__nv_bfloat16*)g1h, (__nv_bfloat16*)g1l, BQ, 256, 128);
    bgemm<1, 0, 1><<<dim3(512 / GBN, BQ / GBM), 256>>>(
        (__nv_bfloat16*)g1h, (__nv_bfloat16*)g1l, (__nv_bfloat16*)D2h, (__nv_bfloat16*)D2l,
        D2b, nullptr, (__nv_bfloat16*)g2h, (__nv_bfloat16*)g2l, BQ, 512, 256);
    bgemm<0, 1, 0><<<dim3(1024 / GBN, BQ / GBM), 256>>>(
        (__nv_bfloat16*)g2h, (__nv_bfloat16*)g2l, (__nv_bfloat16*)D3h, (__nv_bfloat16*)D3l,
        D3b, out, nullptr, nullptr, BQ, 1024, 512);
}

// round 13
// speedup vs baseline: 1.2708x; 1.0358x over previous
#include <cuda_runtime.h>
#include <cuda_bf16.h>
#include <math.h>

// Problem constants (fixed by setup_inputs)
#define BQ    1024
#define DIM   1024
#define CDIM  128
#define NKEYS 100000
#define KNN   5
#define EPSW  1e-6f
#define NB    2048
#define NSL   8
#define NCNT  (NB * NSL)
#define KN_LO 64.0f
#define KN_SPAN 128.0f

// ---------------- scratch (device globals; no allocations allowed) ---------
__device__ __align__(16) __nv_bfloat16 g_qh[BQ * DIM],   g_ql[BQ * DIM];
__device__ __align__(16) __nv_bfloat16 g_W1h[DIM * 512], g_W1l[DIM * 512];
__device__ __align__(16) __nv_bfloat16 g_W2h[512 * 256], g_W2l[512 * 256];
__device__ __align__(16) __nv_bfloat16 g_W3h[256 * 128], g_W3l[256 * 128];
__device__ __align__(16) __nv_bfloat16 g_D1h[128 * 256], g_D1l[128 * 256];
__device__ __align__(16) __nv_bfloat16 g_D2h[256 * 512], g_D2l[256 * 512];
__device__ __align__(16) __nv_bfloat16 g_D3h[512 * 1024], g_D3l[512 * 1024];
__device__ __align__(16) __nv_bfloat16 g_h1h[BQ * 512], g_h1l[BQ * 512];
__device__ __align__(16) __nv_bfloat16 g_h2h[BQ * 256], g_h2l[BQ * 256];
__device__ __align__(16) __nv_bfloat16 g_wh[BQ * CDIM], g_wl[BQ * CDIM];
__device__ __align__(16) __nv_bfloat16 g_g1h[BQ * 256], g_g1l[BQ * 256];
__device__ __align__(16) __nv_bfloat16 g_g2h[BQ * 512], g_g2l[BQ * 512];

__device__ float g_cq[BQ * CDIM];
__device__ float g_qn[BQ];
__device__ float g_kn[NKEYS];
__device__ int   g_hist[NCNT];
__device__ int   g_cursor[NCNT];
__device__ int   g_scand[NKEYS];
__device__ float g_skn[NKEYS];
__device__ float g_sblo[NKEYS];

// ---------------- fixed bucket mapping --------------------------------------
__device__ __forceinline__ int kn_bucket(float kn) {
    int b = (int)((kn - KN_LO) * ((float)NB / KN_SPAN));
    return min(NB - 1, max(0, b));
}
__device__ __forceinline__ float kn_floor(int b) {
    return (b == 0) ? 0.f : (KN_LO + (float)b * (KN_SPAN / (float)NB));
}

// ---------------- batched fp32 -> bf16 hi/lo split (+ counter zero) ---------
struct SplitSeg { const float* src; __nv_bfloat16* h; __nv_bfloat16* l; };
struct SplitArgs { SplitSeg s[7]; int cum[8]; };

__global__ void split_batch_kernel(SplitArgs a) {
    int i = blockIdx.x * blockDim.x + threadIdx.x;   // float4 units
    if (i < NCNT) g_hist[i] = 0;                     // fused counter init
    if (i >= a.cum[7]) return;
    int sg = 0;
    while (i >= a.cum[sg + 1]) sg++;
    int j = i - a.cum[sg];
    float4 v = reinterpret_cast<const float4*>(a.s[sg].src)[j];
    float x[4] = {v.x, v.y, v.z, v.w};
    unsigned short h[4], l[4];
#pragma unroll
    for (int q = 0; q < 4; q++) {
        __nv_bfloat16 hb = __float2bfloat16(x[q]);
        __nv_bfloat16 lb = __float2bfloat16(x[q] - __bfloat162float(hb));
        h[q] = __bfloat16_as_ushort(hb);
        l[q] = __bfloat16_as_ushort(lb);
    }
    uint2 hp = {(unsigned)h[0] | ((unsigned)h[1] << 16),
                (unsigned)h[2] | ((unsigned)h[3] << 16)};
    uint2 lp = {(unsigned)l[0] | ((unsigned)l[1] << 16),
                (unsigned)l[2] | ((unsigned)l[3] << 16)};
    reinterpret_cast<uint2*>(a.s[sg].h)[j] = hp;
    reinterpret_cast<uint2*>(a.s[sg].l)[j] = lp;
}

// ============================================================================
// bf16 hi/lo tensor-core GEMM (mma.sync). Tile 64x64, BK=32, 256 thr / 8 warps,
// warp tile 32x16. 4-stage cp.async pipeline (wait_group 2 -> ~2 tiles of
// memory latency always in flight). AhBh + AhBl + AlBh, fp32 accumulate.
// ============================================================================
#define GBM 64
#define GBN 64
#define GBK 32
#define ASTR 40
#define BSTR 72
#define PIPE 4
// per-stage byte layout: Ah[0,5120) Al[5120,10240) Bh[10240,14848) Bl[14848,19456)
#define PA_L  5120
#define PB_H  10240
#define PB_L  14848
#define PSTG  19456
#define PSM_TOTAL (PIPE * PSTG)

__device__ __forceinline__ void mma_bf16(float c[4], const unsigned a[4],
                                         const unsigned b[2]) {
    asm volatile(
        "mma.sync.aligned.m16n8k16.row.col.f32.bf16.bf16.f32 "
        "{%0,%1,%2,%3}, {%4,%5,%6,%7}, {%8,%9}, {%0,%1,%2,%3};"
        : "+f"(c[0]), "+f"(c[1]), "+f"(c[2]), "+f"(c[3])
        : "r"(a[0]), "r"(a[1]), "r"(a[2]), "r"(a[3]), "r"(b[0]), "r"(b[1]));
}
__device__ __forceinline__ void ldmA(unsigned a[4], unsigned addr) {
    asm volatile("ldmatrix.sync.aligned.m8n8.x4.shared.b16 {%0,%1,%2,%3}, [%4];"
                 : "=r"(a[0]), "=r"(a[1]), "=r"(a[2]), "=r"(a[3]) : "r"(addr));
}
__device__ __forceinline__ void ldmB(unsigned b[2], unsigned addr) {
    asm volatile("ldmatrix.sync.aligned.m8n8.x2.trans.shared.b16 {%0,%1}, [%2];"
                 : "=r"(b[0]), "=r"(b[1]) : "r"(addr));
}
__device__ __forceinline__ void cpa16(unsigned dst, const void* src) {
    asm volatile("cp.async.cg.shared.global [%0], [%1], 16;"
                 :: "r"(dst), "l"(src));
}

template <int RELU, int WF32, int WBF>
__global__ __launch_bounds__(256)
void bgemm(const __nv_bfloat16* __restrict__ Ah, const __nv_bfloat16* __restrict__ Al,
           const __nv_bfloat16* __restrict__ Bh, const __nv_bfloat16* __restrict__ Bl,
           const float* __restrict__ bias,
           float* __restrict__ Cf,
           __nv_bfloat16* __restrict__ Ch, __nv_bfloat16* __restrict__ Cl,
           int M, int N, int K) {
    extern __shared__ __align__(16) char smem[];
    const unsigned sbase = (unsigned)__cvta_generic_to_shared(smem);

    const int tid  = threadIdx.x;
    const int lane = tid & 31;
    const int wid  = tid >> 5;
    const int wm   = wid & 1;       // 2 warps along M (32 rows each)
    const int wn   = wid >> 1;      // 4 warps along N (16 cols each)
    const int bm   = blockIdx.y * GBM;
    const int bn   = blockIdx.x * GBN;

    const int ar  = tid >> 2;           // A row 0..63
    const int ac0 = (tid & 3) << 3;     // A col 0,8,16,24
    const int br  = tid >> 3;           // B row 0..31
    const int bc  = (tid & 7) << 3;     // B col 0..56

    const int a_r  = (lane & 7) + ((lane >> 3) & 1) * 8;
    const int a_k8 = (lane >> 4) * 8;
    const int b_r  = lane & 15;

    float acc[2][2][4];
#pragma unroll
    for (int mt = 0; mt < 2; mt++)
#pragma unroll
        for (int nt = 0; nt < 2; nt++)
#pragma unroll
            for (int i = 0; i < 4; i++) acc[mt][nt][i] = 0.f;

    const int ntk = K >> 5;

    auto stage = [&](int t) {
        if (t < ntk) {
            const unsigned base = sbase + (unsigned)(t & (PIPE - 1)) * PSTG;
            const int k0 = t * GBK;
            size_t ga = (size_t)(bm + ar) * K + k0 + ac0;
            unsigned da = base + (ar * ASTR + ac0) * 2;
            cpa16(da,        Ah + ga);
            cpa16(da + PA_L, Al + ga);
            size_t gb = (size_t)(k0 + br) * N + bn + bc;
            unsigned db = base + PB_H + (br * BSTR + bc) * 2;
            cpa16(db,               Bh + gb);
            cpa16(db + (PB_L - PB_H), Bl + gb);
        }
        asm volatile("cp.async.commit_group;");   // empty group past the end
    };

    // prologue: fill 3 stages
    stage(0);
    stage(1);
    stage(2);

    for (int t = 0; t < ntk; t++) {
        asm volatile("cp.async.wait_group 2;" ::: "memory");  // group t done
        __syncthreads();
        stage(t + 3);

        const unsigned base = sbase + (unsigned)(t & (PIPE - 1)) * PSTG;
        const unsigned base_ah = base;
        const unsigned base_al = base + PA_L;
        const unsigned base_bh = base + PB_H;
        const unsigned base_bl = base + PB_L;

#pragma unroll
        for (int kk = 0; kk < GBK; kk += 16) {
            unsigned ah[2][4], al_[2][4];
#pragma unroll
            for (int mt = 0; mt < 2; mt++) {
                unsigned ro = ((wm * 32 + mt * 16 + a_r) * ASTR + kk + a_k8) * 2;
                ldmA(ah[mt],  base_ah + ro);
                ldmA(al_[mt], base_al + ro);
            }
#pragma unroll
            for (int nt = 0; nt < 2; nt++) {
                unsigned bh[2], bl_[2];
                unsigned bo = ((kk + b_r) * BSTR + wn * 16 + nt * 8) * 2;
                ldmB(bh,  base_bh + bo);
                ldmB(bl_, base_bl + bo);
#pragma unroll
                for (int mt = 0; mt < 2; mt++) {
                    mma_bf16(acc[mt][nt], ah[mt],  bh);
                    mma_bf16(acc[mt][nt], ah[mt],  bl_);
                    mma_bf16(acc[mt][nt], al_[mt], bh);
                }
            }
        }
        __syncthreads();   // all reads of buffer t done before it is re-staged
    }

    // epilogue
    const int g  = lane >> 2;
    const int tq = lane & 3;
#pragma unroll
    for (int mt = 0; mt < 2; mt++) {
#pragma unroll
        for (int nt = 0; nt < 2; nt++) {
            int row = bm + wm * 32 + mt * 16 + g;
            int col = bn + wn * 16 + nt * 8 + tq * 2;
            float bz0 = bias[col], bz1 = bias[col + 1];
            float v0 = acc[mt][nt][0] + bz0;
            float v1 = acc[mt][nt][1] + bz1;
            float v2 = acc[mt][nt][2] + bz0;
            float v3 = acc[mt][nt][3] + bz1;
            if (RELU) {
                v0 = fmaxf(v0, 0.f); v1 = fmaxf(v1, 0.f);
                v2 = fmaxf(v2, 0.f); v3 = fmaxf(v3, 0.f);
            }
            if (WF32) {
                float2 o0 = {v0, v1}, o1 = {v2, v3};
                *reinterpret_cast<float2*>(&Cf[(size_t)row * N + col]) = o0;
                *reinterpret_cast<float2*>(&Cf[(size_t)(row + 8) * N + col]) = o1;
            }
            if (WBF) {
                __nv_bfloat16 h0 = __float2bfloat16(v0);
                __nv_bfloat16 h1 = __float2bfloat16(v1);
                __nv_bfloat16 h2 = __float2bfloat16(v2);
                __nv_bfloat16 h3 = __float2bfloat16(v3);
                unsigned hp0 = (unsigned)__bfloat16_as_ushort(h0) |
                               ((unsigned)__bfloat16_as_ushort(h1) << 16);
                unsigned hp1 = (unsigned)__bfloat16_as_ushort(h2) |
                               ((unsigned)__bfloat16_as_ushort(h3) << 16);
                unsigned lp0 = (unsigned)__bfloat16_as_ushort(
                                   __float2bfloat16(v0 - __bfloat162float(h0))) |
                               ((unsigned)__bfloat16_as_ushort(
                                   __float2bfloat16(v1 - __bfloat162float(h1))) << 16);
                unsigned lp1 = (unsigned)__bfloat16_as_ushort(
                                   __float2bfloat16(v2 - __bfloat162float(h2))) |
                               ((unsigned)__bfloat16_as_ushort(
                                   __float2bfloat16(v3 - __bfloat162float(h3))) << 16);
                *reinterpret_cast<unsigned*>(&Ch[(size_t)row * N + col]) = hp0;
                *reinterpret_cast<unsigned*>(&Ch[(size_t)(row + 8) * N + col]) = hp1;
                *reinterpret_cast<unsigned*>(&Cl[(size_t)row * N + col]) = lp0;
                *reinterpret_cast<unsigned*>(&Cl[(size_t)(row + 8) * N + col]) = lp1;
            }
        }
    }
}

// ---------------- row squared-norms (rows of width 128), fused histogram ---
template <int DO_HIST>
__global__ void rownorm_kernel(const float* __restrict__ X,
                               float* __restrict__ out, int rows) {
    int gw = (int)((blockIdx.x * (size_t)blockDim.x + threadIdx.x) >> 5);
    int lane = threadIdx.x & 31;
    if (gw >= rows) return;
    float4 v = reinterpret_cast<const float4*>(X + (size_t)gw * 128)[lane];
    float s = v.x * v.x + v.y * v.y + v.z * v.z + v.w * v.w;
#pragma unroll
    for (int o = 16; o; o >>= 1) s += __shfl_xor_sync(0xffffffffu, s, o);
    if (lane == 0) {
        out[gw] = s;
        if (DO_HIST) atomicAdd(&g_hist[kn_bucket(s) * NSL + (gw & (NSL - 1))], 1);
    }
}

// ---------------- exclusive scan over NCNT counters (1024 thr, 16/thr) -----
__global__ void scan_kernel() {
    __shared__ int wsum[32];
    const int t = threadIdx.x;
    const int lane = t & 31, w = t >> 5;
    const int base = t * 16;
    int loc[16];
    int s = 0;
#pragma unroll
    for (int i = 0; i < 16; i++) { loc[i] = g_hist[base + i]; s += loc[i]; }
    int x = s;
#pragma unroll
    for (int o = 1; o < 32; o <<= 1) {
        int y = __shfl_up_sync(0xffffffffu, x, o);
        if (lane >= o) x += y;
    }
    if (lane == 31) wsum[w] = x;
    __syncthreads();
    if (w == 0) {
        int v = wsum[lane];
#pragma unroll
        for (int o = 1; o < 32; o <<= 1) {
            int y = __shfl_up_sync(0xffffffffu, v, o);
            if (lane >= o) v += y;
        }
        wsum[lane] = v;
    }
    __syncthreads();
    int excl = x - s + (w > 0 ? wsum[w - 1] : 0);
#pragma unroll
    for (int i = 0; i < 16; i++) { g_cursor[base + i] = excl; excl += loc[i]; }
}

__global__ void scatter_kernel() {
    int n = blockIdx.x * blockDim.x + threadIdx.x;
    if (n >= NKEYS) return;
    float kn = g_kn[n];
    int b = kn_bucket(kn);
    int pos = atomicAdd(&g_cursor[b * NSL + (n & (NSL - 1))], 1);
    g_scand[pos] = n;
    g_skn[pos]   = kn;
    g_sblo[pos]  = kn_floor(b);
}

// ---------------- exact rescore + top-5 + weighted gather ------------------
__global__ __launch_bounds__(128, 8)
void rescore_kernel(const float* __restrict__ keys,
                    const float* __restrict__ values,
                    float* __restrict__ conf_out) {
    const int b = blockIdx.x;
    const int tid = threadIdx.x;
    const int lane = tid & 31;
    const int wid = tid >> 5;
    __shared__ float sq[CDIM];
    __shared__ float rd[KNN];
    __shared__ int   ri[KNN];
    __shared__ float wv[4][KNN];
    __shared__ int   wi[4][KNN];
    __shared__ float sw[KNN];
    __shared__ int   s_stop;

    sq[tid] = g_cq[(size_t)b * CDIM + tid];
    if (tid < KNN) { rd[tid] = 3.4e38f; ri[tid] = 0x7fffffff; }
    if (tid == 0) s_stop = 0;
    const float qn = g_qn[b];
    const float qb = sqrtf(qn);
    __syncthreads();

    for (int c0 = 0; c0 < NKEYS; c0 += 128) {
        int j = c0 + tid;
        float d = 3.4e38f;
        int   nidx = 0x7fffffff;
        if (j < NKEYS) {
            int n = g_scand[j];
            const float4* kr = reinterpret_cast<const float4*>(keys + (size_t)n * CDIM);
            const float4* sq4 = reinterpret_cast<const float4*>(sq);
            float a0 = 0.f, a1 = 0.f, a2 = 0.f, a3 = 0.f;
#pragma unroll
            for (int dd = 0; dd < CDIM / 4; dd++) {
                float4 kv = __ldg(&kr[dd]);
                float4 qv = sq4[dd];
                a0 = fmaf(qv.x, kv.x, a0);
                a1 = fmaf(qv.y, kv.y, a1);
                a2 = fmaf(qv.z, kv.z, a2);
                a3 = fmaf(qv.w, kv.w, a3);
            }
            float dot = (a0 + a1) + (a2 + a3);
            d = qn + g_skn[j] - 2.f * dot;
            nidx = n;
        }

#pragma unroll
        for (int r = 0; r < KNN; r++) {
            float v = d; int ix = nidx;
#pragma unroll
            for (int o = 16; o; o >>= 1) {
                float v2 = __shfl_xor_sync(0xffffffffu, v, o);
                int   i2 = __shfl_xor_sync(0xffffffffu, ix, o);
                if (v2 < v || (v2 == v && i2 < ix)) { v = v2; ix = i2; }
            }
            if (lane == 0) { wv[wid][r] = v; wi[wid][r] = ix; }
            if (d == v && nidx == ix) { d = 3.4e38f; nidx = 0x7fffffff; }
        }
        __syncthreads();

        if (tid == 0) {
#pragma unroll
            for (int w = 0; w < 4; w++) {
#pragma unroll
                for (int r = 0; r < KNN; r++) {
                    float v = wv[w][r]; int n = wi[w][r];
                    if (v < rd[KNN - 1] || (v == rd[KNN - 1] && n < ri[KNN - 1])) {
                        int p = KNN - 1;
                        while (p > 0 && (rd[p - 1] > v ||
                                         (rd[p - 1] == v && ri[p - 1] > n))) {
                            rd[p] = rd[p - 1]; ri[p] = ri[p - 1]; p--;
                        }
                        rd[p] = v; ri[p] = n;
                    }
                }
            }
            if (c0 + 128 < NKEYS) {
                float blo = g_sblo[c0 + 128];
                float lb = qn + blo - 2.f * qb * sqrtf(blo) - 1e-3f;
                if (lb > rd[KNN - 1]) s_stop = 1;
            }
        }
        __syncthreads();
        if (s_stop) break;
    }

    if (tid == 0) {
        float w[KNN], ws = 0.f;
#pragma unroll
        for (int j2 = 0; j2 < KNN; j2++) { w[j2] = 1.f / (rd[j2] + EPSW); ws += w[j2]; }
#pragma unroll
        for (int j2 = 0; j2 < KNN; j2++) sw[j2] = w[j2] / ws;
        conf_out[b] = 1.f / (rd[0] + EPSW);
    }
    __syncthreads();

    float acc = 0.f;
#pragma unroll
    for (int j2 = 0; j2 < KNN; j2++)
        acc += sw[j2] * values[(size_t)ri[j2] * CDIM + tid];
    __nv_bfloat16 hb = __float2bfloat16(acc);
    g_wh[(size_t)b * CDIM + tid] = hb;
    g_wl[(size_t)b * CDIM + tid] = __float2bfloat16(acc - __bfloat162float(hb));
}

// ---------------- launch ----------------------------------------------------
extern "C" void kernel_launch(void* const* d_in, const int* in_sizes, int n_in,
                              void* d_out, int out_size) {
    const float* query = (const float*)d_in[0];
    const float* W1    = (const float*)d_in[1];
    const float* b1    = (const float*)d_in[2];
    const float* W2    = (const float*)d_in[3];
    const float* b2    = (const float*)d_in[4];
    const float* W3    = (const float*)d_in[5];
    const float* b3    = (const float*)d_in[6];
    const float* keys  = (const float*)d_in[7];
    const float* values= (const float*)d_in[8];
    const float* D1w   = (const float*)d_in[9];
    const float* D1b   = (const float*)d_in[10];
    const float* D2w   = (const float*)d_in[11];
    const float* D2b   = (const float*)d_in[12];
    const float* D3w   = (const float*)d_in[13];
    const float* D3b   = (const float*)d_in[14];

    float* out  = (float*)d_out;
    float* conf = out + (size_t)BQ * DIM;

    void *qh, *ql, *W1h, *W1l, *W2h, *W2l, *W3h, *W3l;
    void *D1h, *D1l, *D2h, *D2l, *D3h, *D3l;
    void *h1h, *h1l, *h2h, *h2l, *wh, *wl, *g1h, *g1l, *g2h, *g2l;
    void *cq, *qn, *kn;
    cudaGetSymbolAddress(&qh, g_qh);   cudaGetSymbolAddress(&ql, g_ql);
    cudaGetSymbolAddress(&W1h, g_W1h); cudaGetSymbolAddress(&W1l, g_W1l);
    cudaGetSymbolAddress(&W2h, g_W2h); cudaGetSymbolAddress(&W2l, g_W2l);
    cudaGetSymbolAddress(&W3h, g_W3h); cudaGetSymbolAddress(&W3l, g_W3l);
    cudaGetSymbolAddress(&D1h, g_D1h); cudaGetSymbolAddress(&D1l, g_D1l);
    cudaGetSymbolAddress(&D2h, g_D2h); cudaGetSymbolAddress(&D2l, g_D2l);
    cudaGetSymbolAddress(&D3h, g_D3h); cudaGetSymbolAddress(&D3l, g_D3l);
    cudaGetSymbolAddress(&h1h, g_h1h); cudaGetSymbolAddress(&h1l, g_h1l);
    cudaGetSymbolAddress(&h2h, g_h2h); cudaGetSymbolAddress(&h2l, g_h2l);
    cudaGetSymbolAddress(&wh, g_wh);   cudaGetSymbolAddress(&wl, g_wl);
    cudaGetSymbolAddress(&g1h, g_g1h); cudaGetSymbolAddress(&g1l, g_g1l);
    cudaGetSymbolAddress(&g2h, g_g2h); cudaGetSymbolAddress(&g2l, g_g2l);
    cudaGetSymbolAddress(&cq, g_cq);
    cudaGetSymbolAddress(&qn, g_qn);
    cudaGetSymbolAddress(&kn, g_kn);

    cudaFuncSetAttribute(bgemm<1, 0, 1>,
                         cudaFuncAttributeMaxDynamicSharedMemorySize, PSM_TOTAL);
    cudaFuncSetAttribute(bgemm<0, 1, 0>,
                         cudaFuncAttributeMaxDynamicSharedMemorySize, PSM_TOTAL);

    // 1. batched split: query + 6 weight matrices (+ fused counter zeroing)
    SplitArgs sa;
    int sizes4[7] = {BQ * DIM / 4, DIM * 512 / 4, 512 * 256 / 4, 256 * 128 / 4,
                     128 * 256 / 4, 256 * 512 / 4, 512 * 1024 / 4};
    const float* srcs[7] = {query, W1, W2, W3, D1w, D2w, D3w};
    void* hs[7] = {qh, W1h, W2h, W3h, D1h, D2h, D3h};
    void* ls[7] = {ql, W1l, W2l, W3l, D1l, D2l, D3l};
    sa.cum[0] = 0;
    for (int i = 0; i < 7; i++) {
        sa.s[i].src = srcs[i];
        sa.s[i].h = (__nv_bfloat16*)hs[i];
        sa.s[i].l = (__nv_bfloat16*)ls[i];
        sa.cum[i + 1] = sa.cum[i] + sizes4[i];
    }
    split_batch_kernel<<<(sa.cum[7] + 255) / 256, 256>>>(sa);

    // 2. key norms + sliced histogram
    rownorm_kernel<1><<<(NKEYS * 32 + 255) / 256, 256>>>(keys, (float*)kn, NKEYS);

    // 3. scan
    scan_kernel<<<1, 1024>>>();

    // 4-6. Encode MLP (launch #4 = bgemm L1 -> profiled by ncu)
    bgemm<1, 0, 1><<<dim3(512 / GBN, BQ / GBM), 256, PSM_TOTAL>>>(
        (__nv_bfloat16*)qh, (__nv_bfloat16*)ql, (__nv_bfloat16*)W1h, (__nv_bfloat16*)W1l,
        b1, nullptr, (__nv_bfloat16*)h1h, (__nv_bfloat16*)h1l, BQ, 512, 1024);
    bgemm<1, 0, 1><<<dim3(256 / GBN, BQ / GBM), 256, PSM_TOTAL>>>(
        (__nv_bfloat16*)h1h, (__nv_bfloat16*)h1l, (__nv_bfloat16*)W2h, (__nv_bfloat16*)W2l,
        b2, nullptr, (__nv_bfloat16*)h2h, (__nv_bfloat16*)h2l, BQ, 256, 512);
    bgemm<0, 1, 0><<<dim3(128 / GBN, BQ / GBM), 256, PSM_TOTAL>>>(
        (__nv_bfloat16*)h2h, (__nv_bfloat16*)h2l, (__nv_bfloat16*)W3h, (__nv_bfloat16*)W3l,
        b3, (float*)cq, nullptr, nullptr, BQ, 128, 256);

    // 7. scatter (independent of encode chain)
    scatter_kernel<<<(NKEYS + 255) / 256, 256>>>();

    // 8. query norms
    rownorm_kernel<0><<<(BQ * 32 + 255) / 256, 256>>>((float*)cq, (float*)qn, BQ);

    // 9. exact rescore + top-5 + gather (emits weighted as bf16 hi/lo)
    rescore_kernel<<<BQ, 128>>>(keys, values, conf);

    // 10-12. Decode MLP
    bgemm<1, 0, 1><<<dim3(256 / GBN, BQ / GBM), 256, PSM_TOTAL>>>(
        (__nv_bfloat16*)wh, (__nv_bfloat16*)wl, (__nv_bfloat16*)D1h, (__nv_bfloat16*)D1l,
        D1b, nullptr, (__nv_bfloat16*)g1h, (__nv_bfloat16*)g1l, BQ, 256, 128);
    bgemm<1, 0, 1><<<dim3(512 / GBN, BQ / GBM), 256, PSM_TOTAL>>>(
        (__nv_bfloat16*)g1h, (__nv_bfloat16*)g1l, (__nv_bfloat16*)D2h, (__nv_bfloat16*)D2l,
        D2b, nullptr, (__nv_bfloat16*)g2h, (__nv_bfloat16*)g2l, BQ, 512, 256);
    bgemm<0, 1, 0><<<dim3(1024 / GBN, BQ / GBM), 256, PSM_TOTAL>>>(
        (__nv_bfloat16*)g2h, (__nv_bfloat16*)g2l, (__nv_bfloat16*)D3h, (__nv_bfloat16*)D3l,
        D3b, out, nullptr, nullptr, BQ, 1024, 512);
}

// round 14
// speedup vs baseline: 1.2788x; 1.0063x over previous
#include <cuda_runtime.h>
#include <cuda_bf16.h>
#include <math.h>

// Problem constants (fixed by setup_inputs)
#define BQ    1024
#define DIM   1024
#define CDIM  128
#define NKEYS 100000
#define KNN   5
#define EPSW  1e-6f
#define NB    2048
#define NSL   8
#define NCNT  (NB * NSL)
#define KN_LO 64.0f
#define KN_SPAN 128.0f

// ---------------- scratch (device globals; no allocations allowed) ---------
__device__ __align__(16) __nv_bfloat16 g_qh[BQ * DIM],   g_ql[BQ * DIM];
__device__ __align__(16) __nv_bfloat16 g_W1h[DIM * 512], g_W1l[DIM * 512];
__device__ __align__(16) __nv_bfloat16 g_W2h[512 * 256], g_W2l[512 * 256];
__device__ __align__(16) __nv_bfloat16 g_W3h[256 * 128], g_W3l[256 * 128];
__device__ __align__(16) __nv_bfloat16 g_D1h[128 * 256], g_D1l[128 * 256];
__device__ __align__(16) __nv_bfloat16 g_D2h[256 * 512], g_D2l[256 * 512];
__device__ __align__(16) __nv_bfloat16 g_D3h[512 * 1024], g_D3l[512 * 1024];
__device__ __align__(16) __nv_bfloat16 g_h1h[BQ * 512], g_h1l[BQ * 512];
__device__ __align__(16) __nv_bfloat16 g_h2h[BQ * 256], g_h2l[BQ * 256];
__device__ __align__(16) __nv_bfloat16 g_wh[BQ * CDIM], g_wl[BQ * CDIM];
__device__ __align__(16) __nv_bfloat16 g_g1h[BQ * 256], g_g1l[BQ * 256];
__device__ __align__(16) __nv_bfloat16 g_g2h[BQ * 512], g_g2l[BQ * 512];

__device__ float g_cq[BQ * CDIM];
__device__ float g_qn[BQ];
__device__ float g_kn[NKEYS];
__device__ int   g_hist[NCNT];
__device__ int   g_cursor[NCNT];
__device__ int   g_scand[NKEYS];
__device__ float g_skn[NKEYS];
__device__ float g_sblo[NKEYS];

// ---------------- fixed bucket mapping --------------------------------------
__device__ __forceinline__ int kn_bucket(float kn) {
    int b = (int)((kn - KN_LO) * ((float)NB / KN_SPAN));
    return min(NB - 1, max(0, b));
}
__device__ __forceinline__ float kn_floor(int b) {
    return (b == 0) ? 0.f : (KN_LO + (float)b * (KN_SPAN / (float)NB));
}

// ---------------- batched fp32 -> bf16 hi/lo split (+ counter zero) ---------
struct SplitSeg { const float* src; __nv_bfloat16* h; __nv_bfloat16* l; };
struct SplitArgs { SplitSeg s[7]; int cum[8]; };

__global__ void split_batch_kernel(SplitArgs a) {
    int i = blockIdx.x * blockDim.x + threadIdx.x;   // float4 units
    if (i < NCNT) g_hist[i] = 0;                     // fused counter init
    if (i >= a.cum[7]) return;
    int sg = 0;
    while (i >= a.cum[sg + 1]) sg++;
    int j = i - a.cum[sg];
    float4 v = reinterpret_cast<const float4*>(a.s[sg].src)[j];
    float x[4] = {v.x, v.y, v.z, v.w};
    unsigned short h[4], l[4];
#pragma unroll
    for (int q = 0; q < 4; q++) {
        __nv_bfloat16 hb = __float2bfloat16(x[q]);
        __nv_bfloat16 lb = __float2bfloat16(x[q] - __bfloat162float(hb));
        h[q] = __bfloat16_as_ushort(hb);
        l[q] = __bfloat16_as_ushort(lb);
    }
    uint2 hp = {(unsigned)h[0] | ((unsigned)h[1] << 16),
                (unsigned)h[2] | ((unsigned)h[3] << 16)};
    uint2 lp = {(unsigned)l[0] | ((unsigned)l[1] << 16),
                (unsigned)l[2] | ((unsigned)l[3] << 16)};
    reinterpret_cast<uint2*>(a.s[sg].h)[j] = hp;
    reinterpret_cast<uint2*>(a.s[sg].l)[j] = lp;
}

// ============================================================================
// bf16 hi/lo tensor-core GEMM (mma.sync). Tile 64x64, BK=32, 256 thr / 8 warps,
// warp tile 32x16. 4-stage cp.async pipeline. Per k-tile: all 16 LDSM hoisted
// into registers, then 24 MMAs issued TERM-MAJOR (same-acc dependency distance
// 4 instead of 1). One barrier per k-tile.
// ============================================================================
#define GBM 64
#define GBN 64
#define GBK 32
#define ASTR 40
#define BSTR 72
#define PIPE 4
#define PA_L  5120
#define PB_H  10240
#define PB_L  14848
#define PSTG  19456
#define PSM_TOTAL (PIPE * PSTG)

__device__ __forceinline__ void mma_bf16(float c[4], const unsigned a[4],
                                         const unsigned b[2]) {
    asm volatile(
        "mma.sync.aligned.m16n8k16.row.col.f32.bf16.bf16.f32 "
        "{%0,%1,%2,%3}, {%4,%5,%6,%7}, {%8,%9}, {%0,%1,%2,%3};"
        : "+f"(c[0]), "+f"(c[1]), "+f"(c[2]), "+f"(c[3])
        : "r"(a[0]), "r"(a[1]), "r"(a[2]), "r"(a[3]), "r"(b[0]), "r"(b[1]));
}
__device__ __forceinline__ void ldmA(unsigned a[4], unsigned addr) {
    asm volatile("ldmatrix.sync.aligned.m8n8.x4.shared.b16 {%0,%1,%2,%3}, [%4];"
                 : "=r"(a[0]), "=r"(a[1]), "=r"(a[2]), "=r"(a[3]) : "r"(addr));
}
__device__ __forceinline__ void ldmB(unsigned b[2], unsigned addr) {
    asm volatile("ldmatrix.sync.aligned.m8n8.x2.trans.shared.b16 {%0,%1}, [%2];"
                 : "=r"(b[0]), "=r"(b[1]) : "r"(addr));
}
__device__ __forceinline__ void cpa16(unsigned dst, const void* src) {
    asm volatile("cp.async.cg.shared.global [%0], [%1], 16;"
                 :: "r"(dst), "l"(src));
}

template <int RELU, int WF32, int WBF>
__global__ __launch_bounds__(256)
void bgemm(const __nv_bfloat16* __restrict__ Ah, const __nv_bfloat16* __restrict__ Al,
           const __nv_bfloat16* __restrict__ Bh, const __nv_bfloat16* __restrict__ Bl,
           const float* __restrict__ bias,
           float* __restrict__ Cf,
           __nv_bfloat16* __restrict__ Ch, __nv_bfloat16* __restrict__ Cl,
           int M, int N, int K) {
    extern __shared__ __align__(16) char smem[];
    const unsigned sbase = (unsigned)__cvta_generic_to_shared(smem);

    const int tid  = threadIdx.x;
    const int lane = tid & 31;
    const int wid  = tid >> 5;
    const int wm   = wid & 1;       // 2 warps along M (32 rows each)
    const int wn   = wid >> 1;      // 4 warps along N (16 cols each)
    const int bm   = blockIdx.y * GBM;
    const int bn   = blockIdx.x * GBN;

    const int ar  = tid >> 2;           // A row 0..63
    const int ac0 = (tid & 3) << 3;     // A col 0,8,16,24
    const int br  = tid >> 3;           // B row 0..31
    const int bc  = (tid & 7) << 3;     // B col 0..56

    const int a_r  = (lane & 7) + ((lane >> 3) & 1) * 8;
    const int a_k8 = (lane >> 4) * 8;
    const int b_r  = lane & 15;

    float acc[2][2][4];
#pragma unroll
    for (int mt = 0; mt < 2; mt++)
#pragma unroll
        for (int nt = 0; nt < 2; nt++)
#pragma unroll
            for (int i = 0; i < 4; i++) acc[mt][nt][i] = 0.f;

    const int ntk = K >> 5;

    auto stage = [&](int t) {
        if (t < ntk) {
            const unsigned base = sbase + (unsigned)(t & (PIPE - 1)) * PSTG;
            const int k0 = t * GBK;
            size_t ga = (size_t)(bm + ar) * K + k0 + ac0;
            unsigned da = base + (ar * ASTR + ac0) * 2;
            cpa16(da,        Ah + ga);
            cpa16(da + PA_L, Al + ga);
            size_t gb = (size_t)(k0 + br) * N + bn + bc;
            unsigned db = base + PB_H + (br * BSTR + bc) * 2;
            cpa16(db,                 Bh + gb);
            cpa16(db + (PB_L - PB_H), Bl + gb);
        }
        asm volatile("cp.async.commit_group;");   // empty group past the end
    };

    // prologue: fill 3 stages
    stage(0);
    stage(1);
    stage(2);

    for (int t = 0; t < ntk; t++) {
        asm volatile("cp.async.wait_group 2;" ::: "memory");  // group t done
        __syncthreads();   // also orders: compute(t-1) finished before restage
        stage(t + 3);

        const unsigned base = sbase + (unsigned)(t & (PIPE - 1)) * PSTG;
        const unsigned base_ah = base;
        const unsigned base_al = base + PA_L;
        const unsigned base_bh = base + PB_H;
        const unsigned base_bl = base + PB_L;

        // hoist ALL ldmatrix for this k-tile into registers
        unsigned ah[2][2][4], al_[2][2][4];   // [kk2][mt][..]
        unsigned bh[2][2][2], bl_[2][2][2];   // [kk2][nt][..]
#pragma unroll
        for (int kk2 = 0; kk2 < 2; kk2++) {
            const int kk = kk2 * 16;
#pragma unroll
            for (int mt = 0; mt < 2; mt++) {
                unsigned ro = ((wm * 32 + mt * 16 + a_r) * ASTR + kk + a_k8) * 2;
                ldmA(ah[kk2][mt],  base_ah + ro);
                ldmA(al_[kk2][mt], base_al + ro);
            }
#pragma unroll
            for (int nt = 0; nt < 2; nt++) {
                unsigned bo = ((kk + b_r) * BSTR + wn * 16 + nt * 8) * 2;
                ldmB(bh[kk2][nt],  base_bh + bo);
                ldmB(bl_[kk2][nt], base_bl + bo);
            }
        }

        // term-major MMA issue: same-acc dependency distance = 4
#pragma unroll
        for (int kk2 = 0; kk2 < 2; kk2++) {
#pragma unroll
            for (int mt = 0; mt < 2; mt++)
#pragma unroll
                for (int nt = 0; nt < 2; nt++)
                    mma_bf16(acc[mt][nt], ah[kk2][mt], bh[kk2][nt]);
#pragma unroll
            for (int mt = 0; mt < 2; mt++)
#pragma unroll
                for (int nt = 0; nt < 2; nt++)
                    mma_bf16(acc[mt][nt], ah[kk2][mt], bl_[kk2][nt]);
#pragma unroll
            for (int mt = 0; mt < 2; mt++)
#pragma unroll
                for (int nt = 0; nt < 2; nt++)
                    mma_bf16(acc[mt][nt], al_[kk2][mt], bh[kk2][nt]);
        }
    }

    // epilogue
    const int g  = lane >> 2;
    const int tq = lane & 3;
#pragma unroll
    for (int mt = 0; mt < 2; mt++) {
#pragma unroll
        for (int nt = 0; nt < 2; nt++) {
            int row = bm + wm * 32 + mt * 16 + g;
            int col = bn + wn * 16 + nt * 8 + tq * 2;
            float bz0 = bias[col], bz1 = bias[col + 1];
            float v0 = acc[mt][nt][0] + bz0;
            float v1 = acc[mt][nt][1] + bz1;
            float v2 = acc[mt][nt][2] + bz0;
            float v3 = acc[mt][nt][3] + bz1;
            if (RELU) {
                v0 = fmaxf(v0, 0.f); v1 = fmaxf(v1, 0.f);
                v2 = fmaxf(v2, 0.f); v3 = fmaxf(v3, 0.f);
            }
            if (WF32) {
                float2 o0 = {v0, v1}, o1 = {v2, v3};
                *reinterpret_cast<float2*>(&Cf[(size_t)row * N + col]) = o0;
                *reinterpret_cast<float2*>(&Cf[(size_t)(row + 8) * N + col]) = o1;
            }
            if (WBF) {
                __nv_bfloat16 h0 = __float2bfloat16(v0);
                __nv_bfloat16 h1 = __float2bfloat16(v1);
                __nv_bfloat16 h2 = __float2bfloat16(v2);
                __nv_bfloat16 h3 = __float2bfloat16(v3);
                unsigned hp0 = (unsigned)__bfloat16_as_ushort(h0) |
                               ((unsigned)__bfloat16_as_ushort(h1) << 16);
                unsigned hp1 = (unsigned)__bfloat16_as_ushort(h2) |
                               ((unsigned)__bfloat16_as_ushort(h3) << 16);
                unsigned lp0 = (unsigned)__bfloat16_as_ushort(
                                   __float2bfloat16(v0 - __bfloat162float(h0))) |
                               ((unsigned)__bfloat16_as_ushort(
                                   __float2bfloat16(v1 - __bfloat162float(h1))) << 16);
                unsigned lp1 = (unsigned)__bfloat16_as_ushort(
                                   __float2bfloat16(v2 - __bfloat162float(h2))) |
                               ((unsigned)__bfloat16_as_ushort(
                                   __float2bfloat16(v3 - __bfloat162float(h3))) << 16);
                *reinterpret_cast<unsigned*>(&Ch[(size_t)row * N + col]) = hp0;
                *reinterpret_cast<unsigned*>(&Ch[(size_t)(row + 8) * N + col]) = hp1;
                *reinterpret_cast<unsigned*>(&Cl[(size_t)row * N + col]) = lp0;
                *reinterpret_cast<unsigned*>(&Cl[(size_t)(row + 8) * N + col]) = lp1;
            }
        }
    }
}

// ---------------- row squared-norms (rows of width 128), fused histogram ---
template <int DO_HIST>
__global__ void rownorm_kernel(const float* __restrict__ X,
                               float* __restrict__ out, int rows) {
    int gw = (int)((blockIdx.x * (size_t)blockDim.x + threadIdx.x) >> 5);
    int lane = threadIdx.x & 31;
    if (gw >= rows) return;
    float4 v = reinterpret_cast<const float4*>(X + (size_t)gw * 128)[lane];
    float s = v.x * v.x + v.y * v.y + v.z * v.z + v.w * v.w;
#pragma unroll
    for (int o = 16; o; o >>= 1) s += __shfl_xor_sync(0xffffffffu, s, o);
    if (lane == 0) {
        out[gw] = s;
        if (DO_HIST) atomicAdd(&g_hist[kn_bucket(s) * NSL + (gw & (NSL - 1))], 1);
    }
}

// ---------------- exclusive scan over NCNT counters (1024 thr, 16/thr) -----
__global__ void scan_kernel() {
    __shared__ int wsum[32];
    const int t = threadIdx.x;
    const int lane = t & 31, w = t >> 5;
    const int base = t * 16;
    int loc[16];
    int s = 0;
#pragma unroll
    for (int i = 0; i < 16; i++) { loc[i] = g_hist[base + i]; s += loc[i]; }
    int x = s;
#pragma unroll
    for (int o = 1; o < 32; o <<= 1) {
        int y = __shfl_up_sync(0xffffffffu, x, o);
        if (lane >= o) x += y;
    }
    if (lane == 31) wsum[w] = x;
    __syncthreads();
    if (w == 0) {
        int v = wsum[lane];
#pragma unroll
        for (int o = 1; o < 32; o <<= 1) {
            int y = __shfl_up_sync(0xffffffffu, v, o);
            if (lane >= o) v += y;
        }
        wsum[lane] = v;
    }
    __syncthreads();
    int excl = x - s + (w > 0 ? wsum[w - 1] : 0);
#pragma unroll
    for (int i = 0; i < 16; i++) { g_cursor[base + i] = excl; excl += loc[i]; }
}

__global__ void scatter_kernel() {
    int n = blockIdx.x * blockDim.x + threadIdx.x;
    if (n >= NKEYS) return;
    float kn = g_kn[n];
    int b = kn_bucket(kn);
    int pos = atomicAdd(&g_cursor[b * NSL + (n & (NSL - 1))], 1);
    g_scand[pos] = n;
    g_skn[pos]   = kn;
    g_sblo[pos]  = kn_floor(b);
}

// ---------------- exact rescore + top-5 + weighted gather ------------------
__global__ __launch_bounds__(128, 8)
void rescore_kernel(const float* __restrict__ keys,
                    const float* __restrict__ values,
                    float* __restrict__ conf_out) {
    const int b = blockIdx.x;
    const int tid = threadIdx.x;
    const int lane = tid & 31;
    const int wid = tid >> 5;
    __shared__ float sq[CDIM];
    __shared__ float rd[KNN];
    __shared__ int   ri[KNN];
    __shared__ float wv[4][KNN];
    __shared__ int   wi[4][KNN];
    __shared__ float sw[KNN];
    __shared__ int   s_stop;

    sq[tid] = g_cq[(size_t)b * CDIM + tid];
    if (tid < KNN) { rd[tid] = 3.4e38f; ri[tid] = 0x7fffffff; }
    if (tid == 0) s_stop = 0;
    const float qn = g_qn[b];
    const float qb = sqrtf(qn);
    __syncthreads();

    for (int c0 = 0; c0 < NKEYS; c0 += 128) {
        int j = c0 + tid;
        float d = 3.4e38f;
        int   nidx = 0x7fffffff;
        if (j < NKEYS) {
            int n = g_scand[j];
            const float4* kr = reinterpret_cast<const float4*>(keys + (size_t)n * CDIM);
            const float4* sq4 = reinterpret_cast<const float4*>(sq);
            float a0 = 0.f, a1 = 0.f, a2 = 0.f, a3 = 0.f;
#pragma unroll
            for (int dd = 0; dd < CDIM / 4; dd++) {
                float4 kv = __ldg(&kr[dd]);
                float4 qv = sq4[dd];
                a0 = fmaf(qv.x, kv.x, a0);
                a1 = fmaf(qv.y, kv.y, a1);
                a2 = fmaf(qv.z, kv.z, a2);
                a3 = fmaf(qv.w, kv.w, a3);
            }
            float dot = (a0 + a1) + (a2 + a3);
            d = qn + g_skn[j] - 2.f * dot;
            nidx = n;
        }

#pragma unroll
        for (int r = 0; r < KNN; r++) {
            float v = d; int ix = nidx;
#pragma unroll
            for (int o = 16; o; o >>= 1) {
                float v2 = __shfl_xor_sync(0xffffffffu, v, o);
                int   i2 = __shfl_xor_sync(0xffffffffu, ix, o);
                if (v2 < v || (v2 == v && i2 < ix)) { v = v2; ix = i2; }
            }
            if (lane == 0) { wv[wid][r] = v; wi[wid][r] = ix; }
            if (d == v && nidx == ix) { d = 3.4e38f; nidx = 0x7fffffff; }
        }
        __syncthreads();

        if (tid == 0) {
#pragma unroll
            for (int w = 0; w < 4; w++) {
#pragma unroll
                for (int r = 0; r < KNN; r++) {
                    float v = wv[w][r]; int n = wi[w][r];
                    if (v < rd[KNN - 1] || (v == rd[KNN - 1] && n < ri[KNN - 1])) {
                        int p = KNN - 1;
                        while (p > 0 && (rd[p - 1] > v ||
                                         (rd[p - 1] == v && ri[p - 1] > n))) {
                            rd[p] = rd[p - 1]; ri[p] = ri[p - 1]; p--;
                        }
                        rd[p] = v; ri[p] = n;
                    }
                }
            }
            if (c0 + 128 < NKEYS) {
                float blo = g_sblo[c0 + 128];
                float lb = qn + blo - 2.f * qb * sqrtf(blo) - 1e-3f;
                if (lb > rd[KNN - 1]) s_stop = 1;
            }
        }
        __syncthreads();
        if (s_stop) break;
    }

    if (tid == 0) {
        float w[KNN], ws = 0.f;
#pragma unroll
        for (int j2 = 0; j2 < KNN; j2++) { w[j2] = 1.f / (rd[j2] + EPSW); ws += w[j2]; }
#pragma unroll
        for (int j2 = 0; j2 < KNN; j2++) sw[j2] = w[j2] / ws;
        conf_out[b] = 1.f / (rd[0] + EPSW);
    }
    __syncthreads();

    float acc = 0.f;
#pragma unroll
    for (int j2 = 0; j2 < KNN; j2++)
        acc += sw[j2] * values[(size_t)ri[j2] * CDIM + tid];
    __nv_bfloat16 hb = __float2bfloat16(acc);
    g_wh[(size_t)b * CDIM + tid] = hb;
    g_wl[(size_t)b * CDIM + tid] = __float2bfloat16(acc - __bfloat162float(hb));
}

// ---------------- launch ----------------------------------------------------
extern "C" void kernel_launch(void* const* d_in, const int* in_sizes, int n_in,
                              void* d_out, int out_size) {
    const float* query = (const float*)d_in[0];
    const float* W1    = (const float*)d_in[1];
    const float* b1    = (const float*)d_in[2];
    const float* W2    = (const float*)d_in[3];
    const float* b2    = (const float*)d_in[4];
    const float* W3    = (const float*)d_in[5];
    const float* b3    = (const float*)d_in[6];
    const float* keys  = (const float*)d_in[7];
    const float* values= (const float*)d_in[8];
    const float* D1w   = (const float*)d_in[9];
    const float* D1b   = (const float*)d_in[10];
    const float* D2w   = (const float*)d_in[11];
    const float* D2b   = (const float*)d_in[12];
    const float* D3w   = (const float*)d_in[13];
    const float* D3b   = (const float*)d_in[14];

    float* out  = (float*)d_out;
    float* conf = out + (size_t)BQ * DIM;

    void *qh, *ql, *W1h, *W1l, *W2h, *W2l, *W3h, *W3l;
    void *D1h, *D1l, *D2h, *D2l, *D3h, *D3l;
    void *h1h, *h1l, *h2h, *h2l, *wh, *wl, *g1h, *g1l, *g2h, *g2l;
    void *cq, *qn, *kn;
    cudaGetSymbolAddress(&qh, g_qh);   cudaGetSymbolAddress(&ql, g_ql);
    cudaGetSymbolAddress(&W1h, g_W1h); cudaGetSymbolAddress(&W1l, g_W1l);
    cudaGetSymbolAddress(&W2h, g_W2h); cudaGetSymbolAddress(&W2l, g_W2l);
    cudaGetSymbolAddress(&W3h, g_W3h); cudaGetSymbolAddress(&W3l, g_W3l);
    cudaGetSymbolAddress(&D1h, g_D1h); cudaGetSymbolAddress(&D1l, g_D1l);
    cudaGetSymbolAddress(&D2h, g_D2h); cudaGetSymbolAddress(&D2l, g_D2l);
    cudaGetSymbolAddress(&D3h, g_D3h); cudaGetSymbolAddress(&D3l, g_D3l);
    cudaGetSymbolAddress(&h1h, g_h1h); cudaGetSymbolAddress(&h1l, g_h1l);
    cudaGetSymbolAddress(&h2h, g_h2h); cudaGetSymbolAddress(&h2l, g_h2l);
    cudaGetSymbolAddress(&wh, g_wh);   cudaGetSymbolAddress(&wl, g_wl);
    cudaGetSymbolAddress(&g1h, g_g1h); cudaGetSymbolAddress(&g1l, g_g1l);
    cudaGetSymbolAddress(&g2h, g_g2h); cudaGetSymbolAddress(&g2l, g_g2l);
    cudaGetSymbolAddress(&cq, g_cq);
    cudaGetSymbolAddress(&qn, g_qn);
    cudaGetSymbolAddress(&kn, g_kn);

    cudaFuncSetAttribute(bgemm<1, 0, 1>,
                         cudaFuncAttributeMaxDynamicSharedMemorySize, PSM_TOTAL);
    cudaFuncSetAttribute(bgemm<0, 1, 0>,
                         cudaFuncAttributeMaxDynamicSharedMemorySize, PSM_TOTAL);

    // 1. batched split: query + 6 weight matrices (+ fused counter zeroing)
    SplitArgs sa;
    int sizes4[7] = {BQ * DIM / 4, DIM * 512 / 4, 512 * 256 / 4, 256 * 128 / 4,
                     128 * 256 / 4, 256 * 512 / 4, 512 * 1024 / 4};
    const float* srcs[7] = {query, W1, W2, W3, D1w, D2w, D3w};
    void* hs[7] = {qh, W1h, W2h, W3h, D1h, D2h, D3h};
    void* ls[7] = {ql, W1l, W2l, W3l, D1l, D2l, D3l};
    sa.cum[0] = 0;
    for (int i = 0; i < 7; i++) {
        sa.s[i].src = srcs[i];
        sa.s[i].h = (__nv_bfloat16*)hs[i];
        sa.s[i].l = (__nv_bfloat16*)ls[i];
        sa.cum[i + 1] = sa.cum[i] + sizes4[i];
    }
    split_batch_kernel<<<(sa.cum[7] + 255) / 256, 256>>>(sa);

    // 2. key norms + sliced histogram
    rownorm_kernel<1><<<(NKEYS * 32 + 255) / 256, 256>>>(keys, (float*)kn, NKEYS);

    // 3. scan
    scan_kernel<<<1, 1024>>>();

    // 4-6. Encode MLP (launch #4 = bgemm L1 -> profiled by ncu)
    bgemm<1, 0, 1><<<dim3(512 / GBN, BQ / GBM), 256, PSM_TOTAL>>>(
        (__nv_bfloat16*)qh, (__nv_bfloat16*)ql, (__nv_bfloat16*)W1h, (__nv_bfloat16*)W1l,
        b1, nullptr, (__nv_bfloat16*)h1h, (__nv_bfloat16*)h1l, BQ, 512, 1024);
    bgemm<1, 0, 1><<<dim3(256 / GBN, BQ / GBM), 256, PSM_TOTAL>>>(
        (__nv_bfloat16*)h1h, (__nv_bfloat16*)h1l, (__nv_bfloat16*)W2h, (__nv_bfloat16*)W2l,
        b2, nullptr, (__nv_bfloat16*)h2h, (__nv_bfloat16*)h2l, BQ, 256, 512);
    bgemm<0, 1, 0><<<dim3(128 / GBN, BQ / GBM), 256, PSM_TOTAL>>>(
        (__nv_bfloat16*)h2h, (__nv_bfloat16*)h2l, (__nv_bfloat16*)W3h, (__nv_bfloat16*)W3l,
        b3, (float*)cq, nullptr, nullptr, BQ, 128, 256);

    // 7. scatter (independent of encode chain)
    scatter_kernel<<<(NKEYS + 255) / 256, 256>>>();

    // 8. query norms
    rownorm_kernel<0><<<(BQ * 32 + 255) / 256, 256>>>((float*)cq, (float*)qn, BQ);

    // 9. exact rescore + top-5 + gather (emits weighted as bf16 hi/lo)
    rescore_kernel<<<BQ, 128>>>(keys, values, conf);

    // 10-12. Decode MLP
    bgemm<1, 0, 1><<<dim3(256 / GBN, BQ / GBM), 256, PSM_TOTAL>>>(
        (__nv_bfloat16*)wh, (__nv_bfloat16*)wl, (__nv_bfloat16*)D1h, (__nv_bfloat16*)D1l,
        D1b, nullptr, (__nv_bfloat16*)g1h, (__nv_bfloat16*)g1l, BQ, 256, 128);
    bgemm<1, 0, 1><<<dim3(512 / GBN, BQ / GBM), 256, PSM_TOTAL>>>(
        (__nv_bfloat16*)g1h, (__nv_bfloat16*)g1l, (__nv_bfloat16*)D2h, (__nv_bfloat16*)D2l,
        D2b, nullptr, (__nv_bfloat16*)g2h, (__nv_bfloat16*)g2l, BQ, 512, 256);
    bgemm<0, 1, 0><<<dim3(1024 / GBN, BQ / GBM), 256, PSM_TOTAL>>>(
        (__nv_bfloat16*)g2h, (__nv_bfloat16*)g2l, (__nv_bfloat16*)D3h, (__nv_bfloat16*)D3l,
        D3b, out, nullptr, nullptr, BQ, 1024, 512);
}

// round 15
// speedup vs baseline: 1.4936x; 1.1680x over previous
#include <cuda_runtime.h>
#include <cuda_bf16.h>
#include <math.h>

// Problem constants (fixed by setup_inputs)
#define BQ    1024
#define DIM   1024
#define CDIM  128
#define NKEYS 100000
#define KNN   5
#define EPSW  1e-6f
#define NB    2048
#define NSL   8
#define NCNT  (NB * NSL)
#define KN_LO 64.0f
#define KN_SPAN 128.0f

// ---------------- scratch (device globals; no allocations allowed) ---------
__device__ __align__(16) __nv_bfloat16 g_qh[BQ * DIM],   g_ql[BQ * DIM];
__device__ __align__(16) __nv_bfloat16 g_W1h[DIM * 512], g_W1l[DIM * 512];
__device__ __align__(16) __nv_bfloat16 g_W2h[512 * 256], g_W2l[512 * 256];
__device__ __align__(16) __nv_bfloat16 g_W3h[256 * 128], g_W3l[256 * 128];
__device__ __align__(16) __nv_bfloat16 g_D1h[128 * 256], g_D1l[128 * 256];
__device__ __align__(16) __nv_bfloat16 g_D2h[256 * 512], g_D2l[256 * 512];
__device__ __align__(16) __nv_bfloat16 g_D3h[512 * 1024], g_D3l[512 * 1024];
__device__ __align__(16) __nv_bfloat16 g_h1h[BQ * 512], g_h1l[BQ * 512];
__device__ __align__(16) __nv_bfloat16 g_h2h[BQ * 256], g_h2l[BQ * 256];
__device__ __align__(16) __nv_bfloat16 g_wh[BQ * CDIM], g_wl[BQ * CDIM];
__device__ __align__(16) __nv_bfloat16 g_g1h[BQ * 256], g_g1l[BQ * 256];
__device__ __align__(16) __nv_bfloat16 g_g2h[BQ * 512], g_g2l[BQ * 512];

__device__ float g_cq[BQ * CDIM];
__device__ float g_qn[BQ];
__device__ float g_kn[NKEYS];
__device__ int   g_hist[NCNT];
__device__ int   g_cursor[NCNT];
__device__ int   g_scand[NKEYS];
__device__ float g_skn[NKEYS];
__device__ float g_sblo[NKEYS];

// ---------------- side stream for overlap (created once, host-side only) ---
static cudaStream_t g_side = nullptr;
static cudaEvent_t  g_evFork = nullptr, g_evJoin = nullptr;
static struct StreamInit {
    StreamInit() {
        cudaStreamCreateWithFlags(&g_side, cudaStreamNonBlocking);
        cudaEventCreateWithFlags(&g_evFork, cudaEventDisableTiming);
        cudaEventCreateWithFlags(&g_evJoin, cudaEventDisableTiming);
    }
} g_streamInit;

// ---------------- fixed bucket mapping --------------------------------------
__device__ __forceinline__ int kn_bucket(float kn) {
    int b = (int)((kn - KN_LO) * ((float)NB / KN_SPAN));
    return min(NB - 1, max(0, b));
}
__device__ __forceinline__ float kn_floor(int b) {
    return (b == 0) ? 0.f : (KN_LO + (float)b * (KN_SPAN / (float)NB));
}

// ---------------- batched fp32 -> bf16 hi/lo split (+ counter zero) ---------
struct SplitSeg { const float* src; __nv_bfloat16* h; __nv_bfloat16* l; };
struct SplitArgs { SplitSeg s[7]; int cum[8]; };

__global__ void split_batch_kernel(SplitArgs a) {
    int i = blockIdx.x * blockDim.x + threadIdx.x;   // float4 units
    if (i < NCNT) g_hist[i] = 0;                     // fused counter init
    if (i >= a.cum[7]) return;
    int sg = 0;
    while (i >= a.cum[sg + 1]) sg++;
    int j = i - a.cum[sg];
    float4 v = reinterpret_cast<const float4*>(a.s[sg].src)[j];
    float x[4] = {v.x, v.y, v.z, v.w};
    unsigned short h[4], l[4];
#pragma unroll
    for (int q = 0; q < 4; q++) {
        __nv_bfloat16 hb = __float2bfloat16(x[q]);
        __nv_bfloat16 lb = __float2bfloat16(x[q] - __bfloat162float(hb));
        h[q] = __bfloat16_as_ushort(hb);
        l[q] = __bfloat16_as_ushort(lb);
    }
    uint2 hp = {(unsigned)h[0] | ((unsigned)h[1] << 16),
                (unsigned)h[2] | ((unsigned)h[3] << 16)};
    uint2 lp = {(unsigned)l[0] | ((unsigned)l[1] << 16),
                (unsigned)l[2] | ((unsigned)l[3] << 16)};
    reinterpret_cast<uint2*>(a.s[sg].h)[j] = hp;
    reinterpret_cast<uint2*>(a.s[sg].l)[j] = lp;
}

// ============================================================================
// bf16 hi/lo tensor-core GEMM (mma.sync). Tile 64x64, BK=64, 256 thr / 8 warps,
// warp tile 32x16. 4-stage cp.async pipeline, ONE barrier per 64-wide k-tile
// (half the barrier count of BK=32). Per k16 sub-step: 8 LDSM + 12 term-major
// MMA. AhBh + AhBl + AlBh, fp32 accumulate.
// ============================================================================
#define GBM 64
#define GBN 64
#define GBK 64
#define ASTR 72
#define PIPE 4
#define PA_L  9216
#define PB_H  18432
#define PB_L  27648
#define PSTG  36864
#define PSM_TOTAL (PIPE * PSTG)     // 147456 bytes

__device__ __forceinline__ void mma_bf16(float c[4], const unsigned a[4],
                                         const unsigned b[2]) {
    asm volatile(
        "mma.sync.aligned.m16n8k16.row.col.f32.bf16.bf16.f32 "
        "{%0,%1,%2,%3}, {%4,%5,%6,%7}, {%8,%9}, {%0,%1,%2,%3};"
        : "+f"(c[0]), "+f"(c[1]), "+f"(c[2]), "+f"(c[3])
        : "r"(a[0]), "r"(a[1]), "r"(a[2]), "r"(a[3]), "r"(b[0]), "r"(b[1]));
}
__device__ __forceinline__ void ldmA(unsigned a[4], unsigned addr) {
    asm volatile("ldmatrix.sync.aligned.m8n8.x4.shared.b16 {%0,%1,%2,%3}, [%4];"
                 : "=r"(a[0]), "=r"(a[1]), "=r"(a[2]), "=r"(a[3]) : "r"(addr));
}
__device__ __forceinline__ void ldmB(unsigned b[2], unsigned addr) {
    asm volatile("ldmatrix.sync.aligned.m8n8.x2.trans.shared.b16 {%0,%1}, [%2];"
                 : "=r"(b[0]), "=r"(b[1]) : "r"(addr));
}
__device__ __forceinline__ void cpa16(unsigned dst, const void* src) {
    asm volatile("cp.async.cg.shared.global [%0], [%1], 16;"
                 :: "r"(dst), "l"(src));
}

template <int RELU, int WF32, int WBF>
__global__ __launch_bounds__(256)
void bgemm(const __nv_bfloat16* __restrict__ Ah, const __nv_bfloat16* __restrict__ Al,
           const __nv_bfloat16* __restrict__ Bh, const __nv_bfloat16* __restrict__ Bl,
           const float* __restrict__ bias,
           float* __restrict__ Cf,
           __nv_bfloat16* __restrict__ Ch, __nv_bfloat16* __restrict__ Cl,
           int M, int N, int K) {
    extern __shared__ __align__(16) char smem[];
    const unsigned sbase = (unsigned)__cvta_generic_to_shared(smem);

    const int tid  = threadIdx.x;
    const int lane = tid & 31;
    const int wid  = tid >> 5;
    const int wm   = wid & 1;       // 2 warps along M (32 rows each)
    const int wn   = wid >> 1;      // 4 warps along N (16 cols each)
    const int bm   = blockIdx.y * GBM;
    const int bn   = blockIdx.x * GBN;

    // staging: thread covers row (tid>>2), 16 contiguous elems at col (tid&3)*16
    const int sr  = tid >> 2;           // 0..63 (A row / B k-row)
    const int sc  = (tid & 3) << 4;     // 0,16,32,48

    const int a_r  = (lane & 7) + ((lane >> 3) & 1) * 8;
    const int a_k8 = (lane >> 4) * 8;
    const int b_r  = lane & 15;

    float acc[2][2][4];
#pragma unroll
    for (int mt = 0; mt < 2; mt++)
#pragma unroll
        for (int nt = 0; nt < 2; nt++)
#pragma unroll
            for (int i = 0; i < 4; i++) acc[mt][nt][i] = 0.f;

    const int ntk = K >> 6;

    auto stage = [&](int t) {
        if (t < ntk) {
            const unsigned base = sbase + (unsigned)(t & (PIPE - 1)) * PSTG;
            const int k0 = t * GBK;
            size_t ga = (size_t)(bm + sr) * K + k0 + sc;
            unsigned da = base + (sr * ASTR + sc) * 2;
            cpa16(da,             Ah + ga);
            cpa16(da + 16,        Ah + ga + 8);
            cpa16(da + PA_L,      Al + ga);
            cpa16(da + PA_L + 16, Al + ga + 8);
            size_t gb = (size_t)(k0 + sr) * N + bn + sc;
            unsigned db = base + PB_H + (sr * ASTR + sc) * 2;
            cpa16(db,                     Bh + gb);
            cpa16(db + 16,                Bh + gb + 8);
            cpa16(db + (PB_L - PB_H),     Bl + gb);
            cpa16(db + (PB_L - PB_H) + 16, Bl + gb + 8);
        }
        asm volatile("cp.async.commit_group;");   // empty group past the end
    };

    // prologue: fill 3 stages
    stage(0);
    stage(1);
    stage(2);

    for (int t = 0; t < ntk; t++) {
        asm volatile("cp.async.wait_group 2;" ::: "memory");  // group t done
        __syncthreads();   // also orders: compute(t-1) done before restage
        stage(t + 3);

        const unsigned base = sbase + (unsigned)(t & (PIPE - 1)) * PSTG;
        const unsigned base_ah = base;
        const unsigned base_al = base + PA_L;
        const unsigned base_bh = base + PB_H;
        const unsigned base_bl = base + PB_L;

#pragma unroll
        for (int kk4 = 0; kk4 < 4; kk4++) {
            const int kk = kk4 * 16;
            unsigned ah[2][4], al_[2][4], bhv[2][2], blv[2][2];
#pragma unroll
            for (int mt = 0; mt < 2; mt++) {
                unsigned ro = ((wm * 32 + mt * 16 + a_r) * ASTR + kk + a_k8) * 2;
                ldmA(ah[mt],  base_ah + ro);
                ldmA(al_[mt], base_al + ro);
            }
#pragma unroll
            for (int nt = 0; nt < 2; nt++) {
                unsigned bo = ((kk + b_r) * ASTR + wn * 16 + nt * 8) * 2;
                ldmB(bhv[nt], base_bh + bo);
                ldmB(blv[nt], base_bl + bo);
            }
            // term-major: same-acc dependency distance = 4
#pragma unroll
            for (int mt = 0; mt < 2; mt++)
#pragma unroll
                for (int nt = 0; nt < 2; nt++)
                    mma_bf16(acc[mt][nt], ah[mt], bhv[nt]);
#pragma unroll
            for (int mt = 0; mt < 2; mt++)
#pragma unroll
                for (int nt = 0; nt < 2; nt++)
                    mma_bf16(acc[mt][nt], ah[mt], blv[nt]);
#pragma unroll
            for (int mt = 0; mt < 2; mt++)
#pragma unroll
                for (int nt = 0; nt < 2; nt++)
                    mma_bf16(acc[mt][nt], al_[mt], bhv[nt]);
        }
    }

    // epilogue
    const int g  = lane >> 2;
    const int tq = lane & 3;
#pragma unroll
    for (int mt = 0; mt < 2; mt++) {
#pragma unroll
        for (int nt = 0; nt < 2; nt++) {
            int row = bm + wm * 32 + mt * 16 + g;
            int col = bn + wn * 16 + nt * 8 + tq * 2;
            float bz0 = bias[col], bz1 = bias[col + 1];
            float v0 = acc[mt][nt][0] + bz0;
            float v1 = acc[mt][nt][1] + bz1;
            float v2 = acc[mt][nt][2] + bz0;
            float v3 = acc[mt][nt][3] + bz1;
            if (RELU) {
                v0 = fmaxf(v0, 0.f); v1 = fmaxf(v1, 0.f);
                v2 = fmaxf(v2, 0.f); v3 = fmaxf(v3, 0.f);
            }
            if (WF32) {
                float2 o0 = {v0, v1}, o1 = {v2, v3};
                *reinterpret_cast<float2*>(&Cf[(size_t)row * N + col]) = o0;
                *reinterpret_cast<float2*>(&Cf[(size_t)(row + 8) * N + col]) = o1;
            }
            if (WBF) {
                __nv_bfloat16 h0 = __float2bfloat16(v0);
                __nv_bfloat16 h1 = __float2bfloat16(v1);
                __nv_bfloat16 h2 = __float2bfloat16(v2);
                __nv_bfloat16 h3 = __float2bfloat16(v3);
                unsigned hp0 = (unsigned)__bfloat16_as_ushort(h0) |
                               ((unsigned)__bfloat16_as_ushort(h1) << 16);
                unsigned hp1 = (unsigned)__bfloat16_as_ushort(h2) |
                               ((unsigned)__bfloat16_as_ushort(h3) << 16);
                unsigned lp0 = (unsigned)__bfloat16_as_ushort(
                                   __float2bfloat16(v0 - __bfloat162float(h0))) |
                               ((unsigned)__bfloat16_as_ushort(
                                   __float2bfloat16(v1 - __bfloat162float(h1))) << 16);
                unsigned lp1 = (unsigned)__bfloat16_as_ushort(
                                   __float2bfloat16(v2 - __bfloat162float(h2))) |
                               ((unsigned)__bfloat16_as_ushort(
                                   __float2bfloat16(v3 - __bfloat162float(h3))) << 16);
                *reinterpret_cast<unsigned*>(&Ch[(size_t)row * N + col]) = hp0;
                *reinterpret_cast<unsigned*>(&Ch[(size_t)(row + 8) * N + col]) = hp1;
                *reinterpret_cast<unsigned*>(&Cl[(size_t)row * N + col]) = lp0;
                *reinterpret_cast<unsigned*>(&Cl[(size_t)(row + 8) * N + col]) = lp1;
            }
        }
    }
}

// ---------------- row squared-norms (rows of width 128), fused histogram ---
template <int DO_HIST>
__global__ void rownorm_kernel(const float* __restrict__ X,
                               float* __restrict__ out, int rows) {
    int gw = (int)((blockIdx.x * (size_t)blockDim.x + threadIdx.x) >> 5);
    int lane = threadIdx.x & 31;
    if (gw >= rows) return;
    float4 v = reinterpret_cast<const float4*>(X + (size_t)gw * 128)[lane];
    float s = v.x * v.x + v.y * v.y + v.z * v.z + v.w * v.w;
#pragma unroll
    for (int o = 16; o; o >>= 1) s += __shfl_xor_sync(0xffffffffu, s, o);
    if (lane == 0) {
        out[gw] = s;
        if (DO_HIST) atomicAdd(&g_hist[kn_bucket(s) * NSL + (gw & (NSL - 1))], 1);
    }
}

// ---------------- exclusive scan over NCNT counters (1024 thr, 16/thr) -----
__global__ void scan_kernel() {
    __shared__ int wsum[32];
    const int t = threadIdx.x;
    const int lane = t & 31, w = t >> 5;
    const int base = t * 16;
    int loc[16];
    int s = 0;
#pragma unroll
    for (int i = 0; i < 16; i++) { loc[i] = g_hist[base + i]; s += loc[i]; }
    int x = s;
#pragma unroll
    for (int o = 1; o < 32; o <<= 1) {
        int y = __shfl_up_sync(0xffffffffu, x, o);
        if (lane >= o) x += y;
    }
    if (lane == 31) wsum[w] = x;
    __syncthreads();
    if (w == 0) {
        int v = wsum[lane];
#pragma unroll
        for (int o = 1; o < 32; o <<= 1) {
            int y = __shfl_up_sync(0xffffffffu, v, o);
            if (lane >= o) v += y;
        }
        wsum[lane] = v;
    }
    __syncthreads();
    int excl = x - s + (w > 0 ? wsum[w - 1] : 0);
#pragma unroll
    for (int i = 0; i < 16; i++) { g_cursor[base + i] = excl; excl += loc[i]; }
}

__global__ void scatter_kernel() {
    int n = blockIdx.x * blockDim.x + threadIdx.x;
    if (n >= NKEYS) return;
    float kn = g_kn[n];
    int b = kn_bucket(kn);
    int pos = atomicAdd(&g_cursor[b * NSL + (n & (NSL - 1))], 1);
    g_scand[pos] = n;
    g_skn[pos]   = kn;
    g_sblo[pos]  = kn_floor(b);
}

// ---------------- exact rescore + top-5 + weighted gather ------------------
__global__ __launch_bounds__(128, 8)
void rescore_kernel(const float* __restrict__ keys,
                    const float* __restrict__ values,
                    float* __restrict__ conf_out) {
    const int b = blockIdx.x;
    const int tid = threadIdx.x;
    const int lane = tid & 31;
    const int wid = tid >> 5;
    __shared__ float sq[CDIM];
    __shared__ float rd[KNN];
    __shared__ int   ri[KNN];
    __shared__ float wv[4][KNN];
    __shared__ int   wi[4][KNN];
    __shared__ float sw[KNN];
    __shared__ int   s_stop;

    sq[tid] = g_cq[(size_t)b * CDIM + tid];
    if (tid < KNN) { rd[tid] = 3.4e38f; ri[tid] = 0x7fffffff; }
    if (tid == 0) s_stop = 0;
    const float qn = g_qn[b];
    const float qb = sqrtf(qn);
    __syncthreads();

    for (int c0 = 0; c0 < NKEYS; c0 += 128) {
        int j = c0 + tid;
        float d = 3.4e38f;
        int   nidx = 0x7fffffff;
        if (j < NKEYS) {
            int n = g_scand[j];
            const float4* kr = reinterpret_cast<const float4*>(keys + (size_t)n * CDIM);
            const float4* sq4 = reinterpret_cast<const float4*>(sq);
            float a0 = 0.f, a1 = 0.f, a2 = 0.f, a3 = 0.f;
#pragma unroll
            for (int dd = 0; dd < CDIM / 4; dd++) {
                float4 kv = __ldg(&kr[dd]);
                float4 qv = sq4[dd];
                a0 = fmaf(qv.x, kv.x, a0);
                a1 = fmaf(qv.y, kv.y, a1);
                a2 = fmaf(qv.z, kv.z, a2);
                a3 = fmaf(qv.w, kv.w, a3);
            }
            float dot = (a0 + a1) + (a2 + a3);
            d = qn + g_skn[j] - 2.f * dot;
            nidx = n;
        }

#pragma unroll
        for (int r = 0; r < KNN; r++) {
            float v = d; int ix = nidx;
#pragma unroll
            for (int o = 16; o; o >>= 1) {
                float v2 = __shfl_xor_sync(0xffffffffu, v, o);
                int   i2 = __shfl_xor_sync(0xffffffffu, ix, o);
                if (v2 < v || (v2 == v && i2 < ix)) { v = v2; ix = i2; }
            }
            if (lane == 0) { wv[wid][r] = v; wi[wid][r] = ix; }
            if (d == v && nidx == ix) { d = 3.4e38f; nidx = 0x7fffffff; }
        }
        __syncthreads();

        if (tid == 0) {
#pragma unroll
            for (int w = 0; w < 4; w++) {
#pragma unroll
                for (int r = 0; r < KNN; r++) {
                    float v = wv[w][r]; int n = wi[w][r];
                    if (v < rd[KNN - 1] || (v == rd[KNN - 1] && n < ri[KNN - 1])) {
                        int p = KNN - 1;
                        while (p > 0 && (rd[p - 1] > v ||
                                         (rd[p - 1] == v && ri[p - 1] > n))) {
                            rd[p] = rd[p - 1]; ri[p] = ri[p - 1]; p--;
                        }
                        rd[p] = v; ri[p] = n;
                    }
                }
            }
            if (c0 + 128 < NKEYS) {
                float blo = g_sblo[c0 + 128];
                float lb = qn + blo - 2.f * qb * sqrtf(blo) - 1e-3f;
                if (lb > rd[KNN - 1]) s_stop = 1;
            }
        }
        __syncthreads();
        if (s_stop) break;
    }

    if (tid == 0) {
        float w[KNN], ws = 0.f;
#pragma unroll
        for (int j2 = 0; j2 < KNN; j2++) { w[j2] = 1.f / (rd[j2] + EPSW); ws += w[j2]; }
#pragma unroll
        for (int j2 = 0; j2 < KNN; j2++) sw[j2] = w[j2] / ws;
        conf_out[b] = 1.f / (rd[0] + EPSW);
    }
    __syncthreads();

    float acc = 0.f;
#pragma unroll
    for (int j2 = 0; j2 < KNN; j2++)
        acc += sw[j2] * values[(size_t)ri[j2] * CDIM + tid];
    __nv_bfloat16 hb = __float2bfloat16(acc);
    g_wh[(size_t)b * CDIM + tid] = hb;
    g_wl[(size_t)b * CDIM + tid] = __float2bfloat16(acc - __bfloat162float(hb));
}

// ---------------- launch ----------------------------------------------------
extern "C" void kernel_launch(void* const* d_in, const int* in_sizes, int n_in,
                              void* d_out, int out_size) {
    const float* query = (const float*)d_in[0];
    const float* W1    = (const float*)d_in[1];
    const float* b1    = (const float*)d_in[2];
    const float* W2    = (const float*)d_in[3];
    const float* b2    = (const float*)d_in[4];
    const float* W3    = (const float*)d_in[5];
    const float* b3    = (const float*)d_in[6];
    const float* keys  = (const float*)d_in[7];
    const float* values= (const float*)d_in[8];
    const float* D1w   = (const float*)d_in[9];
    const float* D1b   = (const float*)d_in[10];
    const float* D2w   = (const float*)d_in[11];
    const float* D2b   = (const float*)d_in[12];
    const float* D3w   = (const float*)d_in[13];
    const float* D3b   = (const float*)d_in[14];

    float* out  = (float*)d_out;
    float* conf = out + (size_t)BQ * DIM;

    void *qh, *ql, *W1h, *W1l, *W2h, *W2l, *W3h, *W3l;
    void *D1h, *D1l, *D2h, *D2l, *D3h, *D3l;
    void *h1h, *h1l, *h2h, *h2l, *wh, *wl, *g1h, *g1l, *g2h, *g2l;
    void *cq, *qn, *kn;
    cudaGetSymbolAddress(&qh, g_qh);   cudaGetSymbolAddress(&ql, g_ql);
    cudaGetSymbolAddress(&W1h, g_W1h); cudaGetSymbolAddress(&W1l, g_W1l);
    cudaGetSymbolAddress(&W2h, g_W2h); cudaGetSymbolAddress(&W2l, g_W2l);
    cudaGetSymbolAddress(&W3h, g_W3h); cudaGetSymbolAddress(&W3l, g_W3l);
    cudaGetSymbolAddress(&D1h, g_D1h); cudaGetSymbolAddress(&D1l, g_D1l);
    cudaGetSymbolAddress(&D2h, g_D2h); cudaGetSymbolAddress(&D2l, g_D2l);
    cudaGetSymbolAddress(&D3h, g_D3h); cudaGetSymbolAddress(&D3l, g_D3l);
    cudaGetSymbolAddress(&h1h, g_h1h); cudaGetSymbolAddress(&h1l, g_h1l);
    cudaGetSymbolAddress(&h2h, g_h2h); cudaGetSymbolAddress(&h2l, g_h2l);
    cudaGetSymbolAddress(&wh, g_wh);   cudaGetSymbolAddress(&wl, g_wl);
    cudaGetSymbolAddress(&g1h, g_g1h); cudaGetSymbolAddress(&g1l, g_g1l);
    cudaGetSymbolAddress(&g2h, g_g2h); cudaGetSymbolAddress(&g2l, g_g2l);
    cudaGetSymbolAddress(&cq, g_cq);
    cudaGetSymbolAddress(&qn, g_qn);
    cudaGetSymbolAddress(&kn, g_kn);

    cudaFuncSetAttribute(bgemm<1, 0, 1>,
                         cudaFuncAttributeMaxDynamicSharedMemorySize, PSM_TOTAL);
    cudaFuncSetAttribute(bgemm<0, 1, 0>,
                         cudaFuncAttributeMaxDynamicSharedMemorySize, PSM_TOTAL);

    // 1. batched split: query + 6 weight matrices (+ fused counter zeroing)
    SplitArgs sa;
    int sizes4[7] = {BQ * DIM / 4, DIM * 512 / 4, 512 * 256 / 4, 256 * 128 / 4,
                     128 * 256 / 4, 256 * 512 / 4, 512 * 1024 / 4};
    const float* srcs[7] = {query, W1, W2, W3, D1w, D2w, D3w};
    void* hs[7] = {qh, W1h, W2h, W3h, D1h, D2h, D3h};
    void* ls[7] = {ql, W1l, W2l, W3l, D1l, D2l, D3l};
    sa.cum[0] = 0;
    for (int i = 0; i < 7; i++) {
        sa.s[i].src = srcs[i];
        sa.s[i].h = (__nv_bfloat16*)hs[i];
        sa.s[i].l = (__nv_bfloat16*)ls[i];
        sa.cum[i + 1] = sa.cum[i] + sizes4[i];
    }
    split_batch_kernel<<<(sa.cum[7] + 255) / 256, 256>>>(sa);

    // fork: retrieval prep on side stream, overlapped with encode GEMMs
    cudaEventRecord(g_evFork, 0);
    cudaStreamWaitEvent(g_side, g_evFork, 0);
    rownorm_kernel<1><<<(NKEYS * 32 + 255) / 256, 256, 0, g_side>>>(
        keys, (float*)kn, NKEYS);
    scan_kernel<<<1, 1024, 0, g_side>>>();
    scatter_kernel<<<(NKEYS + 255) / 256, 256, 0, g_side>>>();
    cudaEventRecord(g_evJoin, g_side);

    // Encode MLP (main stream)
    bgemm<1, 0, 1><<<dim3(512 / GBN, BQ / GBM), 256, PSM_TOTAL>>>(
        (__nv_bfloat16*)qh, (__nv_bfloat16*)ql, (__nv_bfloat16*)W1h, (__nv_bfloat16*)W1l,
        b1, nullptr, (__nv_bfloat16*)h1h, (__nv_bfloat16*)h1l, BQ, 512, 1024);
    bgemm<1, 0, 1><<<dim3(256 / GBN, BQ / GBM), 256, PSM_TOTAL>>>(
        (__nv_bfloat16*)h1h, (__nv_bfloat16*)h1l, (__nv_bfloat16*)W2h, (__nv_bfloat16*)W2l,
        b2, nullptr, (__nv_bfloat16*)h2h, (__nv_bfloat16*)h2l, BQ, 256, 512);
    bgemm<0, 1, 0><<<dim3(128 / GBN, BQ / GBM), 256, PSM_TOTAL>>>(
        (__nv_bfloat16*)h2h, (__nv_bfloat16*)h2l, (__nv_bfloat16*)W3h, (__nv_bfloat16*)W3l,
        b3, (float*)cq, nullptr, nullptr, BQ, 128, 256);

    // query norms
    rownorm_kernel<0><<<(BQ * 32 + 255) / 256, 256>>>((float*)cq, (float*)qn, BQ);

    // join: rescore needs scatter results
    cudaStreamWaitEvent(0, g_evJoin, 0);

    // exact rescore + top-5 + gather (emits weighted as bf16 hi/lo)
    rescore_kernel<<<BQ, 128>>>(keys, values, conf);

    // Decode MLP
    bgemm<1, 0, 1><<<dim3(256 / GBN, BQ / GBM), 256, PSM_TOTAL>>>(
        (__nv_bfloat16*)wh, (__nv_bfloat16*)wl, (__nv_bfloat16*)D1h, (__nv_bfloat16*)D1l,
        D1b, nullptr, (__nv_bfloat16*)g1h, (__nv_bfloat16*)g1l, BQ, 256, 128);
    bgemm<1, 0, 1><<<dim3(512 / GBN, BQ / GBM), 256, PSM_TOTAL>>>(
        (__nv_bfloat16*)g1h, (__nv_bfloat16*)g1l, (__nv_bfloat16*)D2h, (__nv_bfloat16*)D2l,
        D2b, nullptr, (__nv_bfloat16*)g2h, (__nv_bfloat16*)g2l, BQ, 512, 256);
    bgemm<0, 1, 0><<<dim3(1024 / GBN, BQ / GBM), 256, PSM_TOTAL>>>(
        (__nv_bfloat16*)g2h, (__nv_bfloat16*)g2l, (__nv_bfloat16*)D3h, (__nv_bfloat16*)D3l,
        D3b, out, nullptr, nullptr, BQ, 1024, 512);
}

// round 16
// speedup vs baseline: 1.5829x; 1.0598x over previous
#include <cuda_runtime.h>
#include <cuda_bf16.h>
#include <math.h>

// Problem constants (fixed by setup_inputs)
#define BQ    1024
#define DIM   1024
#define CDIM  128
#define NKEYS 100000
#define KNN   5
#define EPSW  1e-6f
#define NB    2048
#define NSL   8
#define NCNT  (NB * NSL)
#define KN_LO 64.0f
#define KN_SPAN 128.0f
#define QPB   4            // queries per rescore block (one warp each)

// ---------------- scratch (device globals; no allocations allowed) ---------
__device__ __align__(16) __nv_bfloat16 g_qh[BQ * DIM],   g_ql[BQ * DIM];
__device__ __align__(16) __nv_bfloat16 g_W1h[DIM * 512], g_W1l[DIM * 512];
__device__ __align__(16) __nv_bfloat16 g_W2h[512 * 256], g_W2l[512 * 256];
__device__ __align__(16) __nv_bfloat16 g_W3h[256 * 128], g_W3l[256 * 128];
__device__ __align__(16) __nv_bfloat16 g_D1h[128 * 256], g_D1l[128 * 256];
__device__ __align__(16) __nv_bfloat16 g_D2h[256 * 512], g_D2l[256 * 512];
__device__ __align__(16) __nv_bfloat16 g_D3h[512 * 1024], g_D3l[512 * 1024];
__device__ __align__(16) __nv_bfloat16 g_h1h[BQ * 512], g_h1l[BQ * 512];
__device__ __align__(16) __nv_bfloat16 g_h2h[BQ * 256], g_h2l[BQ * 256];
__device__ __align__(16) __nv_bfloat16 g_wh[BQ * CDIM], g_wl[BQ * CDIM];
__device__ __align__(16) __nv_bfloat16 g_g1h[BQ * 256], g_g1l[BQ * 256];
__device__ __align__(16) __nv_bfloat16 g_g2h[BQ * 512], g_g2l[BQ * 512];

__device__ float g_cq[BQ * CDIM];
__device__ float g_kn[NKEYS];
__device__ int   g_hist[NCNT];
__device__ int   g_cursor[NCNT];
__device__ int   g_scand[NKEYS];
__device__ float g_skn[NKEYS];
__device__ float g_sblo[NKEYS];

// ---------------- side stream for overlap (created once, host-side only) ---
static cudaStream_t g_side = nullptr;
static cudaEvent_t  g_evFork = nullptr, g_evJoin = nullptr;
static struct StreamInit {
    StreamInit() {
        cudaStreamCreateWithFlags(&g_side, cudaStreamNonBlocking);
        cudaEventCreateWithFlags(&g_evFork, cudaEventDisableTiming);
        cudaEventCreateWithFlags(&g_evJoin, cudaEventDisableTiming);
    }
} g_streamInit;

// ---------------- fixed bucket mapping --------------------------------------
__device__ __forceinline__ int kn_bucket(float kn) {
    int b = (int)((kn - KN_LO) * ((float)NB / KN_SPAN));
    return min(NB - 1, max(0, b));
}
__device__ __forceinline__ float kn_floor(int b) {
    return (b == 0) ? 0.f : (KN_LO + (float)b * (KN_SPAN / (float)NB));
}

// ---------------- batched fp32 -> bf16 hi/lo split (+ counter zero) ---------
struct SplitSeg { const float* src; __nv_bfloat16* h; __nv_bfloat16* l; };
struct SplitArgs { SplitSeg s[7]; int cum[8]; };

__global__ void split_batch_kernel(SplitArgs a) {
    int i = blockIdx.x * blockDim.x + threadIdx.x;   // float4 units
    if (i < NCNT) g_hist[i] = 0;                     // fused counter init
    if (i >= a.cum[7]) return;
    int sg = 0;
    while (i >= a.cum[sg + 1]) sg++;
    int j = i - a.cum[sg];
    float4 v = reinterpret_cast<const float4*>(a.s[sg].src)[j];
    float x[4] = {v.x, v.y, v.z, v.w};
    unsigned short h[4], l[4];
#pragma unroll
    for (int q = 0; q < 4; q++) {
        __nv_bfloat16 hb = __float2bfloat16(x[q]);
        __nv_bfloat16 lb = __float2bfloat16(x[q] - __bfloat162float(hb));
        h[q] = __bfloat16_as_ushort(hb);
        l[q] = __bfloat16_as_ushort(lb);
    }
    uint2 hp = {(unsigned)h[0] | ((unsigned)h[1] << 16),
                (unsigned)h[2] | ((unsigned)h[3] << 16)};
    uint2 lp = {(unsigned)l[0] | ((unsigned)l[1] << 16),
                (unsigned)l[2] | ((unsigned)l[3] << 16)};
    reinterpret_cast<uint2*>(a.s[sg].h)[j] = hp;
    reinterpret_cast<uint2*>(a.s[sg].l)[j] = lp;
}

// ============================================================================
// bf16 hi/lo tensor-core GEMM (mma.sync). Tile 64x64, BK=64, 256 thr / 8 warps,
// warp tile 32x16. 4-stage cp.async pipeline, ONE barrier per 64-wide k-tile.
// Per k16 sub-step: 8 LDSM + 12 term-major MMA. AhBh + AhBl + AlBh, fp32 acc.
// ============================================================================
#define GBM 64
#define GBN 64
#define GBK 64
#define ASTR 72
#define PIPE 4
#define PA_L  9216
#define PB_H  18432
#define PB_L  27648
#define PSTG  36864
#define PSM_TOTAL (PIPE * PSTG)     // 147456 bytes

__device__ __forceinline__ void mma_bf16(float c[4], const unsigned a[4],
                                         const unsigned b[2]) {
    asm volatile(
        "mma.sync.aligned.m16n8k16.row.col.f32.bf16.bf16.f32 "
        "{%0,%1,%2,%3}, {%4,%5,%6,%7}, {%8,%9}, {%0,%1,%2,%3};"
        : "+f"(c[0]), "+f"(c[1]), "+f"(c[2]), "+f"(c[3])
        : "r"(a[0]), "r"(a[1]), "r"(a[2]), "r"(a[3]), "r"(b[0]), "r"(b[1]));
}
__device__ __forceinline__ void ldmA(unsigned a[4], unsigned addr) {
    asm volatile("ldmatrix.sync.aligned.m8n8.x4.shared.b16 {%0,%1,%2,%3}, [%4];"
                 : "=r"(a[0]), "=r"(a[1]), "=r"(a[2]), "=r"(a[3]) : "r"(addr));
}
__device__ __forceinline__ void ldmB(unsigned b[2], unsigned addr) {
    asm volatile("ldmatrix.sync.aligned.m8n8.x2.trans.shared.b16 {%0,%1}, [%2];"
                 : "=r"(b[0]), "=r"(b[1]) : "r"(addr));
}
__device__ __forceinline__ void cpa16(unsigned dst, const void* src) {
    asm volatile("cp.async.cg.shared.global [%0], [%1], 16;"
                 :: "r"(dst), "l"(src));
}

template <int RELU, int WF32, int WBF>
__global__ __launch_bounds__(256)
void bgemm(const __nv_bfloat16* __restrict__ Ah, const __nv_bfloat16* __restrict__ Al,
           const __nv_bfloat16* __restrict__ Bh, const __nv_bfloat16* __restrict__ Bl,
           const float* __restrict__ bias,
           float* __restrict__ Cf,
           __nv_bfloat16* __restrict__ Ch, __nv_bfloat16* __restrict__ Cl,
           int M, int N, int K) {
    extern __shared__ __align__(16) char smem[];
    const unsigned sbase = (unsigned)__cvta_generic_to_shared(smem);

    const int tid  = threadIdx.x;
    const int lane = tid & 31;
    const int wid  = tid >> 5;
    const int wm   = wid & 1;
    const int wn   = wid >> 1;
    const int bm   = blockIdx.y * GBM;
    const int bn   = blockIdx.x * GBN;

    const int sr  = tid >> 2;
    const int sc  = (tid & 3) << 4;

    const int a_r  = (lane & 7) + ((lane >> 3) & 1) * 8;
    const int a_k8 = (lane >> 4) * 8;
    const int b_r  = lane & 15;

    float acc[2][2][4];
#pragma unroll
    for (int mt = 0; mt < 2; mt++)
#pragma unroll
        for (int nt = 0; nt < 2; nt++)
#pragma unroll
            for (int i = 0; i < 4; i++) acc[mt][nt][i] = 0.f;

    const int ntk = K >> 6;

    auto stage = [&](int t) {
        if (t < ntk) {
            const unsigned base = sbase + (unsigned)(t & (PIPE - 1)) * PSTG;
            const int k0 = t * GBK;
            size_t ga = (size_t)(bm + sr) * K + k0 + sc;
            unsigned da = base + (sr * ASTR + sc) * 2;
            cpa16(da,             Ah + ga);
            cpa16(da + 16,        Ah + ga + 8);
            cpa16(da + PA_L,      Al + ga);
            cpa16(da + PA_L + 16, Al + ga + 8);
            size_t gb = (size_t)(k0 + sr) * N + bn + sc;
            unsigned db = base + PB_H + (sr * ASTR + sc) * 2;
            cpa16(db,                      Bh + gb);
            cpa16(db + 16,                 Bh + gb + 8);
            cpa16(db + (PB_L - PB_H),      Bl + gb);
            cpa16(db + (PB_L - PB_H) + 16, Bl + gb + 8);
        }
        asm volatile("cp.async.commit_group;");
    };

    stage(0);
    stage(1);
    stage(2);

    for (int t = 0; t < ntk; t++) {
        asm volatile("cp.async.wait_group 2;" ::: "memory");
        __syncthreads();
        stage(t + 3);

        const unsigned base = sbase + (unsigned)(t & (PIPE - 1)) * PSTG;
        const unsigned base_ah = base;
        const unsigned base_al = base + PA_L;
        const unsigned base_bh = base + PB_H;
        const unsigned base_bl = base + PB_L;

#pragma unroll
        for (int kk4 = 0; kk4 < 4; kk4++) {
            const int kk = kk4 * 16;
            unsigned ah[2][4], al_[2][4], bhv[2][2], blv[2][2];
#pragma unroll
            for (int mt = 0; mt < 2; mt++) {
                unsigned ro = ((wm * 32 + mt * 16 + a_r) * ASTR + kk + a_k8) * 2;
                ldmA(ah[mt],  base_ah + ro);
                ldmA(al_[mt], base_al + ro);
            }
#pragma unroll
            for (int nt = 0; nt < 2; nt++) {
                unsigned bo = ((kk + b_r) * ASTR + wn * 16 + nt * 8) * 2;
                ldmB(bhv[nt], base_bh + bo);
                ldmB(blv[nt], base_bl + bo);
            }
#pragma unroll
            for (int mt = 0; mt < 2; mt++)
#pragma unroll
                for (int nt = 0; nt < 2; nt++)
                    mma_bf16(acc[mt][nt], ah[mt], bhv[nt]);
#pragma unroll
            for (int mt = 0; mt < 2; mt++)
#pragma unroll
                for (int nt = 0; nt < 2; nt++)
                    mma_bf16(acc[mt][nt], ah[mt], blv[nt]);
#pragma unroll
            for (int mt = 0; mt < 2; mt++)
#pragma unroll
                for (int nt = 0; nt < 2; nt++)
                    mma_bf16(acc[mt][nt], al_[mt], bhv[nt]);
        }
    }

    const int g  = lane >> 2;
    const int tq = lane & 3;
#pragma unroll
    for (int mt = 0; mt < 2; mt++) {
#pragma unroll
        for (int nt = 0; nt < 2; nt++) {
            int row = bm + wm * 32 + mt * 16 + g;
            int col = bn + wn * 16 + nt * 8 + tq * 2;
            float bz0 = bias[col], bz1 = bias[col + 1];
            float v0 = acc[mt][nt][0] + bz0;
            float v1 = acc[mt][nt][1] + bz1;
            float v2 = acc[mt][nt][2] + bz0;
            float v3 = acc[mt][nt][3] + bz1;
            if (RELU) {
                v0 = fmaxf(v0, 0.f); v1 = fmaxf(v1, 0.f);
                v2 = fmaxf(v2, 0.f); v3 = fmaxf(v3, 0.f);
            }
            if (WF32) {
                float2 o0 = {v0, v1}, o1 = {v2, v3};
                *reinterpret_cast<float2*>(&Cf[(size_t)row * N + col]) = o0;
                *reinterpret_cast<float2*>(&Cf[(size_t)(row + 8) * N + col]) = o1;
            }
            if (WBF) {
                __nv_bfloat16 h0 = __float2bfloat16(v0);
                __nv_bfloat16 h1 = __float2bfloat16(v1);
                __nv_bfloat16 h2 = __float2bfloat16(v2);
                __nv_bfloat16 h3 = __float2bfloat16(v3);
                unsigned hp0 = (unsigned)__bfloat16_as_ushort(h0) |
                               ((unsigned)__bfloat16_as_ushort(h1) << 16);
                unsigned hp1 = (unsigned)__bfloat16_as_ushort(h2) |
                               ((unsigned)__bfloat16_as_ushort(h3) << 16);
                unsigned lp0 = (unsigned)__bfloat16_as_ushort(
                                   __float2bfloat16(v0 - __bfloat162float(h0))) |
                               ((unsigned)__bfloat16_as_ushort(
                                   __float2bfloat16(v1 - __bfloat162float(h1))) << 16);
                unsigned lp1 = (unsigned)__bfloat16_as_ushort(
                                   __float2bfloat16(v2 - __bfloat162float(h2))) |
                               ((unsigned)__bfloat16_as_ushort(
                                   __float2bfloat16(v3 - __bfloat162float(h3))) << 16);
                *reinterpret_cast<unsigned*>(&Ch[(size_t)row * N + col]) = hp0;
                *reinterpret_cast<unsigned*>(&Ch[(size_t)(row + 8) * N + col]) = hp1;
                *reinterpret_cast<unsigned*>(&Cl[(size_t)row * N + col]) = lp0;
                *reinterpret_cast<unsigned*>(&Cl[(size_t)(row + 8) * N + col]) = lp1;
            }
        }
    }
}

// ---------------- key norms + sliced histogram -------------------------------
__global__ void rownorm_kernel(const float* __restrict__ X,
                               float* __restrict__ out, int rows) {
    int gw = (int)((blockIdx.x * (size_t)blockDim.x + threadIdx.x) >> 5);
    int lane = threadIdx.x & 31;
    if (gw >= rows) return;
    float4 v = reinterpret_cast<const float4*>(X + (size_t)gw * 128)[lane];
    float s = v.x * v.x + v.y * v.y + v.z * v.z + v.w * v.w;
#pragma unroll
    for (int o = 16; o; o >>= 1) s += __shfl_xor_sync(0xffffffffu, s, o);
    if (lane == 0) {
        out[gw] = s;
        atomicAdd(&g_hist[kn_bucket(s) * NSL + (gw & (NSL - 1))], 1);
    }
}

// ---------------- exclusive scan over NCNT counters (1024 thr, 16/thr) -----
__global__ void scan_kernel() {
    __shared__ int wsum[32];
    const int t = threadIdx.x;
    const int lane = t & 31, w = t >> 5;
    const int base = t * 16;
    int loc[16];
    int s = 0;
#pragma unroll
    for (int i = 0; i < 16; i++) { loc[i] = g_hist[base + i]; s += loc[i]; }
    int x = s;
#pragma unroll
    for (int o = 1; o < 32; o <<= 1) {
        int y = __shfl_up_sync(0xffffffffu, x, o);
        if (lane >= o) x += y;
    }
    if (lane == 31) wsum[w] = x;
    __syncthreads();
    if (w == 0) {
        int v = wsum[lane];
#pragma unroll
        for (int o = 1; o < 32; o <<= 1) {
            int y = __shfl_up_sync(0xffffffffu, v, o);
            if (lane >= o) v += y;
        }
        wsum[lane] = v;
    }
    __syncthreads();
    int excl = x - s + (w > 0 ? wsum[w - 1] : 0);
#pragma unroll
    for (int i = 0; i < 16; i++) { g_cursor[base + i] = excl; excl += loc[i]; }
}

__global__ void scatter_kernel() {
    int n = blockIdx.x * blockDim.x + threadIdx.x;
    if (n >= NKEYS) return;
    float kn = g_kn[n];
    int b = kn_bucket(kn);
    int pos = atomicAdd(&g_cursor[b * NSL + (n & (NSL - 1))], 1);
    g_scand[pos] = n;
    g_skn[pos]   = kn;
    g_sblo[pos]  = kn_floor(b);
}

// ---------------- exact rescore: 4 queries/block, warp-per-query ------------
// Chunks of 32 keys (lane = key). 4 warps read the same chunk -> L1 dedup,
// L2 traffic /4. Exit per query unchanged (kn-sorted + floor bound); block
// exits when all 4 queries are done. qn computed in-kernel (same shfl order
// as before -> bit-identical).
__global__ __launch_bounds__(128, 8)
void rescore_kernel(const float* __restrict__ keys,
                    const float* __restrict__ values,
                    float* __restrict__ conf_out) {
    const int tid  = threadIdx.x;
    const int lane = tid & 31;
    const int w    = tid >> 5;
    const int q    = blockIdx.x * QPB + w;
    __shared__ float sq[QPB][CDIM];
    __shared__ float rd[QPB][KNN];
    __shared__ int   ri[QPB][KNN];
    __shared__ float sw_[QPB][KNN];
    __shared__ int   done[QPB];

    float4 qv4 = reinterpret_cast<const float4*>(g_cq + (size_t)q * CDIM)[lane];
    *reinterpret_cast<float4*>(&sq[w][lane * 4]) = qv4;
    float s = qv4.x * qv4.x + qv4.y * qv4.y + qv4.z * qv4.z + qv4.w * qv4.w;
#pragma unroll
    for (int o = 16; o; o >>= 1) s += __shfl_xor_sync(0xffffffffu, s, o);
    const float qn = s;
    const float qb = sqrtf(qn);

    if (lane < KNN) { rd[w][lane] = 3.4e38f; ri[w][lane] = 0x7fffffff; }
    if (lane == 0) done[w] = 0;
    __syncthreads();

    const float4* sq4 = reinterpret_cast<const float4*>(sq[w]);

    for (int c0 = 0; c0 < NKEYS; c0 += 32) {
        if (lane == 0 && !done[w] && c0 > 0) {
            float blo = g_sblo[c0];
            float lb = qn + blo - 2.f * qb * sqrtf(blo) - 1e-3f;
            if (lb > rd[w][KNN - 1]) done[w] = 1;
        }
        __syncthreads();
        if (done[0] && done[1] && done[2] && done[3]) break;

        if (!done[w]) {
            int j = c0 + lane;
            float d = 3.4e38f;
            int nidx = 0x7fffffff;
            if (j < NKEYS) {
                int n = g_scand[j];
                const float4* kr =
                    reinterpret_cast<const float4*>(keys + (size_t)n * CDIM);
                float a0 = 0.f, a1 = 0.f, a2 = 0.f, a3 = 0.f;
#pragma unroll
                for (int dd = 0; dd < CDIM / 4; dd++) {
                    float4 kv = __ldg(&kr[dd]);
                    float4 qv = sq4[dd];
                    a0 = fmaf(qv.x, kv.x, a0);
                    a1 = fmaf(qv.y, kv.y, a1);
                    a2 = fmaf(qv.z, kv.z, a2);
                    a3 = fmaf(qv.w, kv.w, a3);
                }
                float dot = (a0 + a1) + (a2 + a3);
                d = qn + g_skn[j] - 2.f * dot;
                nidx = n;
            }
            // exact top-5 insert: argmin-lex rounds with early break
            float rd4 = rd[w][KNN - 1];
            int   ri4 = ri[w][KNN - 1];
#pragma unroll
            for (int r = 0; r < KNN; r++) {
                float v = d; int ix = nidx;
#pragma unroll
                for (int o = 16; o; o >>= 1) {
                    float v2 = __shfl_xor_sync(0xffffffffu, v, o);
                    int   i2 = __shfl_xor_sync(0xffffffffu, ix, o);
                    if (v2 < v || (v2 == v && i2 < ix)) { v = v2; ix = i2; }
                }
                if (!(v < rd4 || (v == rd4 && ix < ri4))) break;  // uniform
                if (lane == 0) {
                    int p = KNN - 1;
                    while (p > 0 && (rd[w][p - 1] > v ||
                                     (rd[w][p - 1] == v && ri[w][p - 1] > ix))) {
                        rd[w][p] = rd[w][p - 1]; ri[w][p] = ri[w][p - 1]; p--;
                    }
                    rd[w][p] = v; ri[w][p] = ix;
                }
                if (d == v && nidx == ix) { d = 3.4e38f; nidx = 0x7fffffff; }
                __syncwarp();
                rd4 = rd[w][KNN - 1];
                ri4 = ri[w][KNN - 1];
            }
        }
        __syncthreads();
    }

    if (lane == 0) {
        float ww[KNN], ws = 0.f;
#pragma unroll
        for (int j2 = 0; j2 < KNN; j2++) { ww[j2] = 1.f / (rd[w][j2] + EPSW); ws += ww[j2]; }
#pragma unroll
        for (int j2 = 0; j2 < KNN; j2++) sw_[w][j2] = ww[j2] / ws;
        conf_out[q] = 1.f / (rd[w][0] + EPSW);
    }
    __syncwarp();

#pragma unroll
    for (int dd = 0; dd < 4; dd++) {
        int dcol = dd * 32 + lane;
        float acc = 0.f;
#pragma unroll
        for (int j2 = 0; j2 < KNN; j2++)
            acc += sw_[w][j2] * values[(size_t)ri[w][j2] * CDIM + dcol];
        __nv_bfloat16 hb = __float2bfloat16(acc);
        g_wh[(size_t)q * CDIM + dcol] = hb;
        g_wl[(size_t)q * CDIM + dcol] =
            __float2bfloat16(acc - __bfloat162float(hb));
    }
}

// ---------------- launch ----------------------------------------------------
extern "C" void kernel_launch(void* const* d_in, const int* in_sizes, int n_in,
                              void* d_out, int out_size) {
    const float* query = (const float*)d_in[0];
    const float* W1    = (const float*)d_in[1];
    const float* b1    = (const float*)d_in[2];
    const float* W2    = (const float*)d_in[3];
    const float* b2    = (const float*)d_in[4];
    const float* W3    = (const float*)d_in[5];
    const float* b3    = (const float*)d_in[6];
    const float* keys  = (const float*)d_in[7];
    const float* values= (const float*)d_in[8];
    const float* D1w   = (const float*)d_in[9];
    const float* D1b   = (const float*)d_in[10];
    const float* D2w   = (const float*)d_in[11];
    const float* D2b   = (const float*)d_in[12];
    const float* D3w   = (const float*)d_in[13];
    const float* D3b   = (const float*)d_in[14];

    float* out  = (float*)d_out;
    float* conf = out + (size_t)BQ * DIM;

    void *qh, *ql, *W1h, *W1l, *W2h, *W2l, *W3h, *W3l;
    void *D1h, *D1l, *D2h, *D2l, *D3h, *D3l;
    void *h1h, *h1l, *h2h, *h2l, *wh, *wl, *g1h, *g1l, *g2h, *g2l;
    void *kn;
    cudaGetSymbolAddress(&qh, g_qh);   cudaGetSymbolAddress(&ql, g_ql);
    cudaGetSymbolAddress(&W1h, g_W1h); cudaGetSymbolAddress(&W1l, g_W1l);
    cudaGetSymbolAddress(&W2h, g_W2h); cudaGetSymbolAddress(&W2l, g_W2l);
    cudaGetSymbolAddress(&W3h, g_W3h); cudaGetSymbolAddress(&W3l, g_W3l);
    cudaGetSymbolAddress(&D1h, g_D1h); cudaGetSymbolAddress(&D1l, g_D1l);
    cudaGetSymbolAddress(&D2h, g_D2h); cudaGetSymbolAddress(&D2l, g_D2l);
    cudaGetSymbolAddress(&D3h, g_D3h); cudaGetSymbolAddress(&D3l, g_D3l);
    cudaGetSymbolAddress(&h1h, g_h1h); cudaGetSymbolAddress(&h1l, g_h1l);
    cudaGetSymbolAddress(&h2h, g_h2h); cudaGetSymbolAddress(&h2l, g_h2l);
    cudaGetSymbolAddress(&wh, g_wh);   cudaGetSymbolAddress(&wl, g_wl);
    cudaGetSymbolAddress(&g1h, g_g1h); cudaGetSymbolAddress(&g1l, g_g1l);
    cudaGetSymbolAddress(&g2h, g_g2h); cudaGetSymbolAddress(&g2l, g_g2l);
    void* cq;
    cudaGetSymbolAddress(&cq, g_cq);
    cudaGetSymbolAddress(&kn, g_kn);

    cudaFuncSetAttribute(bgemm<1, 0, 1>,
                         cudaFuncAttributeMaxDynamicSharedMemorySize, PSM_TOTAL);
    cudaFuncSetAttribute(bgemm<0, 1, 0>,
                         cudaFuncAttributeMaxDynamicSharedMemorySize, PSM_TOTAL);

    // 1. batched split: query + 6 weight matrices (+ fused counter zeroing)
    SplitArgs sa;
    int sizes4[7] = {BQ * DIM / 4, DIM * 512 / 4, 512 * 256 / 4, 256 * 128 / 4,
                     128 * 256 / 4, 256 * 512 / 4, 512 * 1024 / 4};
    const float* srcs[7] = {query, W1, W2, W3, D1w, D2w, D3w};
    void* hs[7] = {qh, W1h, W2h, W3h, D1h, D2h, D3h};
    void* ls[7] = {ql, W1l, W2l, W3l, D1l, D2l, D3l};
    sa.cum[0] = 0;
    for (int i = 0; i < 7; i++) {
        sa.s[i].src = srcs[i];
        sa.s[i].h = (__nv_bfloat16*)hs[i];
        sa.s[i].l = (__nv_bfloat16*)ls[i];
        sa.cum[i + 1] = sa.cum[i] + sizes4[i];
    }
    split_batch_kernel<<<(sa.cum[7] + 255) / 256, 256>>>(sa);

    // fork: retrieval prep on side stream, overlapped with encode GEMMs
    cudaEventRecord(g_evFork, 0);
    cudaStreamWaitEvent(g_side, g_evFork, 0);
    rownorm_kernel<<<(NKEYS * 32 + 255) / 256, 256, 0, g_side>>>(
        keys, (float*)kn, NKEYS);
    scan_kernel<<<1, 1024, 0, g_side>>>();
    scatter_kernel<<<(NKEYS + 255) / 256, 256, 0, g_side>>>();
    cudaEventRecord(g_evJoin, g_side);

    // Encode MLP (main stream)
    bgemm<1, 0, 1><<<dim3(512 / GBN, BQ / GBM), 256, PSM_TOTAL>>>(
        (__nv_bfloat16*)qh, (__nv_bfloat16*)ql, (__nv_bfloat16*)W1h, (__nv_bfloat16*)W1l,
        b1, nullptr, (__nv_bfloat16*)h1h, (__nv_bfloat16*)h1l, BQ, 512, 1024);
    bgemm<1, 0, 1><<<dim3(256 / GBN, BQ / GBM), 256, PSM_TOTAL>>>(
        (__nv_bfloat16*)h1h, (__nv_bfloat16*)h1l, (__nv_bfloat16*)W2h, (__nv_bfloat16*)W2l,
        b2, nullptr, (__nv_bfloat16*)h2h, (__nv_bfloat16*)h2l, BQ, 256, 512);
    bgemm<0, 1, 0><<<dim3(128 / GBN, BQ / GBM), 256, PSM_TOTAL>>>(
        (__nv_bfloat16*)h2h, (__nv_bfloat16*)h2l, (__nv_bfloat16*)W3h, (__nv_bfloat16*)W3l,
        b3, (float*)cq, nullptr, nullptr, BQ, 128, 256);

    // join: rescore needs scatter results (qn computed inside rescore)
    cudaStreamWaitEvent(0, g_evJoin, 0);

    // exact rescore + top-5 + gather (4 queries/block, emits bf16 hi/lo)
    rescore_kernel<<<BQ / QPB, 128>>>(keys, values, conf);

    // Decode MLP
    bgemm<1, 0, 1><<<dim3(256 / GBN, BQ / GBM), 256, PSM_TOTAL>>>(
        (__nv_bfloat16*)wh, (__nv_bfloat16*)wl, (__nv_bfloat16*)D1h, (__nv_bfloat16*)D1l,
        D1b, nullptr, (__nv_bfloat16*)g1h, (__nv_bfloat16*)g1l, BQ, 256, 128);
    bgemm<1, 0, 1><<<dim3(512 / GBN, BQ / GBM), 256, PSM_TOTAL>>>(
        (__nv_bfloat16*)g1h, (__nv_bfloat16*)g1l, (__nv_bfloat16*)D2h, (__nv_bfloat16*)D2l,
        D2b, nullptr, (__nv_bfloat16*)g2h, (__nv_bfloat16*)g2l, BQ, 512, 256);
    bgemm<0, 1, 0><<<dim3(1024 / GBN, BQ / GBM), 256, PSM_TOTAL>>>(
        (__nv_bfloat16*)g2h, (__nv_bfloat16*)g2l, (__nv_bfloat16*)D3h, (__nv_bfloat16*)D3l,
        D3b, out, nullptr, nullptr, BQ, 1024, 512);
}